// round 7
// baseline (speedup 1.0000x reference)
#include <cuda_runtime.h>
#include <cuda_bf16.h>
#include <cstdint>
#include <math.h>

#define BB 2
#define TT 2048
#define CC 1024
#define HH 16
#define DD 64
#define MM (BB*TT)   // 4096 rows

// ---------------------------------------------------------------------------
// Scratch (__device__ globals; allocation-free rule)
// ---------------------------------------------------------------------------
__device__ __nv_bfloat16 g_qhi[BB*HH*TT*DD], g_qlo[BB*HH*TT*DD];  // [B,H,T,D]
__device__ __nv_bfloat16 g_khi[BB*HH*TT*DD], g_klo[BB*HH*TT*DD];
__device__ __nv_bfloat16 g_vhi[BB*HH*TT*DD], g_vlo[BB*HH*TT*DD];

__device__ __nv_bfloat16 g_xhi[MM*CC], g_xlo[MM*CC];        // x split
__device__ __nv_bfloat16 g_whi[3*CC*CC], g_wlo[3*CC*CC];    // Wq|Wk|Wv concat
__device__ __nv_bfloat16 g_wohi[CC*CC], g_wolo[CC*CC];      // Wo
__device__ __nv_bfloat16 g_yhi[MM*CC], g_ylo[MM*CC];        // y split [B,T,C]
__device__ float g_bqkv[3*CC];                               // bq|bk|bv concat

// Q pre-scale: 1/sqrt(64) * log2(e)  (softmax done in base-2)
#define QSCALE (0.125f * 1.4426950408889634f)

// ---------------------------------------------------------------------------
// Helpers: ldmatrix / mma.sync / cp.async (baseline sm_80+)
// ---------------------------------------------------------------------------
__device__ __forceinline__ uint32_t smem_to_u32(const void* p) {
    uint32_t a;
    asm("{ .reg .u64 t; cvta.to.shared.u64 t, %1; cvt.u32.u64 %0, t; }"
        : "=r"(a) : "l"(p));
    return a;
}
__device__ __forceinline__ void ldsm_x4(uint32_t* r, uint32_t addr) {
    asm volatile("ldmatrix.sync.aligned.m8n8.x4.shared.b16 {%0,%1,%2,%3}, [%4];"
        : "=r"(r[0]), "=r"(r[1]), "=r"(r[2]), "=r"(r[3]) : "r"(addr));
}
__device__ __forceinline__ void ldsm_x4_t(uint32_t* r, uint32_t addr) {
    asm volatile("ldmatrix.sync.aligned.m8n8.x4.trans.shared.b16 {%0,%1,%2,%3}, [%4];"
        : "=r"(r[0]), "=r"(r[1]), "=r"(r[2]), "=r"(r[3]) : "r"(addr));
}
__device__ __forceinline__ void mma_bf16(float* d, const uint32_t* a,
                                         const uint32_t* b) {
    asm volatile(
        "mma.sync.aligned.m16n8k16.row.col.f32.bf16.bf16.f32 "
        "{%0,%1,%2,%3}, {%4,%5,%6,%7}, {%8,%9}, {%0,%1,%2,%3};"
        : "+f"(d[0]), "+f"(d[1]), "+f"(d[2]), "+f"(d[3])
        : "r"(a[0]), "r"(a[1]), "r"(a[2]), "r"(a[3]), "r"(b[0]), "r"(b[1]));
}
__device__ __forceinline__ void cp16(uint32_t saddr, const void* g) {
    asm volatile("cp.async.cg.shared.global [%0], [%1], 16;"
        :: "r"(saddr), "l"(g) : "memory");
}
#define CP_COMMIT()  asm volatile("cp.async.commit_group;" ::: "memory")
#define CP_WAIT1()   asm volatile("cp.async.wait_group 1;" ::: "memory")
#define CP_WAIT0()   asm volatile("cp.async.wait_group 0;" ::: "memory")

#define SMEM_SWIZZLE_128B(byte_offset) \
    ((byte_offset) ^ (((byte_offset) >> 3) & 0x70))

__device__ __forceinline__ float exp2a(float x) {
    float y; asm("ex2.approx.f32 %0, %1;" : "=f"(y) : "f"(x)); return y;
}
__device__ __forceinline__ uint32_t pack_bf16x2(float lo, float hi) {
    uint32_t r;
    asm("cvt.rn.bf16x2.f32 %0, %1, %2;" : "=r"(r) : "f"(hi), "f"(lo));
    return r;
}
__device__ __forceinline__ float2 bf16x2_to_f2(uint32_t u) {
    __nv_bfloat162 h = *reinterpret_cast<__nv_bfloat162*>(&u);
    return __bfloat1622float2(h);
}

// ---------------------------------------------------------------------------
// Prep: fp32 -> bf16 hi/lo splits (vectorized x4), bias concat.
// Region boundaries (1M-multiples) are all multiples of 4.
// ---------------------------------------------------------------------------
__global__ __launch_bounds__(256) void prep_split(
    const float* __restrict__ Wq, const float* __restrict__ Wk,
    const float* __restrict__ Wv, const float* __restrict__ Wo,
    const float* __restrict__ x)
{
    const int i = (blockIdx.x * 256 + threadIdx.x) * 4;   // 0 .. 8M-1, step 4
    const int WQKV = 3*CC*CC, WO = CC*CC;
    const float* src;
    __nv_bfloat16 *hi, *lo;
    int j;
    if (i < WQKV) {
        src = (i < CC*CC) ? Wq : (i < 2*CC*CC) ? Wk : Wv;
        src += (i & (CC*CC - 1));
        hi = g_whi; lo = g_wlo; j = i;
    } else if (i < WQKV + WO) {
        j = i - WQKV;
        src = Wo + j;
        hi = g_wohi; lo = g_wolo;
    } else {
        j = i - WQKV - WO;      // 0 .. 4M-1
        src = x + j;
        hi = g_xhi; lo = g_xlo;
    }
    float4 v = *(const float4*)src;
    uint32_t h0 = pack_bf16x2(v.x, v.y);
    uint32_t h1 = pack_bf16x2(v.z, v.w);
    float2 f0 = bf16x2_to_f2(h0);
    float2 f1 = bf16x2_to_f2(h1);
    uint32_t l0 = pack_bf16x2(v.x - f0.x, v.y - f0.y);
    uint32_t l1 = pack_bf16x2(v.z - f1.x, v.w - f1.y);
    *(uint2*)(hi + j) = make_uint2(h0, h1);
    *(uint2*)(lo + j) = make_uint2(l0, l1);
}

__global__ void prep_bias(const float* __restrict__ bq,
                          const float* __restrict__ bk,
                          const float* __restrict__ bv)
{
    int i = blockIdx.x * 256 + threadIdx.x;
    if (i < 3*CC)
        g_bqkv[i] = (i < CC) ? bq[i] : (i < 2*CC) ? bk[i-CC] : bv[i-2*CC];
}

// ---------------------------------------------------------------------------
// mma.sync GEMM: 128x256 tile of A[M,1024] @ B[N,1024]^T, bf16 hi/lo 3-term.
// 8 warps in 4(M)x2(N): warp tile 32x128. 2-stage cp.async pipeline.
// mode 0: A=x, B=WqWkWv, scatter bf16 hi/lo q/k/v (+bias, Q scaled).
// mode 1: A=y(hi/lo), B=Wo, write d_out fp32 (+bo).
// ---------------------------------------------------------------------------
#define CHUNK_K   64
#define NCHUNK    (CC / CHUNK_K)      // 16
#define OFF_AH 0
#define OFF_AL 16384                  // A buf: 128*64*2 = 16 KB
#define OFF_BH 32768
#define OFF_BL 65536                  // B buf: 256*64*2 = 32 KB
#define STAGE_BYTES 98304             // 96 KB
#define GEMM_SMEM (2*STAGE_BYTES + 1024)   // 197632 B

__global__ __launch_bounds__(256, 1) void gemm_tc(
    int mode, const float* __restrict__ bias1, float* __restrict__ outf)
{
    extern __shared__ char smem[];
    const uint32_t smem_u32 = smem_to_u32(smem);
    const uint32_t tile_u32 = (smem_u32 + 1023) & ~1023u;

    const int tid  = threadIdx.x;
    const int wid  = tid >> 5;
    const int lane = tid & 31;
    const int wm   = wid >> 1;          // 0..3 (M, 32 rows each)
    const int wn   = wid & 1;           // 0..1 (N, 128 cols each)
    const int m0   = blockIdx.y << 7;   // 128-row tiles
    const int n0   = blockIdx.x << 8;   // 256-col tiles

    const __nv_bfloat16 *Ah, *Al, *Bh, *Bl;
    if (mode == 0) { Ah = g_xhi; Al = g_xlo; Bh = g_whi;  Bl = g_wlo;  }
    else           { Ah = g_yhi; Al = g_ylo; Bh = g_wohi; Bl = g_wolo; }

    // --- loader: A 2048 chunks (8 iters), B 4096 chunks (16 iters) ---
    auto issue_chunk = [&](int c, int s) {
        const int kc = c * CHUNK_K;
        const uint32_t st = tile_u32 + s * STAGE_BYTES;
        #pragma unroll
        for (int i = 0; i < 8; i++) {
            int idx = tid + i*256;          // 0..2047
            int buf = idx >> 10;            // 0 hi, 1 lo
            int rc = idx & 1023; int r = rc >> 3, g = rc & 7;
            uint32_t so = SMEM_SWIZZLE_128B((uint32_t)(r*128 + g*16));
            size_t aoff = (size_t)(m0 + r) * CC + kc + g*8;
            cp16(st + (buf ? OFF_AL : OFF_AH) + so, (buf ? Al : Ah) + aoff);
        }
        #pragma unroll
        for (int i = 0; i < 16; i++) {
            int idx = tid + i*256;          // 0..4095
            int buf = idx >> 11;            // 0 hi, 1 lo
            int rc = idx & 2047; int r = rc >> 3, g = rc & 7;   // r 0..255
            uint32_t so = SMEM_SWIZZLE_128B((uint32_t)(r*128 + g*16));
            size_t boff = (size_t)(n0 + r) * CC + kc + g*8;
            cp16(st + (buf ? OFF_BL : OFF_BH) + so, (buf ? Bl : Bh) + boff);
        }
        CP_COMMIT();
    };

    float acc[2][16][4];
    #pragma unroll
    for (int mt = 0; mt < 2; mt++)
        #pragma unroll
        for (int nt = 0; nt < 16; nt++)
            #pragma unroll
            for (int e = 0; e < 4; e++) acc[mt][nt][e] = 0.f;

    issue_chunk(0, 0);
    issue_chunk(1, 1);

    for (int c = 0; c < NCHUNK; ++c) {
        const int s = c & 1;
        if (c + 1 < NCHUNK) { CP_WAIT1(); } else { CP_WAIT0(); }
        __syncthreads();

        const uint32_t sAh = tile_u32 + s*STAGE_BYTES + OFF_AH;
        const uint32_t sAl = tile_u32 + s*STAGE_BYTES + OFF_AL;
        const uint32_t sBh = tile_u32 + s*STAGE_BYTES + OFF_BH;
        const uint32_t sBl = tile_u32 + s*STAGE_BYTES + OFF_BL;

        #pragma unroll
        for (int ks = 0; ks < 4; ++ks) {
            uint32_t ah[2][4], al[2][4];
            #pragma unroll
            for (int mt = 0; mt < 2; ++mt) {
                int r = wm*32 + mt*16 + (lane & 15);
                int g = ks*2 + (lane >> 4);
                uint32_t off = SMEM_SWIZZLE_128B((uint32_t)(r*128 + g*16));
                ldsm_x4(ah[mt], sAh + off);
                ldsm_x4(al[mt], sAl + off);
            }
            #pragma unroll
            for (int np = 0; np < 8; ++np) {
                int n = wn*128 + np*16 + ((lane >> 4) << 3) + (lane & 7);
                int g = ks*2 + ((lane >> 3) & 1);
                uint32_t off = SMEM_SWIZZLE_128B((uint32_t)(n*128 + g*16));
                uint32_t bh[4], bl[4];
                ldsm_x4(bh, sBh + off);
                ldsm_x4(bl, sBl + off);
                #pragma unroll
                for (int mt = 0; mt < 2; ++mt) {
                    mma_bf16(acc[mt][2*np],   ah[mt], bh);
                    mma_bf16(acc[mt][2*np+1], ah[mt], bh + 2);
                    mma_bf16(acc[mt][2*np],   ah[mt], bl);
                    mma_bf16(acc[mt][2*np+1], ah[mt], bl + 2);
                    mma_bf16(acc[mt][2*np],   al[mt], bh);
                    mma_bf16(acc[mt][2*np+1], al[mt], bh + 2);
                }
            }
        }

        if (c + 2 < NCHUNK) {
            __syncthreads();
            issue_chunk(c + 2, s);
        }
    }

    // --- epilogue ---
    const int gl = lane >> 2;          // 0..7
    const int tl = lane & 3;           // 0..3
    #pragma unroll
    for (int mt = 0; mt < 2; ++mt) {
        #pragma unroll
        for (int nt = 0; nt < 16; ++nt) {
            const int row0 = m0 + wm*32 + mt*16 + gl;
            const int colg = n0 + wn*128 + nt*8 + 2*tl;
            if (mode == 0) {
                const int head = colg >> 6;        // 0..47
                const int proj = head >> 4;        // 0=q 1=k 2=v
                const int h    = head & 15;
                const int d0c  = colg & 63;
                __nv_bfloat16 *hiP, *loP;
                if (proj == 0)      { hiP = g_qhi; loP = g_qlo; }
                else if (proj == 1) { hiP = g_khi; loP = g_klo; }
                else                { hiP = g_vhi; loP = g_vlo; }
                const float2 bia = *(const float2*)&g_bqkv[colg];
                #pragma unroll
                for (int rr = 0; rr < 2; ++rr) {
                    const int m = row0 + rr*8;
                    const int b_ = m >> 11, t = m & 2047;
                    float v0 = acc[mt][nt][2*rr+0] + bia.x;
                    float v1 = acc[mt][nt][2*rr+1] + bia.y;
                    if (proj == 0) { v0 *= QSCALE; v1 *= QSCALE; }
                    uint32_t hp = pack_bf16x2(v0, v1);
                    float2 hf = bf16x2_to_f2(hp);
                    uint32_t lp = pack_bf16x2(v0 - hf.x, v1 - hf.y);
                    size_t off = ((size_t)(b_*HH + h) * TT + t) * DD + d0c;
                    *(uint32_t*)(hiP + off) = hp;
                    *(uint32_t*)(loP + off) = lp;
                }
            } else {
                const float2 bia = *(const float2*)&bias1[colg];
                #pragma unroll
                for (int rr = 0; rr < 2; ++rr) {
                    const int m = row0 + rr*8;
                    float2 o;
                    o.x = acc[mt][nt][2*rr+0] + bia.x;
                    o.y = acc[mt][nt][2*rr+1] + bia.y;
                    *(float2*)(outf + (size_t)m * CC + colg) = o;
                }
            }
        }
    }
}

// ---------------------------------------------------------------------------
// Tensor-core flash attention (unchanged from R6 — passing).
// ---------------------------------------------------------------------------
#define F_SMEM (32768 + 65536)   // Q(hi+lo) 32KB + 2 stages x (K/V hi/lo) 32KB

__global__ __launch_bounds__(256, 1) void flash_tc()
{
    extern __shared__ char fsm[];
    const uint32_t sb  = smem_to_u32(fsm);
    const uint32_t sQh = sb, sQl = sb + 16384;

    const int tid = threadIdx.x, wid = tid >> 5, lane = tid & 31;
    const int gl = lane >> 2, tl = lane & 3;
    const int jq = (int)gridDim.x - 1 - (int)blockIdx.x;   // heavy tiles first
    const int q0 = jq << 7;
    const int bh = blockIdx.y;
    const size_t hb = (size_t)bh * TT * DD;
    const __nv_bfloat16 *qhp = g_qhi + hb + (size_t)q0 * DD;
    const __nv_bfloat16 *qlp = g_qlo + hb + (size_t)q0 * DD;
    const __nv_bfloat16 *khp = g_khi + hb, *klp = g_klo + hb;
    const __nv_bfloat16 *vhp = g_vhi + hb, *vlp = g_vlo + hb;
    const int ntiles = 2*jq + 2;

    // --- Q tile (hi+lo): 128 rows x 8 chunks x 2 buffers = 2048 chunks ---
    #pragma unroll
    for (int i = 0; i < 8; i++) {
        int idx = tid + i*256;              // 0..2047
        int buf = idx >> 10;                // 0 hi, 1 lo
        int rc = idx & 1023; int r = rc >> 3, c = rc & 7;
        uint32_t so = SMEM_SWIZZLE_128B((uint32_t)(r*128 + c*16));
        cp16((buf ? sQl : sQh) + so, (buf ? qlp : qhp) + (size_t)r*DD + c*8);
    }
    CP_COMMIT();

    auto issue_kv = [&](int kt, int s) {
        const uint32_t st = sb + 32768 + s*32768;
        const int r0 = kt << 6;
        #pragma unroll
        for (int i = 0; i < 8; i++) {
            int idx = tid + i*256;          // 0..2047
            int buf = idx >> 9;             // 0 khi,1 klo,2 vhi,3 vlo
            int rc = idx & 511; int r = rc >> 3, c = rc & 7;
            uint32_t so = SMEM_SWIZZLE_128B((uint32_t)(r*128 + c*16));
            const __nv_bfloat16* src =
                (buf == 0 ? khp : buf == 1 ? klp : buf == 2 ? vhp : vlp)
                + (size_t)(r0 + r) * DD + c*8;
            cp16(st + buf*8192 + so, src);
        }
        CP_COMMIT();
    };
    issue_kv(0, 0);
    issue_kv(1, 1);

    CP_WAIT1();              // Q + stage0 complete
    __syncthreads();

    // --- Q fragments (persistent) ---
    const int qrow = wid << 4;
    uint32_t qfh[4][4], qfl[4][4];
    #pragma unroll
    for (int dc = 0; dc < 4; dc++) {
        uint32_t so = SMEM_SWIZZLE_128B((uint32_t)(
            (qrow + (lane & 15))*128 + (dc*16 + ((lane >> 4) << 3))*2));
        ldsm_x4(qfh[dc], sQh + so);
        ldsm_x4(qfl[dc], sQl + so);
    }

    float m_run[2] = {-1e30f, -1e30f};
    float l_run[2] = {0.f, 0.f};
    float oacc[8][4];
    #pragma unroll
    for (int f = 0; f < 8; f++)
        #pragma unroll
        for (int e = 0; e < 4; e++) oacc[f][e] = 0.f;

    for (int kt = 0; kt < ntiles; kt++) {
        const int s = kt & 1;
        if (kt + 1 < ntiles) { CP_WAIT1(); } else { CP_WAIT0(); }
        __syncthreads();

        const bool active = (q0 + qrow + 15) >= (kt << 6);
        if (active) {
            const uint32_t st = sb + 32768 + s*32768;

            // ---- S = Q @ K^T (3-term) ----
            float sacc[8][4] = {};
            #pragma unroll
            for (int dc = 0; dc < 4; dc++) {
                #pragma unroll
                for (int ng = 0; ng < 4; ng++) {
                    uint32_t so = SMEM_SWIZZLE_128B((uint32_t)(
                        ((ng<<4) + (lane & 7) + ((lane >> 4) << 3))*128 +
                        ((dc<<4) + ((lane >> 3) & 1)*8)*2));
                    uint32_t kfh[4], kfl[4];
                    ldsm_x4(kfh, st + so);
                    ldsm_x4(kfl, st + 8192 + so);
                    mma_bf16(sacc[2*ng],   qfh[dc], kfh);
                    mma_bf16(sacc[2*ng+1], qfh[dc], kfh + 2);
                    mma_bf16(sacc[2*ng],   qfh[dc], kfl);
                    mma_bf16(sacc[2*ng+1], qfh[dc], kfl + 2);
                    mma_bf16(sacc[2*ng],   qfl[dc], kfh);
                    mma_bf16(sacc[2*ng+1], qfl[dc], kfh + 2);
                }
            }

            // ---- causal mask (diagonal tiles only) ----
            if (kt >= 2*jq) {
                const int r0g = q0 + qrow + gl;
                #pragma unroll
                for (int f = 0; f < 8; f++) {
                    const int kc0 = (kt << 6) + (f << 3) + (tl << 1);
                    if (kc0     > r0g)     sacc[f][0] = -1e30f;
                    if (kc0 + 1 > r0g)     sacc[f][1] = -1e30f;
                    if (kc0     > r0g + 8) sacc[f][2] = -1e30f;
                    if (kc0 + 1 > r0g + 8) sacc[f][3] = -1e30f;
                }
            }

            // ---- online softmax (base 2) ----
            float mx0 = m_run[0], mx1 = m_run[1];
            #pragma unroll
            for (int f = 0; f < 8; f++) {
                mx0 = fmaxf(mx0, fmaxf(sacc[f][0], sacc[f][1]));
                mx1 = fmaxf(mx1, fmaxf(sacc[f][2], sacc[f][3]));
            }
            mx0 = fmaxf(mx0, __shfl_xor_sync(0xffffffffu, mx0, 1));
            mx0 = fmaxf(mx0, __shfl_xor_sync(0xffffffffu, mx0, 2));
            mx1 = fmaxf(mx1, __shfl_xor_sync(0xffffffffu, mx1, 1));
            mx1 = fmaxf(mx1, __shfl_xor_sync(0xffffffffu, mx1, 2));
            const float a0 = exp2a(m_run[0] - mx0);
            const float a1 = exp2a(m_run[1] - mx1);
            m_run[0] = mx0; m_run[1] = mx1;

            float sum0 = 0.f, sum1 = 0.f;
            uint32_t pAh[8], pBh[8], pAl[8], pBl[8];
            #pragma unroll
            for (int f = 0; f < 8; f++) {
                float p0 = exp2a(sacc[f][0] - mx0);
                float p1 = exp2a(sacc[f][1] - mx0);
                float p2 = exp2a(sacc[f][2] - mx1);
                float p3 = exp2a(sacc[f][3] - mx1);
                sum0 += p0 + p1; sum1 += p2 + p3;
                uint32_t h01 = pack_bf16x2(p0, p1);
                uint32_t h23 = pack_bf16x2(p2, p3);
                float2 f01 = bf16x2_to_f2(h01);
                float2 f23 = bf16x2_to_f2(h23);
                pAh[f] = h01; pBh[f] = h23;
                pAl[f] = pack_bf16x2(p0 - f01.x, p1 - f01.y);
                pBl[f] = pack_bf16x2(p2 - f23.x, p3 - f23.y);
            }
            sum0 += __shfl_xor_sync(0xffffffffu, sum0, 1);
            sum0 += __shfl_xor_sync(0xffffffffu, sum0, 2);
            sum1 += __shfl_xor_sync(0xffffffffu, sum1, 1);
            sum1 += __shfl_xor_sync(0xffffffffu, sum1, 2);
            l_run[0] = l_run[0]*a0 + sum0;
            l_run[1] = l_run[1]*a1 + sum1;
            #pragma unroll
            for (int f = 0; f < 8; f++) {
                oacc[f][0] *= a0; oacc[f][1] *= a0;
                oacc[f][2] *= a1; oacc[f][3] *= a1;
            }

            // ---- O += P @ V (3-term; V via ldmatrix.trans) ----
            #pragma unroll
            for (int kc = 0; kc < 4; kc++) {
                uint32_t Ahh[4] = {pAh[2*kc], pBh[2*kc], pAh[2*kc+1], pBh[2*kc+1]};
                uint32_t All[4] = {pAl[2*kc], pBl[2*kc], pAl[2*kc+1], pBl[2*kc+1]};
                #pragma unroll
                for (int dg = 0; dg < 4; dg++) {
                    uint32_t so = SMEM_SWIZZLE_128B((uint32_t)(
                        ((kc<<4) + (lane & 7) + ((lane >> 3) & 1)*8)*128 +
                        ((dg<<4) + (lane >> 4)*8)*2));
                    uint32_t vfh[4], vfl[4];
                    ldsm_x4_t(vfh, st + 16384 + so);
                    ldsm_x4_t(vfl, st + 24576 + so);
                    mma_bf16(oacc[2*dg],   Ahh, vfh);
                    mma_bf16(oacc[2*dg+1], Ahh, vfh + 2);
                    mma_bf16(oacc[2*dg],   Ahh, vfl);
                    mma_bf16(oacc[2*dg+1], Ahh, vfl + 2);
                    mma_bf16(oacc[2*dg],   All, vfh);
                    mma_bf16(oacc[2*dg+1], All, vfh + 2);
                }
            }
        }

        __syncthreads();
        if (kt + 2 < ntiles) issue_kv(kt + 2, s);
    }

    // ---- epilogue: normalize, split hi/lo, write y [B,T,C] ----
    const float inv0 = 1.f / l_run[0];
    const float inv1 = 1.f / l_run[1];
    const int b_ = bh >> 4, h = bh & 15;
    const int t0 = q0 + qrow + gl, t1 = t0 + 8;
    #pragma unroll
    for (int f = 0; f < 8; f++) {
        const int col = h*DD + (f << 3) + (tl << 1);
        {
            float y0 = oacc[f][0] * inv0, y1 = oacc[f][1] * inv0;
            uint32_t hp = pack_bf16x2(y0, y1);
            float2 hf = bf16x2_to_f2(hp);
            uint32_t lp = pack_bf16x2(y0 - hf.x, y1 - hf.y);
            size_t off = (size_t)(b_*TT + t0) * CC + col;
            *(uint32_t*)(g_yhi + off) = hp;
            *(uint32_t*)(g_ylo + off) = lp;
        }
        {
            float y2 = oacc[f][2] * inv1, y3 = oacc[f][3] * inv1;
            uint32_t hp = pack_bf16x2(y2, y3);
            float2 hf = bf16x2_to_f2(hp);
            uint32_t lp = pack_bf16x2(y2 - hf.x, y3 - hf.y);
            size_t off = (size_t)(b_*TT + t1) * CC + col;
            *(uint32_t*)(g_yhi + off) = hp;
            *(uint32_t*)(g_ylo + off) = lp;
        }
    }
}

// ---------------------------------------------------------------------------

extern "C" void kernel_launch(void* const* d_in, const int* in_sizes, int n_in,
                              void* d_out, int out_size)
{
    const float* x  = (const float*)d_in[0];
    const float* Wq = (const float*)d_in[1];
    const float* bq = (const float*)d_in[2];
    const float* Wk = (const float*)d_in[3];
    const float* bk = (const float*)d_in[4];
    const float* Wv = (const float*)d_in[5];
    const float* bv = (const float*)d_in[6];
    const float* Wo = (const float*)d_in[7];
    const float* bo = (const float*)d_in[8];
    float* out = (float*)d_out;

    // 0) fp32 -> bf16 hi/lo splits (x4 vectorized) + bias concat
    prep_split<<<(8*1024*1024)/1024, 256>>>(Wq, Wk, Wv, Wo, x);
    prep_bias<<<12, 256>>>(bq, bk, bv);

    // 1) fused QKV projection -> bf16 hi/lo q/k/v (Q pre-scaled)
    cudaFuncSetAttribute(gemm_tc, cudaFuncAttributeMaxDynamicSharedMemorySize,
                         GEMM_SMEM);
    gemm_tc<<<dim3(3*CC/256, MM/128), 256, GEMM_SMEM>>>(0, nullptr, nullptr);

    // 2) tensor-core causal flash attention -> y hi/lo
    cudaFuncSetAttribute(flash_tc, cudaFuncAttributeMaxDynamicSharedMemorySize,
                         F_SMEM);
    flash_tc<<<dim3(TT/128, BB*HH), 256, F_SMEM>>>();

    // 3) output projection -> d_out
    gemm_tc<<<dim3(CC/256, MM/128), 256, GEMM_SMEM>>>(1, bo, out);
}

// round 8
// speedup vs baseline: 1.4849x; 1.4849x over previous
#include <cuda_runtime.h>
#include <cuda_bf16.h>
#include <cstdint>
#include <math.h>

#define BB 2
#define TT 2048
#define CC 1024
#define HH 16
#define DD 64
#define MM (BB*TT)   // 4096 rows

// ---------------------------------------------------------------------------
// Scratch (__device__ globals; allocation-free rule)
// ---------------------------------------------------------------------------
__device__ __nv_bfloat16 g_qhi[BB*HH*TT*DD], g_qlo[BB*HH*TT*DD];  // [B,H,T,D]
__device__ __nv_bfloat16 g_khi[BB*HH*TT*DD], g_klo[BB*HH*TT*DD];
__device__ __nv_bfloat16 g_vhi[BB*HH*TT*DD], g_vlo[BB*HH*TT*DD];

__device__ __nv_bfloat16 g_xhi[MM*CC], g_xlo[MM*CC];        // x split
__device__ __nv_bfloat16 g_whi[3*CC*CC], g_wlo[3*CC*CC];    // Wq|Wk|Wv concat
__device__ __nv_bfloat16 g_wohi[CC*CC], g_wolo[CC*CC];      // Wo
__device__ __nv_bfloat16 g_yhi[MM*CC], g_ylo[MM*CC];        // y split [B,T,C]
__device__ float g_bqkv[3*CC];                               // bq|bk|bv concat

// Q pre-scale: 1/sqrt(64) * log2(e)  (softmax done in base-2)
#define QSCALE (0.125f * 1.4426950408889634f)

// ---------------------------------------------------------------------------
// Helpers: ldmatrix / mma.sync / cp.async (baseline sm_80+)
// ---------------------------------------------------------------------------
__device__ __forceinline__ uint32_t smem_to_u32(const void* p) {
    uint32_t a;
    asm("{ .reg .u64 t; cvta.to.shared.u64 t, %1; cvt.u32.u64 %0, t; }"
        : "=r"(a) : "l"(p));
    return a;
}
__device__ __forceinline__ void ldsm_x4(uint32_t* r, uint32_t addr) {
    asm volatile("ldmatrix.sync.aligned.m8n8.x4.shared.b16 {%0,%1,%2,%3}, [%4];"
        : "=r"(r[0]), "=r"(r[1]), "=r"(r[2]), "=r"(r[3]) : "r"(addr));
}
__device__ __forceinline__ void ldsm_x4_t(uint32_t* r, uint32_t addr) {
    asm volatile("ldmatrix.sync.aligned.m8n8.x4.trans.shared.b16 {%0,%1,%2,%3}, [%4];"
        : "=r"(r[0]), "=r"(r[1]), "=r"(r[2]), "=r"(r[3]) : "r"(addr));
}
__device__ __forceinline__ void mma_bf16(float* d, const uint32_t* a,
                                         const uint32_t* b) {
    asm volatile(
        "mma.sync.aligned.m16n8k16.row.col.f32.bf16.bf16.f32 "
        "{%0,%1,%2,%3}, {%4,%5,%6,%7}, {%8,%9}, {%0,%1,%2,%3};"
        : "+f"(d[0]), "+f"(d[1]), "+f"(d[2]), "+f"(d[3])
        : "r"(a[0]), "r"(a[1]), "r"(a[2]), "r"(a[3]), "r"(b[0]), "r"(b[1]));
}
__device__ __forceinline__ void cp16(uint32_t saddr, const void* g) {
    asm volatile("cp.async.cg.shared.global [%0], [%1], 16;"
        :: "r"(saddr), "l"(g) : "memory");
}
#define CP_COMMIT()  asm volatile("cp.async.commit_group;" ::: "memory")
#define CP_WAIT1()   asm volatile("cp.async.wait_group 1;" ::: "memory")
#define CP_WAIT0()   asm volatile("cp.async.wait_group 0;" ::: "memory")

#define SMEM_SWIZZLE_128B(byte_offset) \
    ((byte_offset) ^ (((byte_offset) >> 3) & 0x70))

__device__ __forceinline__ float exp2a(float x) {
    float y; asm("ex2.approx.f32 %0, %1;" : "=f"(y) : "f"(x)); return y;
}
__device__ __forceinline__ uint32_t pack_bf16x2(float lo, float hi) {
    uint32_t r;
    asm("cvt.rn.bf16x2.f32 %0, %1, %2;" : "=r"(r) : "f"(hi), "f"(lo));
    return r;
}
__device__ __forceinline__ float2 bf16x2_to_f2(uint32_t u) {
    __nv_bfloat162 h = *reinterpret_cast<__nv_bfloat162*>(&u);
    return __bfloat1622float2(h);
}

// ---------------------------------------------------------------------------
// Prep: fp32 -> bf16 hi/lo splits (vectorized x4), bias concat.
// Region boundaries (1M multiples) are multiples of 4.
// ---------------------------------------------------------------------------
__global__ __launch_bounds__(256) void prep_split(
    const float* __restrict__ Wq, const float* __restrict__ Wk,
    const float* __restrict__ Wv, const float* __restrict__ Wo,
    const float* __restrict__ x)
{
    const int i = (blockIdx.x * 256 + threadIdx.x) * 4;   // 0 .. 8M-1, step 4
    const int WQKV = 3*CC*CC, WO = CC*CC;
    const float* src;
    __nv_bfloat16 *hi, *lo;
    int j;
    if (i < WQKV) {
        src = (i < CC*CC) ? Wq : (i < 2*CC*CC) ? Wk : Wv;
        src += (i & (CC*CC - 1));
        hi = g_whi; lo = g_wlo; j = i;
    } else if (i < WQKV + WO) {
        j = i - WQKV;
        src = Wo + j;
        hi = g_wohi; lo = g_wolo;
    } else {
        j = i - WQKV - WO;      // 0 .. 4M-1
        src = x + j;
        hi = g_xhi; lo = g_xlo;
    }
    float4 v = *(const float4*)src;
    uint32_t h0 = pack_bf16x2(v.x, v.y);
    uint32_t h1 = pack_bf16x2(v.z, v.w);
    float2 f0 = bf16x2_to_f2(h0);
    float2 f1 = bf16x2_to_f2(h1);
    uint32_t l0 = pack_bf16x2(v.x - f0.x, v.y - f0.y);
    uint32_t l1 = pack_bf16x2(v.z - f1.x, v.w - f1.y);
    *(uint2*)(hi + j) = make_uint2(h0, h1);
    *(uint2*)(lo + j) = make_uint2(l0, l1);
}

__global__ void prep_bias(const float* __restrict__ bq,
                          const float* __restrict__ bk,
                          const float* __restrict__ bv)
{
    int i = blockIdx.x * 256 + threadIdx.x;
    if (i < 3*CC)
        g_bqkv[i] = (i < CC) ? bq[i] : (i < 2*CC) ? bk[i-CC] : bv[i-2*CC];
}

// ---------------------------------------------------------------------------
// mma.sync GEMM: 128x128 tile of A[M,1024] @ B[N,1024]^T, bf16 hi/lo 3-term
// (R6-proven configuration: warp tile 32x64, 2-stage cp.async, 64 KB/stage).
// mode 0: A=x, B=WqWkWv, scatter bf16 hi/lo q/k/v (+bias, Q scaled).
// mode 1: A=y(hi/lo), B=Wo, write d_out fp32 (+bo).
// ---------------------------------------------------------------------------
#define CHUNK_K   64
#define NCHUNK    (CC / CHUNK_K)      // 16
#define BUF_BYTES (128*64*2)          // 16 KB per operand buffer
#define STAGE_BYTES (4*BUF_BYTES)     // 64 KB
#define OFF_AH 0
#define OFF_AL (1*BUF_BYTES)
#define OFF_BH (2*BUF_BYTES)
#define OFF_BL (3*BUF_BYTES)
#define GEMM_SMEM (2*STAGE_BYTES + 1024)

__global__ __launch_bounds__(256, 1) void gemm_tc(
    int mode, const float* __restrict__ bias1, float* __restrict__ outf)
{
    extern __shared__ char smem[];
    const uint32_t smem_u32 = smem_to_u32(smem);
    const uint32_t tile_u32 = (smem_u32 + 1023) & ~1023u;

    const int tid  = threadIdx.x;
    const int wid  = tid >> 5;
    const int lane = tid & 31;
    const int wm   = wid >> 1;          // 0..3 (M)
    const int wn   = wid & 1;           // 0..1 (N)
    const int m0   = blockIdx.y << 7;
    const int n0   = blockIdx.x << 7;

    const __nv_bfloat16 *Ah, *Al, *Bh, *Bl;
    if (mode == 0) { Ah = g_xhi; Al = g_xlo; Bh = g_whi;  Bl = g_wlo;  }
    else           { Ah = g_yhi; Al = g_ylo; Bh = g_wohi; Bl = g_wolo; }

    auto issue_chunk = [&](int c, int s) {
        const int kc = c * CHUNK_K;
        const uint32_t st = tile_u32 + s * STAGE_BYTES;
        #pragma unroll
        for (int i = 0; i < 4; i++) {
            int idx = tid + i*256;           // 0..1023
            int r   = idx >> 3;              // tile row 0..127
            int g   = idx & 7;               // 16B group in row
            uint32_t so = SMEM_SWIZZLE_128B((uint32_t)(r*128 + g*16));
            size_t aoff = (size_t)(m0 + r) * CC + kc + g*8;
            size_t boff = (size_t)(n0 + r) * CC + kc + g*8;
            cp16(st + OFF_AH + so, Ah + aoff);
            cp16(st + OFF_AL + so, Al + aoff);
            cp16(st + OFF_BH + so, Bh + boff);
            cp16(st + OFF_BL + so, Bl + boff);
        }
        CP_COMMIT();
    };

    float acc[2][8][4];
    #pragma unroll
    for (int mt = 0; mt < 2; mt++)
        #pragma unroll
        for (int nt = 0; nt < 8; nt++)
            #pragma unroll
            for (int e = 0; e < 4; e++) acc[mt][nt][e] = 0.f;

    issue_chunk(0, 0);
    issue_chunk(1, 1);

    for (int c = 0; c < NCHUNK; ++c) {
        const int s = c & 1;
        if (c + 1 < NCHUNK) { CP_WAIT1(); } else { CP_WAIT0(); }
        __syncthreads();

        const uint32_t sAh = tile_u32 + s*STAGE_BYTES + OFF_AH;
        const uint32_t sAl = tile_u32 + s*STAGE_BYTES + OFF_AL;
        const uint32_t sBh = tile_u32 + s*STAGE_BYTES + OFF_BH;
        const uint32_t sBl = tile_u32 + s*STAGE_BYTES + OFF_BL;

        #pragma unroll
        for (int ks = 0; ks < 4; ++ks) {
            uint32_t ah[2][4], al[2][4];
            #pragma unroll
            for (int mt = 0; mt < 2; ++mt) {
                int r = wm*32 + mt*16 + (lane & 15);
                int g = ks*2 + (lane >> 4);
                uint32_t off = SMEM_SWIZZLE_128B((uint32_t)(r*128 + g*16));
                ldsm_x4(ah[mt], sAh + off);
                ldsm_x4(al[mt], sAl + off);
            }
            #pragma unroll
            for (int np = 0; np < 4; ++np) {
                int n = wn*64 + np*16 + ((lane >> 4) << 3) + (lane & 7);
                int g = ks*2 + ((lane >> 3) & 1);
                uint32_t off = SMEM_SWIZZLE_128B((uint32_t)(n*128 + g*16));
                uint32_t bh[4], bl[4];
                ldsm_x4(bh, sBh + off);
                ldsm_x4(bl, sBl + off);
                #pragma unroll
                for (int mt = 0; mt < 2; ++mt) {
                    mma_bf16(acc[mt][2*np],   ah[mt], bh);
                    mma_bf16(acc[mt][2*np+1], ah[mt], bh + 2);
                    mma_bf16(acc[mt][2*np],   ah[mt], bl);
                    mma_bf16(acc[mt][2*np+1], ah[mt], bl + 2);
                    mma_bf16(acc[mt][2*np],   al[mt], bh);
                    mma_bf16(acc[mt][2*np+1], al[mt], bh + 2);
                }
            }
        }

        if (c + 2 < NCHUNK) {
            __syncthreads();
            issue_chunk(c + 2, s);
        }
    }

    // --- epilogue ---
    const int gl = lane >> 2;          // 0..7
    const int tl = lane & 3;           // 0..3
    #pragma unroll
    for (int mt = 0; mt < 2; ++mt) {
        #pragma unroll
        for (int nt = 0; nt < 8; ++nt) {
            const int row0 = m0 + wm*32 + mt*16 + gl;
            const int colg = n0 + wn*64 + nt*8 + 2*tl;
            if (mode == 0) {
                const int head = colg >> 6;        // 0..47
                const int proj = head >> 4;        // 0=q 1=k 2=v
                const int h    = head & 15;
                const int d0c  = colg & 63;
                __nv_bfloat16 *hiP, *loP;
                if (proj == 0)      { hiP = g_qhi; loP = g_qlo; }
                else if (proj == 1) { hiP = g_khi; loP = g_klo; }
                else                { hiP = g_vhi; loP = g_vlo; }
                const float2 bia = *(const float2*)&g_bqkv[colg];
                #pragma unroll
                for (int rr = 0; rr < 2; ++rr) {
                    const int m = row0 + rr*8;
                    const int b_ = m >> 11, t = m & 2047;
                    float v0 = acc[mt][nt][2*rr+0] + bia.x;
                    float v1 = acc[mt][nt][2*rr+1] + bia.y;
                    if (proj == 0) { v0 *= QSCALE; v1 *= QSCALE; }
                    uint32_t hp = pack_bf16x2(v0, v1);
                    float2 hf = bf16x2_to_f2(hp);
                    uint32_t lp = pack_bf16x2(v0 - hf.x, v1 - hf.y);
                    size_t off = ((size_t)(b_*HH + h) * TT + t) * DD + d0c;
                    *(uint32_t*)(hiP + off) = hp;
                    *(uint32_t*)(loP + off) = lp;
                }
            } else {
                const float2 bia = *(const float2*)&bias1[colg];
                #pragma unroll
                for (int rr = 0; rr < 2; ++rr) {
                    const int m = row0 + rr*8;
                    float2 o;
                    o.x = acc[mt][nt][2*rr+0] + bia.x;
                    o.y = acc[mt][nt][2*rr+1] + bia.y;
                    *(float2*)(outf + (size_t)m * CC + colg) = o;
                }
            }
        }
    }
}

// ---------------------------------------------------------------------------
// Tensor-core flash attention (R6 configuration — known-good).
// ---------------------------------------------------------------------------
#define F_SMEM (32768 + 65536)   // Q(hi+lo) 32KB + 2 stages x (K/V hi/lo) 32KB

__global__ __launch_bounds__(256, 1) void flash_tc()
{
    extern __shared__ char fsm[];
    const uint32_t sb  = smem_to_u32(fsm);
    const uint32_t sQh = sb, sQl = sb + 16384;

    const int tid = threadIdx.x, wid = tid >> 5, lane = tid & 31;
    const int gl = lane >> 2, tl = lane & 3;
    const int jq = (int)gridDim.x - 1 - (int)blockIdx.x;   // heavy tiles first
    const int q0 = jq << 7;
    const int bh = blockIdx.y;
    const size_t hb = (size_t)bh * TT * DD;
    const __nv_bfloat16 *qhp = g_qhi + hb + (size_t)q0 * DD;
    const __nv_bfloat16 *qlp = g_qlo + hb + (size_t)q0 * DD;
    const __nv_bfloat16 *khp = g_khi + hb, *klp = g_klo + hb;
    const __nv_bfloat16 *vhp = g_vhi + hb, *vlp = g_vlo + hb;
    const int ntiles = 2*jq + 2;

    // --- Q tile (hi+lo): 128 rows x 8 chunks x 2 buffers = 2048 chunks ---
    #pragma unroll
    for (int i = 0; i < 8; i++) {
        int idx = tid + i*256;              // 0..2047
        int buf = idx >> 10;                // 0 hi, 1 lo
        int rc = idx & 1023; int r = rc >> 3, c = rc & 7;
        uint32_t so = SMEM_SWIZZLE_128B((uint32_t)(r*128 + c*16));
        cp16((buf ? sQl : sQh) + so, (buf ? qlp : qhp) + (size_t)r*DD + c*8);
    }
    CP_COMMIT();

    auto issue_kv = [&](int kt, int s) {
        const uint32_t st = sb + 32768 + s*32768;
        const int r0 = kt << 6;
        #pragma unroll
        for (int i = 0; i < 8; i++) {
            int idx = tid + i*256;          // 0..2047
            int buf = idx >> 9;             // 0 khi,1 klo,2 vhi,3 vlo
            int rc = idx & 511; int r = rc >> 3, c = rc & 7;
            uint32_t so = SMEM_SWIZZLE_128B((uint32_t)(r*128 + c*16));
            const __nv_bfloat16* src =
                (buf == 0 ? khp : buf == 1 ? klp : buf == 2 ? vhp : vlp)
                + (size_t)(r0 + r) * DD + c*8;
            cp16(st + buf*8192 + so, src);
        }
        CP_COMMIT();
    };
    issue_kv(0, 0);
    issue_kv(1, 1);

    CP_WAIT1();              // Q + stage0 complete
    __syncthreads();

    // --- Q fragments (persistent) ---
    const int qrow = wid << 4;
    uint32_t qfh[4][4], qfl[4][4];
    #pragma unroll
    for (int dc = 0; dc < 4; dc++) {
        uint32_t so = SMEM_SWIZZLE_128B((uint32_t)(
            (qrow + (lane & 15))*128 + (dc*16 + ((lane >> 4) << 3))*2));
        ldsm_x4(qfh[dc], sQh + so);
        ldsm_x4(qfl[dc], sQl + so);
    }

    float m_run[2] = {-1e30f, -1e30f};
    float l_run[2] = {0.f, 0.f};
    float oacc[8][4];
    #pragma unroll
    for (int f = 0; f < 8; f++)
        #pragma unroll
        for (int e = 0; e < 4; e++) oacc[f][e] = 0.f;

    for (int kt = 0; kt < ntiles; kt++) {
        const int s = kt & 1;
        if (kt + 1 < ntiles) { CP_WAIT1(); } else { CP_WAIT0(); }
        __syncthreads();

        const bool active = (q0 + qrow + 15) >= (kt << 6);
        if (active) {
            const uint32_t st = sb + 32768 + s*32768;

            // ---- S = Q @ K^T (3-term) ----
            float sacc[8][4] = {};
            #pragma unroll
            for (int dc = 0; dc < 4; dc++) {
                #pragma unroll
                for (int ng = 0; ng < 4; ng++) {
                    uint32_t so = SMEM_SWIZZLE_128B((uint32_t)(
                        ((ng<<4) + (lane & 7) + ((lane >> 4) << 3))*128 +
                        ((dc<<4) + ((lane >> 3) & 1)*8)*2));
                    uint32_t kfh[4], kfl[4];
                    ldsm_x4(kfh, st + so);
                    ldsm_x4(kfl, st + 8192 + so);
                    mma_bf16(sacc[2*ng],   qfh[dc], kfh);
                    mma_bf16(sacc[2*ng+1], qfh[dc], kfh + 2);
                    mma_bf16(sacc[2*ng],   qfh[dc], kfl);
                    mma_bf16(sacc[2*ng+1], qfh[dc], kfl + 2);
                    mma_bf16(sacc[2*ng],   qfl[dc], kfh);
                    mma_bf16(sacc[2*ng+1], qfl[dc], kfh + 2);
                }
            }

            // ---- causal mask (diagonal tiles only) ----
            if (kt >= 2*jq) {
                const int r0g = q0 + qrow + gl;
                #pragma unroll
                for (int f = 0; f < 8; f++) {
                    const int kc0 = (kt << 6) + (f << 3) + (tl << 1);
                    if (kc0     > r0g)     sacc[f][0] = -1e30f;
                    if (kc0 + 1 > r0g)     sacc[f][1] = -1e30f;
                    if (kc0     > r0g + 8) sacc[f][2] = -1e30f;
                    if (kc0 + 1 > r0g + 8) sacc[f][3] = -1e30f;
                }
            }

            // ---- online softmax (base 2) ----
            float mx0 = m_run[0], mx1 = m_run[1];
            #pragma unroll
            for (int f = 0; f < 8; f++) {
                mx0 = fmaxf(mx0, fmaxf(sacc[f][0], sacc[f][1]));
                mx1 = fmaxf(mx1, fmaxf(sacc[f][2], sacc[f][3]));
            }
            mx0 = fmaxf(mx0, __shfl_xor_sync(0xffffffffu, mx0, 1));
            mx0 = fmaxf(mx0, __shfl_xor_sync(0xffffffffu, mx0, 2));
            mx1 = fmaxf(mx1, __shfl_xor_sync(0xffffffffu, mx1, 1));
            mx1 = fmaxf(mx1, __shfl_xor_sync(0xffffffffu, mx1, 2));
            const float a0 = exp2a(m_run[0] - mx0);
            const float a1 = exp2a(m_run[1] - mx1);
            m_run[0] = mx0; m_run[1] = mx1;

            float sum0 = 0.f, sum1 = 0.f;
            uint32_t pAh[8], pBh[8], pAl[8], pBl[8];
            #pragma unroll
            for (int f = 0; f < 8; f++) {
                float p0 = exp2a(sacc[f][0] - mx0);
                float p1 = exp2a(sacc[f][1] - mx0);
                float p2 = exp2a(sacc[f][2] - mx1);
                float p3 = exp2a(sacc[f][3] - mx1);
                sum0 += p0 + p1; sum1 += p2 + p3;
                uint32_t h01 = pack_bf16x2(p0, p1);
                uint32_t h23 = pack_bf16x2(p2, p3);
                float2 f01 = bf16x2_to_f2(h01);
                float2 f23 = bf16x2_to_f2(h23);
                pAh[f] = h01; pBh[f] = h23;
                pAl[f] = pack_bf16x2(p0 - f01.x, p1 - f01.y);
                pBl[f] = pack_bf16x2(p2 - f23.x, p3 - f23.y);
            }
            sum0 += __shfl_xor_sync(0xffffffffu, sum0, 1);
            sum0 += __shfl_xor_sync(0xffffffffu, sum0, 2);
            sum1 += __shfl_xor_sync(0xffffffffu, sum1, 1);
            sum1 += __shfl_xor_sync(0xffffffffu, sum1, 2);
            l_run[0] = l_run[0]*a0 + sum0;
            l_run[1] = l_run[1]*a1 + sum1;
            #pragma unroll
            for (int f = 0; f < 8; f++) {
                oacc[f][0] *= a0; oacc[f][1] *= a0;
                oacc[f][2] *= a1; oacc[f][3] *= a1;
            }

            // ---- O += P @ V (3-term; V via ldmatrix.trans) ----
            #pragma unroll
            for (int kc = 0; kc < 4; kc++) {
                uint32_t Ahh[4] = {pAh[2*kc], pBh[2*kc], pAh[2*kc+1], pBh[2*kc+1]};
                uint32_t All[4] = {pAl[2*kc], pBl[2*kc], pAl[2*kc+1], pBl[2*kc+1]};
                #pragma unroll
                for (int dg = 0; dg < 4; dg++) {
                    uint32_t so = SMEM_SWIZZLE_128B((uint32_t)(
                        ((kc<<4) + (lane & 7) + ((lane >> 3) & 1)*8)*128 +
                        ((dg<<4) + (lane >> 4)*8)*2));
                    uint32_t vfh[4], vfl[4];
                    ldsm_x4_t(vfh, st + 16384 + so);
                    ldsm_x4_t(vfl, st + 24576 + so);
                    mma_bf16(oacc[2*dg],   Ahh, vfh);
                    mma_bf16(oacc[2*dg+1], Ahh, vfh + 2);
                    mma_bf16(oacc[2*dg],   Ahh, vfl);
                    mma_bf16(oacc[2*dg+1], Ahh, vfl + 2);
                    mma_bf16(oacc[2*dg],   All, vfh);
                    mma_bf16(oacc[2*dg+1], All, vfh + 2);
                }
            }
        }

        __syncthreads();
        if (kt + 2 < ntiles) issue_kv(kt + 2, s);
    }

    // ---- epilogue: normalize, split hi/lo, write y [B,T,C] ----
    const float inv0 = 1.f / l_run[0];
    const float inv1 = 1.f / l_run[1];
    const int b_ = bh >> 4, h = bh & 15;
    const int t0 = q0 + qrow + gl, t1 = t0 + 8;
    #pragma unroll
    for (int f = 0; f < 8; f++) {
        const int col = h*DD + (f << 3) + (tl << 1);
        {
            float y0 = oacc[f][0] * inv0, y1 = oacc[f][1] * inv0;
            uint32_t hp = pack_bf16x2(y0, y1);
            float2 hf = bf16x2_to_f2(hp);
            uint32_t lp = pack_bf16x2(y0 - hf.x, y1 - hf.y);
            size_t off = (size_t)(b_*TT + t0) * CC + col;
            *(uint32_t*)(g_yhi + off) = hp;
            *(uint32_t*)(g_ylo + off) = lp;
        }
        {
            float y2 = oacc[f][2] * inv1, y3 = oacc[f][3] * inv1;
            uint32_t hp = pack_bf16x2(y2, y3);
            float2 hf = bf16x2_to_f2(hp);
            uint32_t lp = pack_bf16x2(y2 - hf.x, y3 - hf.y);
            size_t off = (size_t)(b_*TT + t1) * CC + col;
            *(uint32_t*)(g_yhi + off) = hp;
            *(uint32_t*)(g_ylo + off) = lp;
        }
    }
}

// ---------------------------------------------------------------------------

extern "C" void kernel_launch(void* const* d_in, const int* in_sizes, int n_in,
                              void* d_out, int out_size)
{
    const float* x  = (const float*)d_in[0];
    const float* Wq = (const float*)d_in[1];
    const float* bq = (const float*)d_in[2];
    const float* Wk = (const float*)d_in[3];
    const float* bk = (const float*)d_in[4];
    const float* Wv = (const float*)d_in[5];
    const float* bv = (const float*)d_in[6];
    const float* Wo = (const float*)d_in[7];
    const float* bo = (const float*)d_in[8];
    float* out = (float*)d_out;

    // 0) fp32 -> bf16 hi/lo splits (x4 vectorized) + bias concat
    prep_split<<<(8*1024*1024)/1024, 256>>>(Wq, Wk, Wv, Wo, x);
    prep_bias<<<12, 256>>>(bq, bk, bv);

    // 1) fused QKV projection -> bf16 hi/lo q/k/v (Q pre-scaled)
    cudaFuncSetAttribute(gemm_tc, cudaFuncAttributeMaxDynamicSharedMemorySize,
                         GEMM_SMEM);
    gemm_tc<<<dim3(3*CC/128, MM/128), 256, GEMM_SMEM>>>(0, nullptr, nullptr);

    // 2) tensor-core causal flash attention -> y hi/lo
    cudaFuncSetAttribute(flash_tc, cudaFuncAttributeMaxDynamicSharedMemorySize,
                         F_SMEM);
    flash_tc<<<dim3(TT/128, BB*HH), 256, F_SMEM>>>();

    // 3) output projection -> d_out
    gemm_tc<<<dim3(CC/128, MM/128), 256, GEMM_SMEM>>>(1, bo, out);
}

// round 9
// speedup vs baseline: 1.5494x; 1.0434x over previous
#include <cuda_runtime.h>
#include <cuda_bf16.h>
#include <cstdint>
#include <math.h>

#define BB 2
#define TT 2048
#define CC 1024
#define HH 16
#define DD 64
#define MM (BB*TT)   // 4096 rows

// ---------------------------------------------------------------------------
// Scratch (__device__ globals; allocation-free rule)
// ---------------------------------------------------------------------------
__device__ __nv_bfloat16 g_qhi[BB*HH*TT*DD], g_qlo[BB*HH*TT*DD];  // [B,H,T,D]
__device__ __nv_bfloat16 g_khi[BB*HH*TT*DD], g_klo[BB*HH*TT*DD];
__device__ __nv_bfloat16 g_vhi[BB*HH*TT*DD], g_vlo[BB*HH*TT*DD];

__device__ __nv_bfloat16 g_xhi[MM*CC], g_xlo[MM*CC];        // x split
__device__ __nv_bfloat16 g_whi[3*CC*CC], g_wlo[3*CC*CC];    // Wq|Wk|Wv concat
__device__ __nv_bfloat16 g_wohi[CC*CC], g_wolo[CC*CC];      // Wo
__device__ __nv_bfloat16 g_yhi[MM*CC], g_ylo[MM*CC];        // y split [B,T,C]
__device__ float g_bqkv[3*CC];                               // bq|bk|bv concat

// Q pre-scale: 1/sqrt(64) * log2(e)  (softmax done in base-2)
#define QSCALE (0.125f * 1.4426950408889634f)

// ---------------------------------------------------------------------------
// Helpers: ldmatrix / mma.sync / cp.async (baseline sm_80+)
// ---------------------------------------------------------------------------
__device__ __forceinline__ uint32_t smem_to_u32(const void* p) {
    uint32_t a;
    asm("{ .reg .u64 t; cvta.to.shared.u64 t, %1; cvt.u32.u64 %0, t; }"
        : "=r"(a) : "l"(p));
    return a;
}
__device__ __forceinline__ void ldsm_x4(uint32_t* r, uint32_t addr) {
    asm volatile("ldmatrix.sync.aligned.m8n8.x4.shared.b16 {%0,%1,%2,%3}, [%4];"
        : "=r"(r[0]), "=r"(r[1]), "=r"(r[2]), "=r"(r[3]) : "r"(addr));
}
__device__ __forceinline__ void ldsm_x4_t(uint32_t* r, uint32_t addr) {
    asm volatile("ldmatrix.sync.aligned.m8n8.x4.trans.shared.b16 {%0,%1,%2,%3}, [%4];"
        : "=r"(r[0]), "=r"(r[1]), "=r"(r[2]), "=r"(r[3]) : "r"(addr));
}
__device__ __forceinline__ void mma_bf16(float* d, const uint32_t* a,
                                         const uint32_t* b) {
    asm volatile(
        "mma.sync.aligned.m16n8k16.row.col.f32.bf16.bf16.f32 "
        "{%0,%1,%2,%3}, {%4,%5,%6,%7}, {%8,%9}, {%0,%1,%2,%3};"
        : "+f"(d[0]), "+f"(d[1]), "+f"(d[2]), "+f"(d[3])
        : "r"(a[0]), "r"(a[1]), "r"(a[2]), "r"(a[3]), "r"(b[0]), "r"(b[1]));
}
__device__ __forceinline__ void cp16(uint32_t saddr, const void* g) {
    asm volatile("cp.async.cg.shared.global [%0], [%1], 16;"
        :: "r"(saddr), "l"(g) : "memory");
}
#define CP_COMMIT()  asm volatile("cp.async.commit_group;" ::: "memory")
#define CP_WAIT1()   asm volatile("cp.async.wait_group 1;" ::: "memory")
#define CP_WAIT0()   asm volatile("cp.async.wait_group 0;" ::: "memory")

#define SMEM_SWIZZLE_128B(byte_offset) \
    ((byte_offset) ^ (((byte_offset) >> 3) & 0x70))

__device__ __forceinline__ float exp2a(float x) {
    float y; asm("ex2.approx.f32 %0, %1;" : "=f"(y) : "f"(x)); return y;
}
__device__ __forceinline__ uint32_t pack_bf16x2(float lo, float hi) {
    uint32_t r;
    asm("cvt.rn.bf16x2.f32 %0, %1, %2;" : "=r"(r) : "f"(hi), "f"(lo));
    return r;
}
__device__ __forceinline__ float2 bf16x2_to_f2(uint32_t u) {
    __nv_bfloat162 h = *reinterpret_cast<__nv_bfloat162*>(&u);
    return __bfloat1622float2(h);
}

// ---------------------------------------------------------------------------
// Prep: fp32 -> bf16 hi/lo splits (vectorized x4), bias concat.
// ---------------------------------------------------------------------------
__global__ __launch_bounds__(256) void prep_split(
    const float* __restrict__ Wq, const float* __restrict__ Wk,
    const float* __restrict__ Wv, const float* __restrict__ Wo,
    const float* __restrict__ x)
{
    const int i = (blockIdx.x * 256 + threadIdx.x) * 4;   // 0 .. 8M-1, step 4
    const int WQKV = 3*CC*CC, WO = CC*CC;
    const float* src;
    __nv_bfloat16 *hi, *lo;
    int j;
    if (i < WQKV) {
        src = (i < CC*CC) ? Wq : (i < 2*CC*CC) ? Wk : Wv;
        src += (i & (CC*CC - 1));
        hi = g_whi; lo = g_wlo; j = i;
    } else if (i < WQKV + WO) {
        j = i - WQKV;
        src = Wo + j;
        hi = g_wohi; lo = g_wolo;
    } else {
        j = i - WQKV - WO;      // 0 .. 4M-1
        src = x + j;
        hi = g_xhi; lo = g_xlo;
    }
    float4 v = *(const float4*)src;
    uint32_t h0 = pack_bf16x2(v.x, v.y);
    uint32_t h1 = pack_bf16x2(v.z, v.w);
    float2 f0 = bf16x2_to_f2(h0);
    float2 f1 = bf16x2_to_f2(h1);
    uint32_t l0 = pack_bf16x2(v.x - f0.x, v.y - f0.y);
    uint32_t l1 = pack_bf16x2(v.z - f1.x, v.w - f1.y);
    *(uint2*)(hi + j) = make_uint2(h0, h1);
    *(uint2*)(lo + j) = make_uint2(l0, l1);
}

__global__ void prep_bias(const float* __restrict__ bq,
                          const float* __restrict__ bk,
                          const float* __restrict__ bv)
{
    int i = blockIdx.x * 256 + threadIdx.x;
    if (i < 3*CC)
        g_bqkv[i] = (i < CC) ? bq[i] : (i < 2*CC) ? bk[i-CC] : bv[i-2*CC];
}

// ---------------------------------------------------------------------------
// mma.sync GEMM: 128x128 tile (R6-proven, unchanged).
// ---------------------------------------------------------------------------
#define CHUNK_K   64
#define NCHUNK    (CC / CHUNK_K)      // 16
#define BUF_BYTES (128*64*2)          // 16 KB per operand buffer
#define STAGE_BYTES (4*BUF_BYTES)     // 64 KB
#define OFF_AH 0
#define OFF_AL (1*BUF_BYTES)
#define OFF_BH (2*BUF_BYTES)
#define OFF_BL (3*BUF_BYTES)
#define GEMM_SMEM (2*STAGE_BYTES + 1024)

__global__ __launch_bounds__(256, 1) void gemm_tc(
    int mode, const float* __restrict__ bias1, float* __restrict__ outf)
{
    extern __shared__ char smem[];
    const uint32_t smem_u32 = smem_to_u32(smem);
    const uint32_t tile_u32 = (smem_u32 + 1023) & ~1023u;

    const int tid  = threadIdx.x;
    const int wid  = tid >> 5;
    const int lane = tid & 31;
    const int wm   = wid >> 1;          // 0..3 (M)
    const int wn   = wid & 1;           // 0..1 (N)
    const int m0   = blockIdx.y << 7;
    const int n0   = blockIdx.x << 7;

    const __nv_bfloat16 *Ah, *Al, *Bh, *Bl;
    if (mode == 0) { Ah = g_xhi; Al = g_xlo; Bh = g_whi;  Bl = g_wlo;  }
    else           { Ah = g_yhi; Al = g_ylo; Bh = g_wohi; Bl = g_wolo; }

    auto issue_chunk = [&](int c, int s) {
        const int kc = c * CHUNK_K;
        const uint32_t st = tile_u32 + s * STAGE_BYTES;
        #pragma unroll
        for (int i = 0; i < 4; i++) {
            int idx = tid + i*256;           // 0..1023
            int r   = idx >> 3;              // tile row 0..127
            int g   = idx & 7;               // 16B group in row
            uint32_t so = SMEM_SWIZZLE_128B((uint32_t)(r*128 + g*16));
            size_t aoff = (size_t)(m0 + r) * CC + kc + g*8;
            size_t boff = (size_t)(n0 + r) * CC + kc + g*8;
            cp16(st + OFF_AH + so, Ah + aoff);
            cp16(st + OFF_AL + so, Al + aoff);
            cp16(st + OFF_BH + so, Bh + boff);
            cp16(st + OFF_BL + so, Bl + boff);
        }
        CP_COMMIT();
    };

    float acc[2][8][4];
    #pragma unroll
    for (int mt = 0; mt < 2; mt++)
        #pragma unroll
        for (int nt = 0; nt < 8; nt++)
            #pragma unroll
            for (int e = 0; e < 4; e++) acc[mt][nt][e] = 0.f;

    issue_chunk(0, 0);
    issue_chunk(1, 1);

    for (int c = 0; c < NCHUNK; ++c) {
        const int s = c & 1;
        if (c + 1 < NCHUNK) { CP_WAIT1(); } else { CP_WAIT0(); }
        __syncthreads();

        const uint32_t sAh = tile_u32 + s*STAGE_BYTES + OFF_AH;
        const uint32_t sAl = tile_u32 + s*STAGE_BYTES + OFF_AL;
        const uint32_t sBh = tile_u32 + s*STAGE_BYTES + OFF_BH;
        const uint32_t sBl = tile_u32 + s*STAGE_BYTES + OFF_BL;

        #pragma unroll
        for (int ks = 0; ks < 4; ++ks) {
            uint32_t ah[2][4], al[2][4];
            #pragma unroll
            for (int mt = 0; mt < 2; ++mt) {
                int r = wm*32 + mt*16 + (lane & 15);
                int g = ks*2 + (lane >> 4);
                uint32_t off = SMEM_SWIZZLE_128B((uint32_t)(r*128 + g*16));
                ldsm_x4(ah[mt], sAh + off);
                ldsm_x4(al[mt], sAl + off);
            }
            #pragma unroll
            for (int np = 0; np < 4; ++np) {
                int n = wn*64 + np*16 + ((lane >> 4) << 3) + (lane & 7);
                int g = ks*2 + ((lane >> 3) & 1);
                uint32_t off = SMEM_SWIZZLE_128B((uint32_t)(n*128 + g*16));
                uint32_t bh[4], bl[4];
                ldsm_x4(bh, sBh + off);
                ldsm_x4(bl, sBl + off);
                #pragma unroll
                for (int mt = 0; mt < 2; ++mt) {
                    mma_bf16(acc[mt][2*np],   ah[mt], bh);
                    mma_bf16(acc[mt][2*np+1], ah[mt], bh + 2);
                    mma_bf16(acc[mt][2*np],   ah[mt], bl);
                    mma_bf16(acc[mt][2*np+1], ah[mt], bl + 2);
                    mma_bf16(acc[mt][2*np],   al[mt], bh);
                    mma_bf16(acc[mt][2*np+1], al[mt], bh + 2);
                }
            }
        }

        if (c + 2 < NCHUNK) {
            __syncthreads();
            issue_chunk(c + 2, s);
        }
    }

    // --- epilogue ---
    const int gl = lane >> 2;          // 0..7
    const int tl = lane & 3;           // 0..3
    #pragma unroll
    for (int mt = 0; mt < 2; ++mt) {
        #pragma unroll
        for (int nt = 0; nt < 8; ++nt) {
            const int row0 = m0 + wm*32 + mt*16 + gl;
            const int colg = n0 + wn*64 + nt*8 + 2*tl;
            if (mode == 0) {
                const int head = colg >> 6;        // 0..47
                const int proj = head >> 4;        // 0=q 1=k 2=v
                const int h    = head & 15;
                const int d0c  = colg & 63;
                __nv_bfloat16 *hiP, *loP;
                if (proj == 0)      { hiP = g_qhi; loP = g_qlo; }
                else if (proj == 1) { hiP = g_khi; loP = g_klo; }
                else                { hiP = g_vhi; loP = g_vlo; }
                const float2 bia = *(const float2*)&g_bqkv[colg];
                #pragma unroll
                for (int rr = 0; rr < 2; ++rr) {
                    const int m = row0 + rr*8;
                    const int b_ = m >> 11, t = m & 2047;
                    float v0 = acc[mt][nt][2*rr+0] + bia.x;
                    float v1 = acc[mt][nt][2*rr+1] + bia.y;
                    if (proj == 0) { v0 *= QSCALE; v1 *= QSCALE; }
                    uint32_t hp = pack_bf16x2(v0, v1);
                    float2 hf = bf16x2_to_f2(hp);
                    uint32_t lp = pack_bf16x2(v0 - hf.x, v1 - hf.y);
                    size_t off = ((size_t)(b_*HH + h) * TT + t) * DD + d0c;
                    *(uint32_t*)(hiP + off) = hp;
                    *(uint32_t*)(loP + off) = lp;
                }
            } else {
                const float2 bia = *(const float2*)&bias1[colg];
                #pragma unroll
                for (int rr = 0; rr < 2; ++rr) {
                    const int m = row0 + rr*8;
                    float2 o;
                    o.x = acc[mt][nt][2*rr+0] + bia.x;
                    o.y = acc[mt][nt][2*rr+1] + bia.y;
                    *(float2*)(outf + (size_t)m * CC + colg) = o;
                }
            }
        }
    }
}

// ---------------------------------------------------------------------------
// Tensor-core flash attention: 64-query x 64-key tiles, 4 warps / 128 thr,
// 2 CTAs per SM (80 KB smem, ~27K regs/CTA) so softmax of one CTA overlaps
// MMAs of the other. Per-warp layout identical to R6 (16 q-rows/warp).
// ---------------------------------------------------------------------------
#define F_THREADS 128
#define F_SMEM (16384 + 65536)   // Q(hi+lo) 16KB + 2 stages x (K/V hi/lo) 32KB

__global__ __launch_bounds__(F_THREADS, 2) void flash_tc()
{
    extern __shared__ char fsm[];
    const uint32_t sb  = smem_to_u32(fsm);
    const uint32_t sQh = sb, sQl = sb + 8192;

    const int tid = threadIdx.x, wid = tid >> 5, lane = tid & 31;
    const int gl = lane >> 2, tl = lane & 3;
    const int jq = (int)gridDim.x - 1 - (int)blockIdx.x;   // heavy tiles first
    const int q0 = jq << 6;                                 // 64-row q tiles
    const int bh = blockIdx.y;
    const size_t hb = (size_t)bh * TT * DD;
    const __nv_bfloat16 *qhp = g_qhi + hb + (size_t)q0 * DD;
    const __nv_bfloat16 *qlp = g_qlo + hb + (size_t)q0 * DD;
    const __nv_bfloat16 *khp = g_khi + hb, *klp = g_klo + hb;
    const __nv_bfloat16 *vhp = g_vhi + hb, *vlp = g_vlo + hb;
    const int ntiles = jq + 1;

    // --- Q tile (hi+lo): 64 rows x 8 chunks x 2 buffers = 1024 chunks ---
    #pragma unroll
    for (int i = 0; i < 8; i++) {
        int idx = tid + i*F_THREADS;        // 0..1023
        int buf = idx >> 9;                 // 0 hi, 1 lo
        int rc = idx & 511; int r = rc >> 3, c = rc & 7;
        uint32_t so = SMEM_SWIZZLE_128B((uint32_t)(r*128 + c*16));
        cp16((buf ? sQl : sQh) + so, (buf ? qlp : qhp) + (size_t)r*DD + c*8);
    }
    CP_COMMIT();

    auto issue_kv = [&](int kt, int s) {
        const uint32_t st = sb + 16384 + s*32768;
        const int r0 = kt << 6;
        #pragma unroll
        for (int i = 0; i < 16; i++) {
            int idx = tid + i*F_THREADS;    // 0..2047
            int buf = idx >> 9;             // 0 khi,1 klo,2 vhi,3 vlo
            int rc = idx & 511; int r = rc >> 3, c = rc & 7;
            uint32_t so = SMEM_SWIZZLE_128B((uint32_t)(r*128 + c*16));
            const __nv_bfloat16* src =
                (buf == 0 ? khp : buf == 1 ? klp : buf == 2 ? vhp : vlp)
                + (size_t)(r0 + r) * DD + c*8;
            cp16(st + buf*8192 + so, src);
        }
        CP_COMMIT();
    };
    issue_kv(0, 0);
    issue_kv(1, 1);       // kt=1 prefetch (reads valid memory even if unused)

    CP_WAIT1();           // Q + stage0 complete
    __syncthreads();

    // --- Q fragments (persistent) ---
    const int qrow = wid << 4;               // 0..48
    uint32_t qfh[4][4], qfl[4][4];
    #pragma unroll
    for (int dc = 0; dc < 4; dc++) {
        uint32_t so = SMEM_SWIZZLE_128B((uint32_t)(
            (qrow + (lane & 15))*128 + (dc*16 + ((lane >> 4) << 3))*2));
        ldsm_x4(qfh[dc], sQh + so);
        ldsm_x4(qfl[dc], sQl + so);
    }

    float m_run[2] = {-1e30f, -1e30f};
    float l_run[2] = {0.f, 0.f};
    float oacc[8][4];
    #pragma unroll
    for (int f = 0; f < 8; f++)
        #pragma unroll
        for (int e = 0; e < 4; e++) oacc[f][e] = 0.f;

    for (int kt = 0; kt < ntiles; kt++) {
        const int s = kt & 1;
        if (kt + 1 < ntiles) { CP_WAIT1(); } else { CP_WAIT0(); }
        __syncthreads();

        const uint32_t st = sb + 16384 + s*32768;

        // ---- S = Q @ K^T (3-term) ----
        float sacc[8][4] = {};
        #pragma unroll
        for (int dc = 0; dc < 4; dc++) {
            #pragma unroll
            for (int ng = 0; ng < 4; ng++) {
                uint32_t so = SMEM_SWIZZLE_128B((uint32_t)(
                    ((ng<<4) + (lane & 7) + ((lane >> 4) << 3))*128 +
                    ((dc<<4) + ((lane >> 3) & 1)*8)*2));
                uint32_t kfh[4], kfl[4];
                ldsm_x4(kfh, st + so);
                ldsm_x4(kfl, st + 8192 + so);
                mma_bf16(sacc[2*ng],   qfh[dc], kfh);
                mma_bf16(sacc[2*ng+1], qfh[dc], kfh + 2);
                mma_bf16(sacc[2*ng],   qfh[dc], kfl);
                mma_bf16(sacc[2*ng+1], qfh[dc], kfl + 2);
                mma_bf16(sacc[2*ng],   qfl[dc], kfh);
                mma_bf16(sacc[2*ng+1], qfl[dc], kfh + 2);
            }
        }

        // ---- causal mask (diagonal = last tile) ----
        if (kt == jq) {
            const int r0g = q0 + qrow + gl;
            #pragma unroll
            for (int f = 0; f < 8; f++) {
                const int kc0 = (kt << 6) + (f << 3) + (tl << 1);
                if (kc0     > r0g)     sacc[f][0] = -1e30f;
                if (kc0 + 1 > r0g)     sacc[f][1] = -1e30f;
                if (kc0     > r0g + 8) sacc[f][2] = -1e30f;
                if (kc0 + 1 > r0g + 8) sacc[f][3] = -1e30f;
            }
        }

        // ---- online softmax (base 2) ----
        float mx0 = m_run[0], mx1 = m_run[1];
        #pragma unroll
        for (int f = 0; f < 8; f++) {
            mx0 = fmaxf(mx0, fmaxf(sacc[f][0], sacc[f][1]));
            mx1 = fmaxf(mx1, fmaxf(sacc[f][2], sacc[f][3]));
        }
        mx0 = fmaxf(mx0, __shfl_xor_sync(0xffffffffu, mx0, 1));
        mx0 = fmaxf(mx0, __shfl_xor_sync(0xffffffffu, mx0, 2));
        mx1 = fmaxf(mx1, __shfl_xor_sync(0xffffffffu, mx1, 1));
        mx1 = fmaxf(mx1, __shfl_xor_sync(0xffffffffu, mx1, 2));
        const float a0 = exp2a(m_run[0] - mx0);
        const float a1 = exp2a(m_run[1] - mx1);
        m_run[0] = mx0; m_run[1] = mx1;

        float sum0 = 0.f, sum1 = 0.f;
        uint32_t pAh[8], pBh[8], pAl[8], pBl[8];
        #pragma unroll
        for (int f = 0; f < 8; f++) {
            float p0 = exp2a(sacc[f][0] - mx0);
            float p1 = exp2a(sacc[f][1] - mx0);
            float p2 = exp2a(sacc[f][2] - mx1);
            float p3 = exp2a(sacc[f][3] - mx1);
            sum0 += p0 + p1; sum1 += p2 + p3;
            uint32_t h01 = pack_bf16x2(p0, p1);
            uint32_t h23 = pack_bf16x2(p2, p3);
            float2 f01 = bf16x2_to_f2(h01);
            float2 f23 = bf16x2_to_f2(h23);
            pAh[f] = h01; pBh[f] = h23;
            pAl[f] = pack_bf16x2(p0 - f01.x, p1 - f01.y);
            pBl[f] = pack_bf16x2(p2 - f23.x, p3 - f23.y);
        }
        sum0 += __shfl_xor_sync(0xffffffffu, sum0, 1);
        sum0 += __shfl_xor_sync(0xffffffffu, sum0, 2);
        sum1 += __shfl_xor_sync(0xffffffffu, sum1, 1);
        sum1 += __shfl_xor_sync(0xffffffffu, sum1, 2);
        l_run[0] = l_run[0]*a0 + sum0;
        l_run[1] = l_run[1]*a1 + sum1;
        #pragma unroll
        for (int f = 0; f < 8; f++) {
            oacc[f][0] *= a0; oacc[f][1] *= a0;
            oacc[f][2] *= a1; oacc[f][3] *= a1;
        }

        // ---- O += P @ V (3-term; V via ldmatrix.trans) ----
        #pragma unroll
        for (int kc = 0; kc < 4; kc++) {
            uint32_t Ahh[4] = {pAh[2*kc], pBh[2*kc], pAh[2*kc+1], pBh[2*kc+1]};
            uint32_t All[4] = {pAl[2*kc], pBl[2*kc], pAl[2*kc+1], pBl[2*kc+1]};
            #pragma unroll
            for (int dg = 0; dg < 4; dg++) {
                uint32_t so = SMEM_SWIZZLE_128B((uint32_t)(
                    ((kc<<4) + (lane & 7) + ((lane >> 3) & 1)*8)*128 +
                    ((dg<<4) + (lane >> 4)*8)*2));
                uint32_t vfh[4], vfl[4];
                ldsm_x4_t(vfh, st + 16384 + so);
                ldsm_x4_t(vfl, st + 24576 + so);
                mma_bf16(oacc[2*dg],   Ahh, vfh);
                mma_bf16(oacc[2*dg+1], Ahh, vfh + 2);
                mma_bf16(oacc[2*dg],   Ahh, vfl);
                mma_bf16(oacc[2*dg+1], Ahh, vfl + 2);
                mma_bf16(oacc[2*dg],   All, vfh);
                mma_bf16(oacc[2*dg+1], All, vfh + 2);
            }
        }

        __syncthreads();
        if (kt + 2 < ntiles) issue_kv(kt + 2, s);
    }

    // ---- epilogue: normalize, split hi/lo, write y [B,T,C] ----
    const float inv0 = 1.f / l_run[0];
    const float inv1 = 1.f / l_run[1];
    const int b_ = bh >> 4, h = bh & 15;
    const int t0 = q0 + qrow + gl, t1 = t0 + 8;
    #pragma unroll
    for (int f = 0; f < 8; f++) {
        const int col = h*DD + (f << 3) + (tl << 1);
        {
            float y0 = oacc[f][0] * inv0, y1 = oacc[f][1] * inv0;
            uint32_t hp = pack_bf16x2(y0, y1);
            float2 hf = bf16x2_to_f2(hp);
            uint32_t lp = pack_bf16x2(y0 - hf.x, y1 - hf.y);
            size_t off = (size_t)(b_*TT + t0) * CC + col;
            *(uint32_t*)(g_yhi + off) = hp;
            *(uint32_t*)(g_ylo + off) = lp;
        }
        {
            float y2 = oacc[f][2] * inv1, y3 = oacc[f][3] * inv1;
            uint32_t hp = pack_bf16x2(y2, y3);
            float2 hf = bf16x2_to_f2(hp);
            uint32_t lp = pack_bf16x2(y2 - hf.x, y3 - hf.y);
            size_t off = (size_t)(b_*TT + t1) * CC + col;
            *(uint32_t*)(g_yhi + off) = hp;
            *(uint32_t*)(g_ylo + off) = lp;
        }
    }
}

// ---------------------------------------------------------------------------

extern "C" void kernel_launch(void* const* d_in, const int* in_sizes, int n_in,
                              void* d_out, int out_size)
{
    const float* x  = (const float*)d_in[0];
    const float* Wq = (const float*)d_in[1];
    const float* bq = (const float*)d_in[2];
    const float* Wk = (const float*)d_in[3];
    const float* bk = (const float*)d_in[4];
    const float* Wv = (const float*)d_in[5];
    const float* bv = (const float*)d_in[6];
    const float* Wo = (const float*)d_in[7];
    const float* bo = (const float*)d_in[8];
    float* out = (float*)d_out;

    // 0) fp32 -> bf16 hi/lo splits (x4 vectorized) + bias concat
    prep_split<<<(8*1024*1024)/1024, 256>>>(Wq, Wk, Wv, Wo, x);
    prep_bias<<<12, 256>>>(bq, bk, bv);

    // 1) fused QKV projection -> bf16 hi/lo q/k/v (Q pre-scaled)
    cudaFuncSetAttribute(gemm_tc, cudaFuncAttributeMaxDynamicSharedMemorySize,
                         GEMM_SMEM);
    gemm_tc<<<dim3(3*CC/128, MM/128), 256, GEMM_SMEM>>>(0, nullptr, nullptr);

    // 2) tensor-core causal flash attention (64-row CTAs, 2/SM) -> y hi/lo
    cudaFuncSetAttribute(flash_tc, cudaFuncAttributeMaxDynamicSharedMemorySize,
                         F_SMEM);
    flash_tc<<<dim3(TT/64, BB*HH), F_THREADS, F_SMEM>>>();

    // 3) output projection -> d_out
    gemm_tc<<<dim3(CC/128, MM/128), 256, GEMM_SMEM>>>(1, bo, out);
}

// round 10
// speedup vs baseline: 2.5242x; 1.6292x over previous
#include <cuda_runtime.h>
#include <cuda_bf16.h>
#include <cuda_fp16.h>
#include <cstdint>
#include <math.h>

#define BB 2
#define TT 2048
#define CC 1024
#define HH 16
#define DD 64
#define MM (BB*TT)   // 4096 rows

// ---------------------------------------------------------------------------
// Scratch (__device__ globals; allocation-free rule)
// ---------------------------------------------------------------------------
__device__ __nv_bfloat16 g_qhi[BB*HH*TT*DD], g_qlo[BB*HH*TT*DD];  // [B,H,T,D]
__device__ __nv_bfloat16 g_khi[BB*HH*TT*DD], g_klo[BB*HH*TT*DD];
__device__ __nv_bfloat16 g_vhi[BB*HH*TT*DD], g_vlo[BB*HH*TT*DD];

__device__ __half g_xh[MM*CC];        // x fp16
__device__ __half g_wh[3*CC*CC];      // Wq|Wk|Wv concat fp16
__device__ __half g_woh[CC*CC];       // Wo fp16
__device__ __half g_yh[MM*CC];        // attention output fp16 [B,T,C]
__device__ float g_bqkv[3*CC];        // bq|bk|bv concat

// Q pre-scale: 1/sqrt(64) * log2(e)  (softmax done in base-2)
#define QSCALE (0.125f * 1.4426950408889634f)

// ---------------------------------------------------------------------------
// Helpers: ldmatrix / mma.sync / cp.async (baseline sm_80+)
// ---------------------------------------------------------------------------
__device__ __forceinline__ uint32_t smem_to_u32(const void* p) {
    uint32_t a;
    asm("{ .reg .u64 t; cvta.to.shared.u64 t, %1; cvt.u32.u64 %0, t; }"
        : "=r"(a) : "l"(p));
    return a;
}
__device__ __forceinline__ void ldsm_x4(uint32_t* r, uint32_t addr) {
    asm volatile("ldmatrix.sync.aligned.m8n8.x4.shared.b16 {%0,%1,%2,%3}, [%4];"
        : "=r"(r[0]), "=r"(r[1]), "=r"(r[2]), "=r"(r[3]) : "r"(addr));
}
__device__ __forceinline__ void ldsm_x4_t(uint32_t* r, uint32_t addr) {
    asm volatile("ldmatrix.sync.aligned.m8n8.x4.trans.shared.b16 {%0,%1,%2,%3}, [%4];"
        : "=r"(r[0]), "=r"(r[1]), "=r"(r[2]), "=r"(r[3]) : "r"(addr));
}
__device__ __forceinline__ void mma_bf16(float* d, const uint32_t* a,
                                         const uint32_t* b) {
    asm volatile(
        "mma.sync.aligned.m16n8k16.row.col.f32.bf16.bf16.f32 "
        "{%0,%1,%2,%3}, {%4,%5,%6,%7}, {%8,%9}, {%0,%1,%2,%3};"
        : "+f"(d[0]), "+f"(d[1]), "+f"(d[2]), "+f"(d[3])
        : "r"(a[0]), "r"(a[1]), "r"(a[2]), "r"(a[3]), "r"(b[0]), "r"(b[1]));
}
__device__ __forceinline__ void mma_fp16(float* d, const uint32_t* a,
                                         const uint32_t* b) {
    asm volatile(
        "mma.sync.aligned.m16n8k16.row.col.f32.f16.f16.f32 "
        "{%0,%1,%2,%3}, {%4,%5,%6,%7}, {%8,%9}, {%0,%1,%2,%3};"
        : "+f"(d[0]), "+f"(d[1]), "+f"(d[2]), "+f"(d[3])
        : "r"(a[0]), "r"(a[1]), "r"(a[2]), "r"(a[3]), "r"(b[0]), "r"(b[1]));
}
__device__ __forceinline__ void cp16(uint32_t saddr, const void* g) {
    asm volatile("cp.async.cg.shared.global [%0], [%1], 16;"
        :: "r"(saddr), "l"(g) : "memory");
}
#define CP_COMMIT()  asm volatile("cp.async.commit_group;" ::: "memory")
#define CP_WAIT1()   asm volatile("cp.async.wait_group 1;" ::: "memory")
#define CP_WAIT0()   asm volatile("cp.async.wait_group 0;" ::: "memory")

#define SMEM_SWIZZLE_128B(byte_offset) \
    ((byte_offset) ^ (((byte_offset) >> 3) & 0x70))

__device__ __forceinline__ float exp2a(float x) {
    float y; asm("ex2.approx.f32 %0, %1;" : "=f"(y) : "f"(x)); return y;
}
__device__ __forceinline__ uint32_t pack_bf16x2(float lo, float hi) {
    uint32_t r;
    asm("cvt.rn.bf16x2.f32 %0, %1, %2;" : "=r"(r) : "f"(hi), "f"(lo));
    return r;
}
__device__ __forceinline__ float2 bf16x2_to_f2(uint32_t u) {
    __nv_bfloat162 h = *reinterpret_cast<__nv_bfloat162*>(&u);
    return __bfloat1622float2(h);
}

// ---------------------------------------------------------------------------
// Prep: fp32 -> fp16 (vectorized x4), bias concat.
// ---------------------------------------------------------------------------
__global__ __launch_bounds__(256) void prep_split(
    const float* __restrict__ Wq, const float* __restrict__ Wk,
    const float* __restrict__ Wv, const float* __restrict__ Wo,
    const float* __restrict__ x)
{
    const int i = (blockIdx.x * 256 + threadIdx.x) * 4;   // 0 .. 8M-1, step 4
    const int WQKV = 3*CC*CC, WO = CC*CC;
    const float* src;
    __half* dst;
    int j;
    if (i < WQKV) {
        src = (i < CC*CC) ? Wq : (i < 2*CC*CC) ? Wk : Wv;
        src += (i & (CC*CC - 1));
        dst = g_wh; j = i;
    } else if (i < WQKV + WO) {
        j = i - WQKV;
        src = Wo + j;
        dst = g_woh;
    } else {
        j = i - WQKV - WO;      // 0 .. 4M-1
        src = x + j;
        dst = g_xh;
    }
    float4 v = *(const float4*)src;
    __half2 h0 = __floats2half2_rn(v.x, v.y);
    __half2 h1 = __floats2half2_rn(v.z, v.w);
    uint2 o;
    o.x = *reinterpret_cast<uint32_t*>(&h0);
    o.y = *reinterpret_cast<uint32_t*>(&h1);
    *(uint2*)(dst + j) = o;
}

__global__ void prep_bias(const float* __restrict__ bq,
                          const float* __restrict__ bk,
                          const float* __restrict__ bv)
{
    int i = blockIdx.x * 256 + threadIdx.x;
    if (i < 3*CC)
        g_bqkv[i] = (i < CC) ? bq[i] : (i < 2*CC) ? bk[i-CC] : bv[i-2*CC];
}

// ---------------------------------------------------------------------------
// mma.sync GEMM (fp16 single-term): 128x128 tile of A[M,1024] @ B[N,1024]^T.
// 8 warps 4(M)x2(N), warp tile 32x64, 2-stage cp.async, 32 KB/stage ->
// 66 KB smem total -> 2+ CTAs/SM for inter-CTA latency hiding.
// mode 0: A=x, B=WqWkWv, scatter bf16 hi/lo q/k/v (+bias, Q scaled).
// mode 1: A=y(fp16), B=Wo, write d_out fp32 (+bo).
// ---------------------------------------------------------------------------
#define CHUNK_K   64
#define NCHUNK    (CC / CHUNK_K)      // 16
#define BUF_BYTES (128*64*2)          // 16 KB per operand buffer
#define STAGE_BYTES (2*BUF_BYTES)     // 32 KB
#define OFF_A 0
#define OFF_B BUF_BYTES
#define GEMM_SMEM (2*STAGE_BYTES + 1024)   // 66560 B

__global__ __launch_bounds__(256, 2) void gemm_tc(
    int mode, const float* __restrict__ bias1, float* __restrict__ outf)
{
    extern __shared__ char smem[];
    const uint32_t smem_u32 = smem_to_u32(smem);
    const uint32_t tile_u32 = (smem_u32 + 1023) & ~1023u;

    const int tid  = threadIdx.x;
    const int wid  = tid >> 5;
    const int lane = tid & 31;
    const int wm   = wid >> 1;          // 0..3 (M)
    const int wn   = wid & 1;           // 0..1 (N)
    const int m0   = blockIdx.y << 7;
    const int n0   = blockIdx.x << 7;

    const __half *A, *B;
    if (mode == 0) { A = g_xh; B = g_wh;  }
    else           { A = g_yh; B = g_woh; }

    auto issue_chunk = [&](int c, int s) {
        const int kc = c * CHUNK_K;
        const uint32_t st = tile_u32 + s * STAGE_BYTES;
        #pragma unroll
        for (int i = 0; i < 4; i++) {
            int idx = tid + i*256;           // 0..1023
            int r   = idx >> 3;              // tile row 0..127
            int g   = idx & 7;               // 16B group in row
            uint32_t so = SMEM_SWIZZLE_128B((uint32_t)(r*128 + g*16));
            size_t aoff = (size_t)(m0 + r) * CC + kc + g*8;
            size_t boff = (size_t)(n0 + r) * CC + kc + g*8;
            cp16(st + OFF_A + so, A + aoff);
            cp16(st + OFF_B + so, B + boff);
        }
        CP_COMMIT();
    };

    float acc[2][8][4];
    #pragma unroll
    for (int mt = 0; mt < 2; mt++)
        #pragma unroll
        for (int nt = 0; nt < 8; nt++)
            #pragma unroll
            for (int e = 0; e < 4; e++) acc[mt][nt][e] = 0.f;

    issue_chunk(0, 0);
    issue_chunk(1, 1);

    for (int c = 0; c < NCHUNK; ++c) {
        const int s = c & 1;
        if (c + 1 < NCHUNK) { CP_WAIT1(); } else { CP_WAIT0(); }
        __syncthreads();

        const uint32_t sA = tile_u32 + s*STAGE_BYTES + OFF_A;
        const uint32_t sB = tile_u32 + s*STAGE_BYTES + OFF_B;

        #pragma unroll
        for (int ks = 0; ks < 4; ++ks) {
            uint32_t af[2][4];
            #pragma unroll
            for (int mt = 0; mt < 2; ++mt) {
                int r = wm*32 + mt*16 + (lane & 15);
                int g = ks*2 + (lane >> 4);
                uint32_t off = SMEM_SWIZZLE_128B((uint32_t)(r*128 + g*16));
                ldsm_x4(af[mt], sA + off);
            }
            #pragma unroll
            for (int np = 0; np < 4; ++np) {
                int n = wn*64 + np*16 + ((lane >> 4) << 3) + (lane & 7);
                int g = ks*2 + ((lane >> 3) & 1);
                uint32_t off = SMEM_SWIZZLE_128B((uint32_t)(n*128 + g*16));
                uint32_t bf[4];
                ldsm_x4(bf, sB + off);
                #pragma unroll
                for (int mt = 0; mt < 2; ++mt) {
                    mma_fp16(acc[mt][2*np],   af[mt], bf);
                    mma_fp16(acc[mt][2*np+1], af[mt], bf + 2);
                }
            }
        }

        if (c + 2 < NCHUNK) {
            __syncthreads();
            issue_chunk(c + 2, s);
        }
    }

    // --- epilogue ---
    const int gl = lane >> 2;          // 0..7
    const int tl = lane & 3;           // 0..3
    #pragma unroll
    for (int mt = 0; mt < 2; ++mt) {
        #pragma unroll
        for (int nt = 0; nt < 8; ++nt) {
            const int row0 = m0 + wm*32 + mt*16 + gl;
            const int colg = n0 + wn*64 + nt*8 + 2*tl;
            if (mode == 0) {
                const int head = colg >> 6;        // 0..47
                const int proj = head >> 4;        // 0=q 1=k 2=v
                const int h    = head & 15;
                const int d0c  = colg & 63;
                __nv_bfloat16 *hiP, *loP;
                if (proj == 0)      { hiP = g_qhi; loP = g_qlo; }
                else if (proj == 1) { hiP = g_khi; loP = g_klo; }
                else                { hiP = g_vhi; loP = g_vlo; }
                const float2 bia = *(const float2*)&g_bqkv[colg];
                #pragma unroll
                for (int rr = 0; rr < 2; ++rr) {
                    const int m = row0 + rr*8;
                    const int b_ = m >> 11, t = m & 2047;
                    float v0 = acc[mt][nt][2*rr+0] + bia.x;
                    float v1 = acc[mt][nt][2*rr+1] + bia.y;
                    if (proj == 0) { v0 *= QSCALE; v1 *= QSCALE; }
                    uint32_t hp = pack_bf16x2(v0, v1);
                    float2 hf = bf16x2_to_f2(hp);
                    uint32_t lp = pack_bf16x2(v0 - hf.x, v1 - hf.y);
                    size_t off = ((size_t)(b_*HH + h) * TT + t) * DD + d0c;
                    *(uint32_t*)(hiP + off) = hp;
                    *(uint32_t*)(loP + off) = lp;
                }
            } else {
                const float2 bia = *(const float2*)&bias1[colg];
                #pragma unroll
                for (int rr = 0; rr < 2; ++rr) {
                    const int m = row0 + rr*8;
                    float2 o;
                    o.x = acc[mt][nt][2*rr+0] + bia.x;
                    o.y = acc[mt][nt][2*rr+1] + bia.y;
                    *(float2*)(outf + (size_t)m * CC + colg) = o;
                }
            }
        }
    }
}

// ---------------------------------------------------------------------------
// Tensor-core flash attention: 64-query x 64-key tiles, bf16 hi/lo 3-term
// (mainloop unchanged from R9). Epilogue now writes y as fp16 single.
// ---------------------------------------------------------------------------
#define F_THREADS 128
#define F_SMEM (16384 + 65536)   // Q(hi+lo) 16KB + 2 stages x (K/V hi/lo) 32KB

__global__ __launch_bounds__(F_THREADS, 2) void flash_tc()
{
    extern __shared__ char fsm[];
    const uint32_t sb  = smem_to_u32(fsm);
    const uint32_t sQh = sb, sQl = sb + 8192;

    const int tid = threadIdx.x, wid = tid >> 5, lane = tid & 31;
    const int gl = lane >> 2, tl = lane & 3;
    const int jq = (int)gridDim.x - 1 - (int)blockIdx.x;   // heavy tiles first
    const int q0 = jq << 6;                                 // 64-row q tiles
    const int bh = blockIdx.y;
    const size_t hb = (size_t)bh * TT * DD;
    const __nv_bfloat16 *qhp = g_qhi + hb + (size_t)q0 * DD;
    const __nv_bfloat16 *qlp = g_qlo + hb + (size_t)q0 * DD;
    const __nv_bfloat16 *khp = g_khi + hb, *klp = g_klo + hb;
    const __nv_bfloat16 *vhp = g_vhi + hb, *vlp = g_vlo + hb;
    const int ntiles = jq + 1;

    // --- Q tile (hi+lo): 64 rows x 8 chunks x 2 buffers = 1024 chunks ---
    #pragma unroll
    for (int i = 0; i < 8; i++) {
        int idx = tid + i*F_THREADS;        // 0..1023
        int buf = idx >> 9;                 // 0 hi, 1 lo
        int rc = idx & 511; int r = rc >> 3, c = rc & 7;
        uint32_t so = SMEM_SWIZZLE_128B((uint32_t)(r*128 + c*16));
        cp16((buf ? sQl : sQh) + so, (buf ? qlp : qhp) + (size_t)r*DD + c*8);
    }
    CP_COMMIT();

    auto issue_kv = [&](int kt, int s) {
        const uint32_t st = sb + 16384 + s*32768;
        const int r0 = kt << 6;
        #pragma unroll
        for (int i = 0; i < 16; i++) {
            int idx = tid + i*F_THREADS;    // 0..2047
            int buf = idx >> 9;             // 0 khi,1 klo,2 vhi,3 vlo
            int rc = idx & 511; int r = rc >> 3, c = rc & 7;
            uint32_t so = SMEM_SWIZZLE_128B((uint32_t)(r*128 + c*16));
            const __nv_bfloat16* src =
                (buf == 0 ? khp : buf == 1 ? klp : buf == 2 ? vhp : vlp)
                + (size_t)(r0 + r) * DD + c*8;
            cp16(st + buf*8192 + so, src);
        }
        CP_COMMIT();
    };
    issue_kv(0, 0);
    issue_kv(1, 1);       // kt=1 prefetch (reads valid memory even if unused)

    CP_WAIT1();           // Q + stage0 complete
    __syncthreads();

    // --- Q fragments (persistent) ---
    const int qrow = wid << 4;               // 0..48
    uint32_t qfh[4][4], qfl[4][4];
    #pragma unroll
    for (int dc = 0; dc < 4; dc++) {
        uint32_t so = SMEM_SWIZZLE_128B((uint32_t)(
            (qrow + (lane & 15))*128 + (dc*16 + ((lane >> 4) << 3))*2));
        ldsm_x4(qfh[dc], sQh + so);
        ldsm_x4(qfl[dc], sQl + so);
    }

    float m_run[2] = {-1e30f, -1e30f};
    float l_run[2] = {0.f, 0.f};
    float oacc[8][4];
    #pragma unroll
    for (int f = 0; f < 8; f++)
        #pragma unroll
        for (int e = 0; e < 4; e++) oacc[f][e] = 0.f;

    for (int kt = 0; kt < ntiles; kt++) {
        const int s = kt & 1;
        if (kt + 1 < ntiles) { CP_WAIT1(); } else { CP_WAIT0(); }
        __syncthreads();

        const uint32_t st = sb + 16384 + s*32768;

        // ---- S = Q @ K^T (3-term) ----
        float sacc[8][4] = {};
        #pragma unroll
        for (int dc = 0; dc < 4; dc++) {
            #pragma unroll
            for (int ng = 0; ng < 4; ng++) {
                uint32_t so = SMEM_SWIZZLE_128B((uint32_t)(
                    ((ng<<4) + (lane & 7) + ((lane >> 4) << 3))*128 +
                    ((dc<<4) + ((lane >> 3) & 1)*8)*2));
                uint32_t kfh[4], kfl[4];
                ldsm_x4(kfh, st + so);
                ldsm_x4(kfl, st + 8192 + so);
                mma_bf16(sacc[2*ng],   qfh[dc], kfh);
                mma_bf16(sacc[2*ng+1], qfh[dc], kfh + 2);
                mma_bf16(sacc[2*ng],   qfh[dc], kfl);
                mma_bf16(sacc[2*ng+1], qfh[dc], kfl + 2);
                mma_bf16(sacc[2*ng],   qfl[dc], kfh);
                mma_bf16(sacc[2*ng+1], qfl[dc], kfh + 2);
            }
        }

        // ---- causal mask (diagonal = last tile) ----
        if (kt == jq) {
            const int r0g = q0 + qrow + gl;
            #pragma unroll
            for (int f = 0; f < 8; f++) {
                const int kc0 = (kt << 6) + (f << 3) + (tl << 1);
                if (kc0     > r0g)     sacc[f][0] = -1e30f;
                if (kc0 + 1 > r0g)     sacc[f][1] = -1e30f;
                if (kc0     > r0g + 8) sacc[f][2] = -1e30f;
                if (kc0 + 1 > r0g + 8) sacc[f][3] = -1e30f;
            }
        }

        // ---- online softmax (base 2) ----
        float mx0 = m_run[0], mx1 = m_run[1];
        #pragma unroll
        for (int f = 0; f < 8; f++) {
            mx0 = fmaxf(mx0, fmaxf(sacc[f][0], sacc[f][1]));
            mx1 = fmaxf(mx1, fmaxf(sacc[f][2], sacc[f][3]));
        }
        mx0 = fmaxf(mx0, __shfl_xor_sync(0xffffffffu, mx0, 1));
        mx0 = fmaxf(mx0, __shfl_xor_sync(0xffffffffu, mx0, 2));
        mx1 = fmaxf(mx1, __shfl_xor_sync(0xffffffffu, mx1, 1));
        mx1 = fmaxf(mx1, __shfl_xor_sync(0xffffffffu, mx1, 2));
        const float a0 = exp2a(m_run[0] - mx0);
        const float a1 = exp2a(m_run[1] - mx1);
        m_run[0] = mx0; m_run[1] = mx1;

        float sum0 = 0.f, sum1 = 0.f;
        uint32_t pAh[8], pBh[8], pAl[8], pBl[8];
        #pragma unroll
        for (int f = 0; f < 8; f++) {
            float p0 = exp2a(sacc[f][0] - mx0);
            float p1 = exp2a(sacc[f][1] - mx0);
            float p2 = exp2a(sacc[f][2] - mx1);
            float p3 = exp2a(sacc[f][3] - mx1);
            sum0 += p0 + p1; sum1 += p2 + p3;
            uint32_t h01 = pack_bf16x2(p0, p1);
            uint32_t h23 = pack_bf16x2(p2, p3);
            float2 f01 = bf16x2_to_f2(h01);
            float2 f23 = bf16x2_to_f2(h23);
            pAh[f] = h01; pBh[f] = h23;
            pAl[f] = pack_bf16x2(p0 - f01.x, p1 - f01.y);
            pBl[f] = pack_bf16x2(p2 - f23.x, p3 - f23.y);
        }
        sum0 += __shfl_xor_sync(0xffffffffu, sum0, 1);
        sum0 += __shfl_xor_sync(0xffffffffu, sum0, 2);
        sum1 += __shfl_xor_sync(0xffffffffu, sum1, 1);
        sum1 += __shfl_xor_sync(0xffffffffu, sum1, 2);
        l_run[0] = l_run[0]*a0 + sum0;
        l_run[1] = l_run[1]*a1 + sum1;
        #pragma unroll
        for (int f = 0; f < 8; f++) {
            oacc[f][0] *= a0; oacc[f][1] *= a0;
            oacc[f][2] *= a1; oacc[f][3] *= a1;
        }

        // ---- O += P @ V (3-term; V via ldmatrix.trans) ----
        #pragma unroll
        for (int kc = 0; kc < 4; kc++) {
            uint32_t Ahh[4] = {pAh[2*kc], pBh[2*kc], pAh[2*kc+1], pBh[2*kc+1]};
            uint32_t All[4] = {pAl[2*kc], pBl[2*kc], pAl[2*kc+1], pBl[2*kc+1]};
            #pragma unroll
            for (int dg = 0; dg < 4; dg++) {
                uint32_t so = SMEM_SWIZZLE_128B((uint32_t)(
                    ((kc<<4) + (lane & 7) + ((lane >> 3) & 1)*8)*128 +
                    ((dg<<4) + (lane >> 4)*8)*2));
                uint32_t vfh[4], vfl[4];
                ldsm_x4_t(vfh, st + 16384 + so);
                ldsm_x4_t(vfl, st + 24576 + so);
                mma_bf16(oacc[2*dg],   Ahh, vfh);
                mma_bf16(oacc[2*dg+1], Ahh, vfh + 2);
                mma_bf16(oacc[2*dg],   Ahh, vfl);
                mma_bf16(oacc[2*dg+1], Ahh, vfl + 2);
                mma_bf16(oacc[2*dg],   All, vfh);
                mma_bf16(oacc[2*dg+1], All, vfh + 2);
            }
        }

        __syncthreads();
        if (kt + 2 < ntiles) issue_kv(kt + 2, s);
    }

    // ---- epilogue: normalize, write y as fp16 [B,T,C] ----
    const float inv0 = 1.f / l_run[0];
    const float inv1 = 1.f / l_run[1];
    const int b_ = bh >> 4, h = bh & 15;
    const int t0 = q0 + qrow + gl, t1 = t0 + 8;
    #pragma unroll
    for (int f = 0; f < 8; f++) {
        const int col = h*DD + (f << 3) + (tl << 1);
        {
            __half2 hp = __floats2half2_rn(oacc[f][0] * inv0, oacc[f][1] * inv0);
            *(uint32_t*)(g_yh + (size_t)(b_*TT + t0) * CC + col) =
                *reinterpret_cast<uint32_t*>(&hp);
        }
        {
            __half2 hp = __floats2half2_rn(oacc[f][2] * inv1, oacc[f][3] * inv1);
            *(uint32_t*)(g_yh + (size_t)(b_*TT + t1) * CC + col) =
                *reinterpret_cast<uint32_t*>(&hp);
        }
    }
}

// ---------------------------------------------------------------------------

extern "C" void kernel_launch(void* const* d_in, const int* in_sizes, int n_in,
                              void* d_out, int out_size)
{
    const float* x  = (const float*)d_in[0];
    const float* Wq = (const float*)d_in[1];
    const float* bq = (const float*)d_in[2];
    const float* Wk = (const float*)d_in[3];
    const float* bk = (const float*)d_in[4];
    const float* Wv = (const float*)d_in[5];
    const float* bv = (const float*)d_in[6];
    const float* Wo = (const float*)d_in[7];
    const float* bo = (const float*)d_in[8];
    float* out = (float*)d_out;

    // 0) fp32 -> fp16 conversions (x4 vectorized) + bias concat
    prep_split<<<(8*1024*1024)/1024, 256>>>(Wq, Wk, Wv, Wo, x);
    prep_bias<<<12, 256>>>(bq, bk, bv);

    // 1) fused QKV projection (fp16 single-term) -> bf16 hi/lo q/k/v
    cudaFuncSetAttribute(gemm_tc, cudaFuncAttributeMaxDynamicSharedMemorySize,
                         GEMM_SMEM);
    gemm_tc<<<dim3(3*CC/128, MM/128), 256, GEMM_SMEM>>>(0, nullptr, nullptr);

    // 2) tensor-core causal flash attention (bf16 3-term) -> y fp16
    cudaFuncSetAttribute(flash_tc, cudaFuncAttributeMaxDynamicSharedMemorySize,
                         F_SMEM);
    flash_tc<<<dim3(TT/64, BB*HH), F_THREADS, F_SMEM>>>();

    // 3) output projection (fp16 single-term) -> d_out
    gemm_tc<<<dim3(CC/128, MM/128), 256, GEMM_SMEM>>>(1, bo, out);
}

// round 11
// speedup vs baseline: 3.7429x; 1.4828x over previous
#include <cuda_runtime.h>
#include <cuda_bf16.h>
#include <cuda_fp16.h>
#include <cstdint>
#include <math.h>

#define BB 2
#define TT 2048
#define CC 1024
#define HH 16
#define DD 64
#define MM (BB*TT)   // 4096 rows

// ---------------------------------------------------------------------------
// Scratch (__device__ globals; allocation-free rule)
// ---------------------------------------------------------------------------
__device__ __half g_q[BB*HH*TT*DD];   // fp16 [B,H,T,D], Q pre-scaled
__device__ __half g_k[BB*HH*TT*DD];
__device__ __half g_v[BB*HH*TT*DD];

__device__ __half g_xh[MM*CC];        // x fp16
__device__ __half g_wh[3*CC*CC];      // Wq|Wk|Wv concat fp16
__device__ __half g_woh[CC*CC];       // Wo fp16
__device__ __half g_yh[MM*CC];        // attention output fp16 [B,T,C]
__device__ float g_bqkv[3*CC];        // bq|bk|bv concat

// Q pre-scale: 1/sqrt(64) * log2(e)  (softmax done in base-2)
#define QSCALE (0.125f * 1.4426950408889634f)

// ---------------------------------------------------------------------------
// Helpers: ldmatrix / mma.sync / cp.async (baseline sm_80+)
// ---------------------------------------------------------------------------
__device__ __forceinline__ uint32_t smem_to_u32(const void* p) {
    uint32_t a;
    asm("{ .reg .u64 t; cvta.to.shared.u64 t, %1; cvt.u32.u64 %0, t; }"
        : "=r"(a) : "l"(p));
    return a;
}
__device__ __forceinline__ void ldsm_x4(uint32_t* r, uint32_t addr) {
    asm volatile("ldmatrix.sync.aligned.m8n8.x4.shared.b16 {%0,%1,%2,%3}, [%4];"
        : "=r"(r[0]), "=r"(r[1]), "=r"(r[2]), "=r"(r[3]) : "r"(addr));
}
__device__ __forceinline__ void ldsm_x4_t(uint32_t* r, uint32_t addr) {
    asm volatile("ldmatrix.sync.aligned.m8n8.x4.trans.shared.b16 {%0,%1,%2,%3}, [%4];"
        : "=r"(r[0]), "=r"(r[1]), "=r"(r[2]), "=r"(r[3]) : "r"(addr));
}
__device__ __forceinline__ void mma_fp16(float* d, const uint32_t* a,
                                         const uint32_t* b) {
    asm volatile(
        "mma.sync.aligned.m16n8k16.row.col.f32.f16.f16.f32 "
        "{%0,%1,%2,%3}, {%4,%5,%6,%7}, {%8,%9}, {%0,%1,%2,%3};"
        : "+f"(d[0]), "+f"(d[1]), "+f"(d[2]), "+f"(d[3])
        : "r"(a[0]), "r"(a[1]), "r"(a[2]), "r"(a[3]), "r"(b[0]), "r"(b[1]));
}
__device__ __forceinline__ void cp16(uint32_t saddr, const void* g) {
    asm volatile("cp.async.cg.shared.global [%0], [%1], 16;"
        :: "r"(saddr), "l"(g) : "memory");
}
#define CP_COMMIT()  asm volatile("cp.async.commit_group;" ::: "memory")
#define CP_WAIT1()   asm volatile("cp.async.wait_group 1;" ::: "memory")
#define CP_WAIT0()   asm volatile("cp.async.wait_group 0;" ::: "memory")

#define SMEM_SWIZZLE_128B(byte_offset) \
    ((byte_offset) ^ (((byte_offset) >> 3) & 0x70))

__device__ __forceinline__ float exp2a(float x) {
    float y; asm("ex2.approx.f32 %0, %1;" : "=f"(y) : "f"(x)); return y;
}
__device__ __forceinline__ uint32_t pack_h2(float a, float b) {
    __half2 h = __floats2half2_rn(a, b);
    return *reinterpret_cast<uint32_t*>(&h);
}

// ---------------------------------------------------------------------------
// Prep: fp32 -> fp16 (vectorized x4), bias concat.
// ---------------------------------------------------------------------------
__global__ __launch_bounds__(256) void prep_split(
    const float* __restrict__ Wq, const float* __restrict__ Wk,
    const float* __restrict__ Wv, const float* __restrict__ Wo,
    const float* __restrict__ x)
{
    const int i = (blockIdx.x * 256 + threadIdx.x) * 4;   // 0 .. 8M-1, step 4
    const int WQKV = 3*CC*CC, WO = CC*CC;
    const float* src;
    __half* dst;
    int j;
    if (i < WQKV) {
        src = (i < CC*CC) ? Wq : (i < 2*CC*CC) ? Wk : Wv;
        src += (i & (CC*CC - 1));
        dst = g_wh; j = i;
    } else if (i < WQKV + WO) {
        j = i - WQKV;
        src = Wo + j;
        dst = g_woh;
    } else {
        j = i - WQKV - WO;      // 0 .. 4M-1
        src = x + j;
        dst = g_xh;
    }
    float4 v = *(const float4*)src;
    uint2 o;
    o.x = pack_h2(v.x, v.y);
    o.y = pack_h2(v.z, v.w);
    *(uint2*)(dst + j) = o;
}

__global__ void prep_bias(const float* __restrict__ bq,
                          const float* __restrict__ bk,
                          const float* __restrict__ bv)
{
    int i = blockIdx.x * 256 + threadIdx.x;
    if (i < 3*CC)
        g_bqkv[i] = (i < CC) ? bq[i] : (i < 2*CC) ? bk[i-CC] : bv[i-2*CC];
}

// ---------------------------------------------------------------------------
// mma.sync GEMM (fp16 single-term): 128x128 tile of A[M,1024] @ B[N,1024]^T.
// mode 0: A=x, B=WqWkWv, scatter fp16 q/k/v (+bias, Q scaled).
// mode 1: A=y(fp16), B=Wo, write d_out fp32 (+bo).
// ---------------------------------------------------------------------------
#define CHUNK_K   64
#define NCHUNK    (CC / CHUNK_K)      // 16
#define BUF_BYTES (128*64*2)          // 16 KB per operand buffer
#define STAGE_BYTES (2*BUF_BYTES)     // 32 KB
#define OFF_A 0
#define OFF_B BUF_BYTES
#define GEMM_SMEM (2*STAGE_BYTES + 1024)   // 66560 B

__global__ __launch_bounds__(256, 2) void gemm_tc(
    int mode, const float* __restrict__ bias1, float* __restrict__ outf)
{
    extern __shared__ char smem[];
    const uint32_t smem_u32 = smem_to_u32(smem);
    const uint32_t tile_u32 = (smem_u32 + 1023) & ~1023u;

    const int tid  = threadIdx.x;
    const int wid  = tid >> 5;
    const int lane = tid & 31;
    const int wm   = wid >> 1;          // 0..3 (M)
    const int wn   = wid & 1;           // 0..1 (N)
    const int m0   = blockIdx.y << 7;
    const int n0   = blockIdx.x << 7;

    const __half *A, *B;
    if (mode == 0) { A = g_xh; B = g_wh;  }
    else           { A = g_yh; B = g_woh; }

    auto issue_chunk = [&](int c, int s) {
        const int kc = c * CHUNK_K;
        const uint32_t st = tile_u32 + s * STAGE_BYTES;
        #pragma unroll
        for (int i = 0; i < 4; i++) {
            int idx = tid + i*256;           // 0..1023
            int r   = idx >> 3;              // tile row 0..127
            int g   = idx & 7;               // 16B group in row
            uint32_t so = SMEM_SWIZZLE_128B((uint32_t)(r*128 + g*16));
            size_t aoff = (size_t)(m0 + r) * CC + kc + g*8;
            size_t boff = (size_t)(n0 + r) * CC + kc + g*8;
            cp16(st + OFF_A + so, A + aoff);
            cp16(st + OFF_B + so, B + boff);
        }
        CP_COMMIT();
    };

    float acc[2][8][4];
    #pragma unroll
    for (int mt = 0; mt < 2; mt++)
        #pragma unroll
        for (int nt = 0; nt < 8; nt++)
            #pragma unroll
            for (int e = 0; e < 4; e++) acc[mt][nt][e] = 0.f;

    issue_chunk(0, 0);
    issue_chunk(1, 1);

    for (int c = 0; c < NCHUNK; ++c) {
        const int s = c & 1;
        if (c + 1 < NCHUNK) { CP_WAIT1(); } else { CP_WAIT0(); }
        __syncthreads();

        const uint32_t sA = tile_u32 + s*STAGE_BYTES + OFF_A;
        const uint32_t sB = tile_u32 + s*STAGE_BYTES + OFF_B;

        #pragma unroll
        for (int ks = 0; ks < 4; ++ks) {
            uint32_t af[2][4];
            #pragma unroll
            for (int mt = 0; mt < 2; ++mt) {
                int r = wm*32 + mt*16 + (lane & 15);
                int g = ks*2 + (lane >> 4);
                uint32_t off = SMEM_SWIZZLE_128B((uint32_t)(r*128 + g*16));
                ldsm_x4(af[mt], sA + off);
            }
            #pragma unroll
            for (int np = 0; np < 4; ++np) {
                int n = wn*64 + np*16 + ((lane >> 4) << 3) + (lane & 7);
                int g = ks*2 + ((lane >> 3) & 1);
                uint32_t off = SMEM_SWIZZLE_128B((uint32_t)(n*128 + g*16));
                uint32_t bf[4];
                ldsm_x4(bf, sB + off);
                #pragma unroll
                for (int mt = 0; mt < 2; ++mt) {
                    mma_fp16(acc[mt][2*np],   af[mt], bf);
                    mma_fp16(acc[mt][2*np+1], af[mt], bf + 2);
                }
            }
        }

        if (c + 2 < NCHUNK) {
            __syncthreads();
            issue_chunk(c + 2, s);
        }
    }

    // --- epilogue ---
    const int gl = lane >> 2;          // 0..7
    const int tl = lane & 3;           // 0..3
    #pragma unroll
    for (int mt = 0; mt < 2; ++mt) {
        #pragma unroll
        for (int nt = 0; nt < 8; ++nt) {
            const int row0 = m0 + wm*32 + mt*16 + gl;
            const int colg = n0 + wn*64 + nt*8 + 2*tl;
            if (mode == 0) {
                const int head = colg >> 6;        // 0..47
                const int proj = head >> 4;        // 0=q 1=k 2=v
                const int h    = head & 15;
                const int d0c  = colg & 63;
                __half* dstp = (proj == 0) ? g_q : (proj == 1) ? g_k : g_v;
                const float2 bia = *(const float2*)&g_bqkv[colg];
                #pragma unroll
                for (int rr = 0; rr < 2; ++rr) {
                    const int m = row0 + rr*8;
                    const int b_ = m >> 11, t = m & 2047;
                    float v0 = acc[mt][nt][2*rr+0] + bia.x;
                    float v1 = acc[mt][nt][2*rr+1] + bia.y;
                    if (proj == 0) { v0 *= QSCALE; v1 *= QSCALE; }
                    size_t off = ((size_t)(b_*HH + h) * TT + t) * DD + d0c;
                    *(uint32_t*)(dstp + off) = pack_h2(v0, v1);
                }
            } else {
                const float2 bia = *(const float2*)&bias1[colg];
                #pragma unroll
                for (int rr = 0; rr < 2; ++rr) {
                    const int m = row0 + rr*8;
                    float2 o;
                    o.x = acc[mt][nt][2*rr+0] + bia.x;
                    o.y = acc[mt][nt][2*rr+1] + bia.y;
                    *(float2*)(outf + (size_t)m * CC + colg) = o;
                }
            }
        }
    }
}

// ---------------------------------------------------------------------------
// Tensor-core flash attention, full fp16 single-term.
// 64-query x 64-key tiles, 4 warps / 128 thr, 3 CTAs/SM target
// (smem 40 KB, regs capped by launch_bounds(128,3)).
// ---------------------------------------------------------------------------
#define F_THREADS 128
#define F_STAGE 16384                 // K(8KB) + V(8KB) per stage
#define F_SMEM (8192 + 2*F_STAGE)     // Q 8KB + 2 stages = 40960 B

__global__ __launch_bounds__(F_THREADS, 3) void flash_tc()
{
    extern __shared__ char fsm[];
    const uint32_t sb = smem_to_u32(fsm);
    const uint32_t sQ = sb;

    const int tid = threadIdx.x, wid = tid >> 5, lane = tid & 31;
    const int gl = lane >> 2, tl = lane & 3;
    const int jq = (int)gridDim.x - 1 - (int)blockIdx.x;   // heavy tiles first
    const int q0 = jq << 6;                                 // 64-row q tiles
    const int bh = blockIdx.y;
    const size_t hb = (size_t)bh * TT * DD;
    const __half *qp = g_q + hb + (size_t)q0 * DD;
    const __half *kp = g_k + hb, *vp = g_v + hb;
    const int ntiles = jq + 1;

    // --- Q tile: 64 rows x 8 chunks = 512 chunks (4 iters x 128 thr) ---
    #pragma unroll
    for (int i = 0; i < 4; i++) {
        int idx = tid + i*F_THREADS;        // 0..511
        int r = idx >> 3, c = idx & 7;
        uint32_t so = SMEM_SWIZZLE_128B((uint32_t)(r*128 + c*16));
        cp16(sQ + so, qp + (size_t)r*DD + c*8);
    }
    CP_COMMIT();

    auto issue_kv = [&](int kt, int s) {
        const uint32_t st = sb + 8192 + s*F_STAGE;
        const int r0 = kt << 6;
        #pragma unroll
        for (int i = 0; i < 8; i++) {
            int idx = tid + i*F_THREADS;    // 0..1023
            int buf = idx >> 9;             // 0 K, 1 V
            int rc = idx & 511; int r = rc >> 3, c = rc & 7;
            uint32_t so = SMEM_SWIZZLE_128B((uint32_t)(r*128 + c*16));
            const __half* src = (buf ? vp : kp) + (size_t)(r0 + r) * DD + c*8;
            cp16(st + buf*8192 + so, src);
        }
        CP_COMMIT();
    };
    issue_kv(0, 0);
    issue_kv(1, 1);       // prefetch (valid memory even if unused)

    CP_WAIT1();           // Q + stage0 complete
    __syncthreads();

    // --- Q fragments (persistent) ---
    const int qrow = wid << 4;               // 0..48
    uint32_t qf[4][4];
    #pragma unroll
    for (int dc = 0; dc < 4; dc++) {
        uint32_t so = SMEM_SWIZZLE_128B((uint32_t)(
            (qrow + (lane & 15))*128 + (dc*16 + ((lane >> 4) << 3))*2));
        ldsm_x4(qf[dc], sQ + so);
    }

    float m_run[2] = {-1e30f, -1e30f};
    float l_run[2] = {0.f, 0.f};
    float oacc[8][4];
    #pragma unroll
    for (int f = 0; f < 8; f++)
        #pragma unroll
        for (int e = 0; e < 4; e++) oacc[f][e] = 0.f;

    for (int kt = 0; kt < ntiles; kt++) {
        const int s = kt & 1;
        if (kt + 1 < ntiles) { CP_WAIT1(); } else { CP_WAIT0(); }
        __syncthreads();

        const uint32_t st = sb + 8192 + s*F_STAGE;

        // ---- S = Q @ K^T (fp16 single) ----
        float sacc[8][4] = {};
        #pragma unroll
        for (int dc = 0; dc < 4; dc++) {
            #pragma unroll
            for (int ng = 0; ng < 4; ng++) {
                uint32_t so = SMEM_SWIZZLE_128B((uint32_t)(
                    ((ng<<4) + (lane & 7) + ((lane >> 4) << 3))*128 +
                    ((dc<<4) + ((lane >> 3) & 1)*8)*2));
                uint32_t kf[4];
                ldsm_x4(kf, st + so);
                mma_fp16(sacc[2*ng],   qf[dc], kf);
                mma_fp16(sacc[2*ng+1], qf[dc], kf + 2);
            }
        }

        // ---- causal mask (diagonal = last tile) ----
        if (kt == jq) {
            const int r0g = q0 + qrow + gl;
            #pragma unroll
            for (int f = 0; f < 8; f++) {
                const int kc0 = (kt << 6) + (f << 3) + (tl << 1);
                if (kc0     > r0g)     sacc[f][0] = -1e30f;
                if (kc0 + 1 > r0g)     sacc[f][1] = -1e30f;
                if (kc0     > r0g + 8) sacc[f][2] = -1e30f;
                if (kc0 + 1 > r0g + 8) sacc[f][3] = -1e30f;
            }
        }

        // ---- online softmax (base 2) ----
        float mx0 = m_run[0], mx1 = m_run[1];
        #pragma unroll
        for (int f = 0; f < 8; f++) {
            mx0 = fmaxf(mx0, fmaxf(sacc[f][0], sacc[f][1]));
            mx1 = fmaxf(mx1, fmaxf(sacc[f][2], sacc[f][3]));
        }
        mx0 = fmaxf(mx0, __shfl_xor_sync(0xffffffffu, mx0, 1));
        mx0 = fmaxf(mx0, __shfl_xor_sync(0xffffffffu, mx0, 2));
        mx1 = fmaxf(mx1, __shfl_xor_sync(0xffffffffu, mx1, 1));
        mx1 = fmaxf(mx1, __shfl_xor_sync(0xffffffffu, mx1, 2));
        const float a0 = exp2a(m_run[0] - mx0);
        const float a1 = exp2a(m_run[1] - mx1);
        m_run[0] = mx0; m_run[1] = mx1;

        float sum0 = 0.f, sum1 = 0.f;
        uint32_t pA[8], pB[8];
        #pragma unroll
        for (int f = 0; f < 8; f++) {
            float p0 = exp2a(sacc[f][0] - mx0);
            float p1 = exp2a(sacc[f][1] - mx0);
            float p2 = exp2a(sacc[f][2] - mx1);
            float p3 = exp2a(sacc[f][3] - mx1);
            sum0 += p0 + p1; sum1 += p2 + p3;
            pA[f] = pack_h2(p0, p1);
            pB[f] = pack_h2(p2, p3);
        }
        sum0 += __shfl_xor_sync(0xffffffffu, sum0, 1);
        sum0 += __shfl_xor_sync(0xffffffffu, sum0, 2);
        sum1 += __shfl_xor_sync(0xffffffffu, sum1, 1);
        sum1 += __shfl_xor_sync(0xffffffffu, sum1, 2);
        l_run[0] = l_run[0]*a0 + sum0;
        l_run[1] = l_run[1]*a1 + sum1;
        #pragma unroll
        for (int f = 0; f < 8; f++) {
            oacc[f][0] *= a0; oacc[f][1] *= a0;
            oacc[f][2] *= a1; oacc[f][3] *= a1;
        }

        // ---- O += P @ V (fp16 single; V via ldmatrix.trans) ----
        #pragma unroll
        for (int kc = 0; kc < 4; kc++) {
            uint32_t Af[4] = {pA[2*kc], pB[2*kc], pA[2*kc+1], pB[2*kc+1]};
            #pragma unroll
            for (int dg = 0; dg < 4; dg++) {
                uint32_t so = SMEM_SWIZZLE_128B((uint32_t)(
                    ((kc<<4) + (lane & 7) + ((lane >> 3) & 1)*8)*128 +
                    ((dg<<4) + (lane >> 4)*8)*2));
                uint32_t vf[4];
                ldsm_x4_t(vf, st + 8192 + so);
                mma_fp16(oacc[2*dg],   Af, vf);
                mma_fp16(oacc[2*dg+1], Af, vf + 2);
            }
        }

        __syncthreads();
        if (kt + 2 < ntiles) issue_kv(kt + 2, s);
    }

    // ---- epilogue: normalize, write y as fp16 [B,T,C] ----
    const float inv0 = 1.f / l_run[0];
    const float inv1 = 1.f / l_run[1];
    const int b_ = bh >> 4, h = bh & 15;
    const int t0 = q0 + qrow + gl, t1 = t0 + 8;
    #pragma unroll
    for (int f = 0; f < 8; f++) {
        const int col = h*DD + (f << 3) + (tl << 1);
        *(uint32_t*)(g_yh + (size_t)(b_*TT + t0) * CC + col) =
            pack_h2(oacc[f][0] * inv0, oacc[f][1] * inv0);
        *(uint32_t*)(g_yh + (size_t)(b_*TT + t1) * CC + col) =
            pack_h2(oacc[f][2] * inv1, oacc[f][3] * inv1);
    }
}

// ---------------------------------------------------------------------------

extern "C" void kernel_launch(void* const* d_in, const int* in_sizes, int n_in,
                              void* d_out, int out_size)
{
    const float* x  = (const float*)d_in[0];
    const float* Wq = (const float*)d_in[1];
    const float* bq = (const float*)d_in[2];
    const float* Wk = (const float*)d_in[3];
    const float* bk = (const float*)d_in[4];
    const float* Wv = (const float*)d_in[5];
    const float* bv = (const float*)d_in[6];
    const float* Wo = (const float*)d_in[7];
    const float* bo = (const float*)d_in[8];
    float* out = (float*)d_out;

    // 0) fp32 -> fp16 conversions (x4 vectorized) + bias concat
    prep_split<<<(8*1024*1024)/1024, 256>>>(Wq, Wk, Wv, Wo, x);
    prep_bias<<<12, 256>>>(bq, bk, bv);

    // 1) fused QKV projection (fp16 single) -> fp16 q/k/v (Q pre-scaled)
    cudaFuncSetAttribute(gemm_tc, cudaFuncAttributeMaxDynamicSharedMemorySize,
                         GEMM_SMEM);
    gemm_tc<<<dim3(3*CC/128, MM/128), 256, GEMM_SMEM>>>(0, nullptr, nullptr);

    // 2) tensor-core causal flash attention (fp16 single) -> y fp16
    cudaFuncSetAttribute(flash_tc, cudaFuncAttributeMaxDynamicSharedMemorySize,
                         F_SMEM);
    flash_tc<<<dim3(TT/64, BB*HH), F_THREADS, F_SMEM>>>();

    // 3) output projection (fp16 single) -> d_out
    gemm_tc<<<dim3(CC/128, MM/128), 256, GEMM_SMEM>>>(1, bo, out);
}

// round 12
// speedup vs baseline: 3.8674x; 1.0332x over previous
#include <cuda_runtime.h>
#include <cuda_bf16.h>
#include <cuda_fp16.h>
#include <cstdint>
#include <math.h>

#define BB 2
#define TT 2048
#define CC 1024
#define HH 16
#define DD 64
#define MM (BB*TT)   // 4096 rows

// ---------------------------------------------------------------------------
// Scratch (__device__ globals; allocation-free rule)
// ---------------------------------------------------------------------------
__device__ __half g_q[BB*HH*TT*DD];   // fp16 [B,H,T,D], Q pre-scaled
__device__ __half g_k[BB*HH*TT*DD];
__device__ __half g_v[BB*HH*TT*DD];

__device__ __half g_xh[MM*CC];        // x fp16
__device__ __half g_wh[3*CC*CC];      // Wq|Wk|Wv concat fp16
__device__ __half g_woh[CC*CC];       // Wo fp16
__device__ __half g_yh[MM*CC];        // attention output fp16 [B,T,C]
__device__ float g_bqkv[3*CC];        // bq|bk|bv concat

// Q pre-scale: 1/sqrt(64) * log2(e)  (softmax done in base-2)
#define QSCALE (0.125f * 1.4426950408889634f)

// ---------------------------------------------------------------------------
// Helpers: ldmatrix / mma.sync / cp.async (baseline sm_80+)
// ---------------------------------------------------------------------------
__device__ __forceinline__ uint32_t smem_to_u32(const void* p) {
    uint32_t a;
    asm("{ .reg .u64 t; cvta.to.shared.u64 t, %1; cvt.u32.u64 %0, t; }"
        : "=r"(a) : "l"(p));
    return a;
}
__device__ __forceinline__ void ldsm_x4(uint32_t* r, uint32_t addr) {
    asm volatile("ldmatrix.sync.aligned.m8n8.x4.shared.b16 {%0,%1,%2,%3}, [%4];"
        : "=r"(r[0]), "=r"(r[1]), "=r"(r[2]), "=r"(r[3]) : "r"(addr));
}
__device__ __forceinline__ void ldsm_x4_t(uint32_t* r, uint32_t addr) {
    asm volatile("ldmatrix.sync.aligned.m8n8.x4.trans.shared.b16 {%0,%1,%2,%3}, [%4];"
        : "=r"(r[0]), "=r"(r[1]), "=r"(r[2]), "=r"(r[3]) : "r"(addr));
}
__device__ __forceinline__ void mma_fp16(float* d, const uint32_t* a,
                                         const uint32_t* b) {
    asm volatile(
        "mma.sync.aligned.m16n8k16.row.col.f32.f16.f16.f32 "
        "{%0,%1,%2,%3}, {%4,%5,%6,%7}, {%8,%9}, {%0,%1,%2,%3};"
        : "+f"(d[0]), "+f"(d[1]), "+f"(d[2]), "+f"(d[3])
        : "r"(a[0]), "r"(a[1]), "r"(a[2]), "r"(a[3]), "r"(b[0]), "r"(b[1]));
}
__device__ __forceinline__ void cp16(uint32_t saddr, const void* g) {
    asm volatile("cp.async.cg.shared.global [%0], [%1], 16;"
        :: "r"(saddr), "l"(g) : "memory");
}
#define CP_COMMIT()  asm volatile("cp.async.commit_group;" ::: "memory")
#define CP_WAIT1()   asm volatile("cp.async.wait_group 1;" ::: "memory")
#define CP_WAIT0()   asm volatile("cp.async.wait_group 0;" ::: "memory")

#define SMEM_SWIZZLE_128B(byte_offset) \
    ((byte_offset) ^ (((byte_offset) >> 3) & 0x70))

__device__ __forceinline__ float exp2a(float x) {
    float y; asm("ex2.approx.f32 %0, %1;" : "=f"(y) : "f"(x)); return y;
}
__device__ __forceinline__ uint32_t exp2_h2(uint32_t x) {
    uint32_t y;
    asm("ex2.approx.f16x2 %0, %1;" : "=r"(y) : "r"(x));
    return y;
}
__device__ __forceinline__ uint32_t pack_h2(float a, float b) {
    __half2 h = __floats2half2_rn(a, b);
    return *reinterpret_cast<uint32_t*>(&h);
}

// ---------------------------------------------------------------------------
// Prep: fp32 -> fp16 (vectorized x4), bias concat.
// ---------------------------------------------------------------------------
__global__ __launch_bounds__(256) void prep_split(
    const float* __restrict__ Wq, const float* __restrict__ Wk,
    const float* __restrict__ Wv, const float* __restrict__ Wo,
    const float* __restrict__ x)
{
    const int i = (blockIdx.x * 256 + threadIdx.x) * 4;   // 0 .. 8M-1, step 4
    const int WQKV = 3*CC*CC, WO = CC*CC;
    const float* src;
    __half* dst;
    int j;
    if (i < WQKV) {
        src = (i < CC*CC) ? Wq : (i < 2*CC*CC) ? Wk : Wv;
        src += (i & (CC*CC - 1));
        dst = g_wh; j = i;
    } else if (i < WQKV + WO) {
        j = i - WQKV;
        src = Wo + j;
        dst = g_woh;
    } else {
        j = i - WQKV - WO;      // 0 .. 4M-1
        src = x + j;
        dst = g_xh;
    }
    float4 v = *(const float4*)src;
    uint2 o;
    o.x = pack_h2(v.x, v.y);
    o.y = pack_h2(v.z, v.w);
    *(uint2*)(dst + j) = o;
}

__global__ void prep_bias(const float* __restrict__ bq,
                          const float* __restrict__ bk,
                          const float* __restrict__ bv)
{
    int i = blockIdx.x * 256 + threadIdx.x;
    if (i < 3*CC)
        g_bqkv[i] = (i < CC) ? bq[i] : (i < 2*CC) ? bk[i-CC] : bv[i-2*CC];
}

// ---------------------------------------------------------------------------
// mma.sync GEMM (fp16 single-term): 128x128 tile of A[M,1024] @ B[N,1024]^T.
// mode 0: A=x, B=WqWkWv, scatter fp16 q/k/v (+bias, Q scaled).
// mode 1: A=y(fp16), B=Wo, write d_out fp32 (+bo).
// ---------------------------------------------------------------------------
#define CHUNK_K   64
#define NCHUNK    (CC / CHUNK_K)      // 16
#define BUF_BYTES (128*64*2)          // 16 KB per operand buffer
#define STAGE_BYTES (2*BUF_BYTES)     // 32 KB
#define OFF_A 0
#define OFF_B BUF_BYTES
#define GEMM_SMEM (2*STAGE_BYTES + 1024)   // 66560 B

__global__ __launch_bounds__(256, 2) void gemm_tc(
    int mode, const float* __restrict__ bias1, float* __restrict__ outf)
{
    extern __shared__ char smem[];
    const uint32_t smem_u32 = smem_to_u32(smem);
    const uint32_t tile_u32 = (smem_u32 + 1023) & ~1023u;

    const int tid  = threadIdx.x;
    const int wid  = tid >> 5;
    const int lane = tid & 31;
    const int wm   = wid >> 1;          // 0..3 (M)
    const int wn   = wid & 1;           // 0..1 (N)
    const int m0   = blockIdx.y << 7;
    const int n0   = blockIdx.x << 7;

    const __half *A, *B;
    if (mode == 0) { A = g_xh; B = g_wh;  }
    else           { A = g_yh; B = g_woh; }

    auto issue_chunk = [&](int c, int s) {
        const int kc = c * CHUNK_K;
        const uint32_t st = tile_u32 + s * STAGE_BYTES;
        #pragma unroll
        for (int i = 0; i < 4; i++) {
            int idx = tid + i*256;           // 0..1023
            int r   = idx >> 3;              // tile row 0..127
            int g   = idx & 7;               // 16B group in row
            uint32_t so = SMEM_SWIZZLE_128B((uint32_t)(r*128 + g*16));
            size_t aoff = (size_t)(m0 + r) * CC + kc + g*8;
            size_t boff = (size_t)(n0 + r) * CC + kc + g*8;
            cp16(st + OFF_A + so, A + aoff);
            cp16(st + OFF_B + so, B + boff);
        }
        CP_COMMIT();
    };

    float acc[2][8][4];
    #pragma unroll
    for (int mt = 0; mt < 2; mt++)
        #pragma unroll
        for (int nt = 0; nt < 8; nt++)
            #pragma unroll
            for (int e = 0; e < 4; e++) acc[mt][nt][e] = 0.f;

    issue_chunk(0, 0);
    issue_chunk(1, 1);

    for (int c = 0; c < NCHUNK; ++c) {
        const int s = c & 1;
        if (c + 1 < NCHUNK) { CP_WAIT1(); } else { CP_WAIT0(); }
        __syncthreads();

        const uint32_t sA = tile_u32 + s*STAGE_BYTES + OFF_A;
        const uint32_t sB = tile_u32 + s*STAGE_BYTES + OFF_B;

        #pragma unroll
        for (int ks = 0; ks < 4; ++ks) {
            uint32_t af[2][4];
            #pragma unroll
            for (int mt = 0; mt < 2; ++mt) {
                int r = wm*32 + mt*16 + (lane & 15);
                int g = ks*2 + (lane >> 4);
                uint32_t off = SMEM_SWIZZLE_128B((uint32_t)(r*128 + g*16));
                ldsm_x4(af[mt], sA + off);
            }
            #pragma unroll
            for (int np = 0; np < 4; ++np) {
                int n = wn*64 + np*16 + ((lane >> 4) << 3) + (lane & 7);
                int g = ks*2 + ((lane >> 3) & 1);
                uint32_t off = SMEM_SWIZZLE_128B((uint32_t)(n*128 + g*16));
                uint32_t bf[4];
                ldsm_x4(bf, sB + off);
                #pragma unroll
                for (int mt = 0; mt < 2; ++mt) {
                    mma_fp16(acc[mt][2*np],   af[mt], bf);
                    mma_fp16(acc[mt][2*np+1], af[mt], bf + 2);
                }
            }
        }

        if (c + 2 < NCHUNK) {
            __syncthreads();
            issue_chunk(c + 2, s);
        }
    }

    // --- epilogue ---
    const int gl = lane >> 2;          // 0..7
    const int tl = lane & 3;           // 0..3
    #pragma unroll
    for (int mt = 0; mt < 2; ++mt) {
        #pragma unroll
        for (int nt = 0; nt < 8; ++nt) {
            const int row0 = m0 + wm*32 + mt*16 + gl;
            const int colg = n0 + wn*64 + nt*8 + 2*tl;
            if (mode == 0) {
                const int head = colg >> 6;        // 0..47
                const int proj = head >> 4;        // 0=q 1=k 2=v
                const int h    = head & 15;
                const int d0c  = colg & 63;
                __half* dstp = (proj == 0) ? g_q : (proj == 1) ? g_k : g_v;
                const float2 bia = *(const float2*)&g_bqkv[colg];
                #pragma unroll
                for (int rr = 0; rr < 2; ++rr) {
                    const int m = row0 + rr*8;
                    const int b_ = m >> 11, t = m & 2047;
                    float v0 = acc[mt][nt][2*rr+0] + bia.x;
                    float v1 = acc[mt][nt][2*rr+1] + bia.y;
                    if (proj == 0) { v0 *= QSCALE; v1 *= QSCALE; }
                    size_t off = ((size_t)(b_*HH + h) * TT + t) * DD + d0c;
                    *(uint32_t*)(dstp + off) = pack_h2(v0, v1);
                }
            } else {
                const float2 bia = *(const float2*)&bias1[colg];
                #pragma unroll
                for (int rr = 0; rr < 2; ++rr) {
                    const int m = row0 + rr*8;
                    float2 o;
                    o.x = acc[mt][nt][2*rr+0] + bia.x;
                    o.y = acc[mt][nt][2*rr+1] + bia.y;
                    *(float2*)(outf + (size_t)m * CC + colg) = o;
                }
            }
        }
    }
}

// ---------------------------------------------------------------------------
// Tensor-core flash attention, full fp16 single-term.
// R12: softmax exp via ex2.approx.f16x2 (MUFU halved); row-sums l via
// ones-MMA (P @ 1), eliminating sum shuffles and guaranteeing p/l consistency.
// ---------------------------------------------------------------------------
#define F_THREADS 128
#define F_STAGE 16384                 // K(8KB) + V(8KB) per stage
#define F_SMEM (8192 + 2*F_STAGE)     // Q 8KB + 2 stages = 40960 B

__global__ __launch_bounds__(F_THREADS, 3) void flash_tc()
{
    extern __shared__ char fsm[];
    const uint32_t sb = smem_to_u32(fsm);
    const uint32_t sQ = sb;

    const int tid = threadIdx.x, wid = tid >> 5, lane = tid & 31;
    const int gl = lane >> 2, tl = lane & 3;
    const int jq = (int)gridDim.x - 1 - (int)blockIdx.x;   // heavy tiles first
    const int q0 = jq << 6;                                 // 64-row q tiles
    const int bh = blockIdx.y;
    const size_t hb = (size_t)bh * TT * DD;
    const __half *qp = g_q + hb + (size_t)q0 * DD;
    const __half *kp = g_k + hb, *vp = g_v + hb;
    const int ntiles = jq + 1;

    // --- Q tile: 64 rows x 8 chunks = 512 chunks (4 iters x 128 thr) ---
    #pragma unroll
    for (int i = 0; i < 4; i++) {
        int idx = tid + i*F_THREADS;        // 0..511
        int r = idx >> 3, c = idx & 7;
        uint32_t so = SMEM_SWIZZLE_128B((uint32_t)(r*128 + c*16));
        cp16(sQ + so, qp + (size_t)r*DD + c*8);
    }
    CP_COMMIT();

    auto issue_kv = [&](int kt, int s) {
        const uint32_t st = sb + 8192 + s*F_STAGE;
        const int r0 = kt << 6;
        #pragma unroll
        for (int i = 0; i < 8; i++) {
            int idx = tid + i*F_THREADS;    // 0..1023
            int buf = idx >> 9;             // 0 K, 1 V
            int rc = idx & 511; int r = rc >> 3, c = rc & 7;
            uint32_t so = SMEM_SWIZZLE_128B((uint32_t)(r*128 + c*16));
            const __half* src = (buf ? vp : kp) + (size_t)(r0 + r) * DD + c*8;
            cp16(st + buf*8192 + so, src);
        }
        CP_COMMIT();
    };
    issue_kv(0, 0);
    issue_kv(1, 1);       // prefetch (valid memory even if unused)

    CP_WAIT1();           // Q + stage0 complete
    __syncthreads();

    // --- Q fragments (persistent) ---
    const int qrow = wid << 4;               // 0..48
    uint32_t qf[4][4];
    #pragma unroll
    for (int dc = 0; dc < 4; dc++) {
        uint32_t so = SMEM_SWIZZLE_128B((uint32_t)(
            (qrow + (lane & 15))*128 + (dc*16 + ((lane >> 4) << 3))*2));
        ldsm_x4(qf[dc], sQ + so);
    }

    float m_run[2] = {-1e30f, -1e30f};
    float l_run[2] = {0.f, 0.f};
    float oacc[8][4];
    #pragma unroll
    for (int f = 0; f < 8; f++)
        #pragma unroll
        for (int e = 0; e < 4; e++) oacc[f][e] = 0.f;

    const uint32_t onesB[2] = {0x3C003C00u, 0x3C003C00u};   // fp16 1.0 x4

    for (int kt = 0; kt < ntiles; kt++) {
        const int s = kt & 1;
        if (kt + 1 < ntiles) { CP_WAIT1(); } else { CP_WAIT0(); }
        __syncthreads();

        const uint32_t st = sb + 8192 + s*F_STAGE;

        // ---- S = Q @ K^T (fp16 single) ----
        float sacc[8][4] = {};
        #pragma unroll
        for (int dc = 0; dc < 4; dc++) {
            #pragma unroll
            for (int ng = 0; ng < 4; ng++) {
                uint32_t so = SMEM_SWIZZLE_128B((uint32_t)(
                    ((ng<<4) + (lane & 7) + ((lane >> 4) << 3))*128 +
                    ((dc<<4) + ((lane >> 3) & 1)*8)*2));
                uint32_t kf[4];
                ldsm_x4(kf, st + so);
                mma_fp16(sacc[2*ng],   qf[dc], kf);
                mma_fp16(sacc[2*ng+1], qf[dc], kf + 2);
            }
        }

        // ---- causal mask (diagonal = last tile) ----
        if (kt == jq) {
            const int r0g = q0 + qrow + gl;
            #pragma unroll
            for (int f = 0; f < 8; f++) {
                const int kc0 = (kt << 6) + (f << 3) + (tl << 1);
                if (kc0     > r0g)     sacc[f][0] = -1e30f;
                if (kc0 + 1 > r0g)     sacc[f][1] = -1e30f;
                if (kc0     > r0g + 8) sacc[f][2] = -1e30f;
                if (kc0 + 1 > r0g + 8) sacc[f][3] = -1e30f;
            }
        }

        // ---- online softmax (base 2; exp via f16x2, sums via ones-MMA) ----
        float mx0 = m_run[0], mx1 = m_run[1];
        #pragma unroll
        for (int f = 0; f < 8; f++) {
            mx0 = fmaxf(mx0, fmaxf(sacc[f][0], sacc[f][1]));
            mx1 = fmaxf(mx1, fmaxf(sacc[f][2], sacc[f][3]));
        }
        mx0 = fmaxf(mx0, __shfl_xor_sync(0xffffffffu, mx0, 1));
        mx0 = fmaxf(mx0, __shfl_xor_sync(0xffffffffu, mx0, 2));
        mx1 = fmaxf(mx1, __shfl_xor_sync(0xffffffffu, mx1, 1));
        mx1 = fmaxf(mx1, __shfl_xor_sync(0xffffffffu, mx1, 2));
        const float a0 = exp2a(m_run[0] - mx0);
        const float a1 = exp2a(m_run[1] - mx1);
        m_run[0] = mx0; m_run[1] = mx1;

        uint32_t pA[8], pB[8];
        #pragma unroll
        for (int f = 0; f < 8; f++) {
            pA[f] = exp2_h2(pack_h2(sacc[f][0] - mx0, sacc[f][1] - mx0));
            pB[f] = exp2_h2(pack_h2(sacc[f][2] - mx1, sacc[f][3] - mx1));
        }

        // row sums: lacc = P @ ones  (d[0]=row gl, d[2]=row gl+8)
        float lacc[4] = {0.f, 0.f, 0.f, 0.f};
        #pragma unroll
        for (int kc = 0; kc < 4; kc++) {
            uint32_t Af[4] = {pA[2*kc], pB[2*kc], pA[2*kc+1], pB[2*kc+1]};
            mma_fp16(lacc, Af, onesB);
        }
        l_run[0] = l_run[0]*a0 + lacc[0];
        l_run[1] = l_run[1]*a1 + lacc[2];
        #pragma unroll
        for (int f = 0; f < 8; f++) {
            oacc[f][0] *= a0; oacc[f][1] *= a0;
            oacc[f][2] *= a1; oacc[f][3] *= a1;
        }

        // ---- O += P @ V (fp16 single; V via ldmatrix.trans) ----
        #pragma unroll
        for (int kc = 0; kc < 4; kc++) {
            uint32_t Af[4] = {pA[2*kc], pB[2*kc], pA[2*kc+1], pB[2*kc+1]};
            #pragma unroll
            for (int dg = 0; dg < 4; dg++) {
                uint32_t so = SMEM_SWIZZLE_128B((uint32_t)(
                    ((kc<<4) + (lane & 7) + ((lane >> 3) & 1)*8)*128 +
                    ((dg<<4) + (lane >> 4)*8)*2));
                uint32_t vf[4];
                ldsm_x4_t(vf, st + 8192 + so);
                mma_fp16(oacc[2*dg],   Af, vf);
                mma_fp16(oacc[2*dg+1], Af, vf + 2);
            }
        }

        __syncthreads();
        if (kt + 2 < ntiles) issue_kv(kt + 2, s);
    }

    // ---- epilogue: normalize, write y as fp16 [B,T,C] ----
    const float inv0 = 1.f / l_run[0];
    const float inv1 = 1.f / l_run[1];
    const int b_ = bh >> 4, h = bh & 15;
    const int t0 = q0 + qrow + gl, t1 = t0 + 8;
    #pragma unroll
    for (int f = 0; f < 8; f++) {
        const int col = h*DD + (f << 3) + (tl << 1);
        *(uint32_t*)(g_yh + (size_t)(b_*TT + t0) * CC + col) =
            pack_h2(oacc[f][0] * inv0, oacc[f][1] * inv0);
        *(uint32_t*)(g_yh + (size_t)(b_*TT + t1) * CC + col) =
            pack_h2(oacc[f][2] * inv1, oacc[f][3] * inv1);
    }
}

// ---------------------------------------------------------------------------

extern "C" void kernel_launch(void* const* d_in, const int* in_sizes, int n_in,
                              void* d_out, int out_size)
{
    const float* x  = (const float*)d_in[0];
    const float* Wq = (const float*)d_in[1];
    const float* bq = (const float*)d_in[2];
    const float* Wk = (const float*)d_in[3];
    const float* bk = (const float*)d_in[4];
    const float* Wv = (const float*)d_in[5];
    const float* bv = (const float*)d_in[6];
    const float* Wo = (const float*)d_in[7];
    const float* bo = (const float*)d_in[8];
    float* out = (float*)d_out;

    // 0) fp32 -> fp16 conversions (x4 vectorized) + bias concat
    prep_split<<<(8*1024*1024)/1024, 256>>>(Wq, Wk, Wv, Wo, x);
    prep_bias<<<12, 256>>>(bq, bk, bv);

    // 1) fused QKV projection (fp16 single) -> fp16 q/k/v (Q pre-scaled)
    cudaFuncSetAttribute(gemm_tc, cudaFuncAttributeMaxDynamicSharedMemorySize,
                         GEMM_SMEM);
    gemm_tc<<<dim3(3*CC/128, MM/128), 256, GEMM_SMEM>>>(0, nullptr, nullptr);

    // 2) tensor-core causal flash attention (fp16 single) -> y fp16
    cudaFuncSetAttribute(flash_tc, cudaFuncAttributeMaxDynamicSharedMemorySize,
                         F_SMEM);
    flash_tc<<<dim3(TT/64, BB*HH), F_THREADS, F_SMEM>>>();

    // 3) output projection (fp16 single) -> d_out
    gemm_tc<<<dim3(CC/128, MM/128), 256, GEMM_SMEM>>>(1, bo, out);
}

// round 13
// speedup vs baseline: 3.8971x; 1.0077x over previous
#include <cuda_runtime.h>
#include <cuda_bf16.h>
#include <cuda_fp16.h>
#include <cstdint>
#include <math.h>

#define BB 2
#define TT 2048
#define CC 1024
#define HH 16
#define DD 64
#define MM (BB*TT)   // 4096 rows

// ---------------------------------------------------------------------------
// Scratch (__device__ globals; allocation-free rule)
// ---------------------------------------------------------------------------
__device__ __half g_q[BB*HH*TT*DD];   // fp16 [B,H,T,D], Q pre-scaled
__device__ __half g_k[BB*HH*TT*DD];
__device__ __half g_v[BB*HH*TT*DD];

__device__ __half g_xh[MM*CC];        // x fp16
__device__ __half g_wh[3*CC*CC];      // Wq|Wk|Wv concat fp16
__device__ __half g_woh[CC*CC];       // Wo fp16
__device__ __half g_yh[MM*CC];        // attention output fp16 [B,T,C]
__device__ float g_bqkv[3*CC];        // bq|bk|bv concat

// Q pre-scale: 1/sqrt(64) * log2(e)  (softmax done in base-2)
#define QSCALE (0.125f * 1.4426950408889634f)

// ---------------------------------------------------------------------------
// Helpers: ldmatrix / mma.sync / cp.async (baseline sm_80+)
// ---------------------------------------------------------------------------
__device__ __forceinline__ uint32_t smem_to_u32(const void* p) {
    uint32_t a;
    asm("{ .reg .u64 t; cvta.to.shared.u64 t, %1; cvt.u32.u64 %0, t; }"
        : "=r"(a) : "l"(p));
    return a;
}
__device__ __forceinline__ void ldsm_x4(uint32_t* r, uint32_t addr) {
    asm volatile("ldmatrix.sync.aligned.m8n8.x4.shared.b16 {%0,%1,%2,%3}, [%4];"
        : "=r"(r[0]), "=r"(r[1]), "=r"(r[2]), "=r"(r[3]) : "r"(addr));
}
__device__ __forceinline__ void ldsm_x4_t(uint32_t* r, uint32_t addr) {
    asm volatile("ldmatrix.sync.aligned.m8n8.x4.trans.shared.b16 {%0,%1,%2,%3}, [%4];"
        : "=r"(r[0]), "=r"(r[1]), "=r"(r[2]), "=r"(r[3]) : "r"(addr));
}
__device__ __forceinline__ void mma_fp16(float* d, const uint32_t* a,
                                         const uint32_t* b) {
    asm volatile(
        "mma.sync.aligned.m16n8k16.row.col.f32.f16.f16.f32 "
        "{%0,%1,%2,%3}, {%4,%5,%6,%7}, {%8,%9}, {%0,%1,%2,%3};"
        : "+f"(d[0]), "+f"(d[1]), "+f"(d[2]), "+f"(d[3])
        : "r"(a[0]), "r"(a[1]), "r"(a[2]), "r"(a[3]), "r"(b[0]), "r"(b[1]));
}
__device__ __forceinline__ void cp16(uint32_t saddr, const void* g) {
    asm volatile("cp.async.cg.shared.global [%0], [%1], 16;"
        :: "r"(saddr), "l"(g) : "memory");
}
#define CP_COMMIT()  asm volatile("cp.async.commit_group;" ::: "memory")
#define CP_WAIT2()   asm volatile("cp.async.wait_group 2;" ::: "memory")
#define CP_WAIT1()   asm volatile("cp.async.wait_group 1;" ::: "memory")
#define CP_WAIT0()   asm volatile("cp.async.wait_group 0;" ::: "memory")

#define SMEM_SWIZZLE_128B(byte_offset) \
    ((byte_offset) ^ (((byte_offset) >> 3) & 0x70))

__device__ __forceinline__ float exp2a(float x) {
    float y; asm("ex2.approx.f32 %0, %1;" : "=f"(y) : "f"(x)); return y;
}
__device__ __forceinline__ uint32_t exp2_h2(uint32_t x) {
    uint32_t y;
    asm("ex2.approx.f16x2 %0, %1;" : "=r"(y) : "r"(x));
    return y;
}
__device__ __forceinline__ uint32_t pack_h2(float a, float b) {
    __half2 h = __floats2half2_rn(a, b);
    return *reinterpret_cast<uint32_t*>(&h);
}

// ---------------------------------------------------------------------------
// Prep: fp32 -> fp16 (vectorized x4), bias concat.
// ---------------------------------------------------------------------------
__global__ __launch_bounds__(256) void prep_split(
    const float* __restrict__ Wq, const float* __restrict__ Wk,
    const float* __restrict__ Wv, const float* __restrict__ Wo,
    const float* __restrict__ x)
{
    const int i = (blockIdx.x * 256 + threadIdx.x) * 4;   // 0 .. 8M-1, step 4
    const int WQKV = 3*CC*CC, WO = CC*CC;
    const float* src;
    __half* dst;
    int j;
    if (i < WQKV) {
        src = (i < CC*CC) ? Wq : (i < 2*CC*CC) ? Wk : Wv;
        src += (i & (CC*CC - 1));
        dst = g_wh; j = i;
    } else if (i < WQKV + WO) {
        j = i - WQKV;
        src = Wo + j;
        dst = g_woh;
    } else {
        j = i - WQKV - WO;      // 0 .. 4M-1
        src = x + j;
        dst = g_xh;
    }
    float4 v = *(const float4*)src;
    uint2 o;
    o.x = pack_h2(v.x, v.y);
    o.y = pack_h2(v.z, v.w);
    *(uint2*)(dst + j) = o;
}

__global__ void prep_bias(const float* __restrict__ bq,
                          const float* __restrict__ bk,
                          const float* __restrict__ bv)
{
    int i = blockIdx.x * 256 + threadIdx.x;
    if (i < 3*CC)
        g_bqkv[i] = (i < CC) ? bq[i] : (i < 2*CC) ? bk[i-CC] : bv[i-2*CC];
}

// ---------------------------------------------------------------------------
// mma.sync GEMM (fp16 single-term): 128x128 tile, 3-stage cp.async pipeline
// (prefetch depth 2). mode 0: A=x, B=WqWkWv -> fp16 q/k/v (+bias, Q scaled).
// mode 1: A=y(fp16), B=Wo -> d_out fp32 (+bo).
// ---------------------------------------------------------------------------
#define CHUNK_K   64
#define NCHUNK    (CC / CHUNK_K)      // 16
#define BUF_BYTES (128*64*2)          // 16 KB per operand buffer
#define STAGE_BYTES (2*BUF_BYTES)     // 32 KB
#define OFF_A 0
#define OFF_B BUF_BYTES
#define GEMM_SMEM (3*STAGE_BYTES + 1024)   // 99328 B (2 CTAs/SM)

__global__ __launch_bounds__(256, 2) void gemm_tc(
    int mode, const float* __restrict__ bias1, float* __restrict__ outf)
{
    extern __shared__ char smem[];
    const uint32_t smem_u32 = smem_to_u32(smem);
    const uint32_t tile_u32 = (smem_u32 + 1023) & ~1023u;

    const int tid  = threadIdx.x;
    const int wid  = tid >> 5;
    const int lane = tid & 31;
    const int wm   = wid >> 1;          // 0..3 (M)
    const int wn   = wid & 1;           // 0..1 (N)
    const int m0   = blockIdx.y << 7;
    const int n0   = blockIdx.x << 7;

    const __half *A, *B;
    if (mode == 0) { A = g_xh; B = g_wh;  }
    else           { A = g_yh; B = g_woh; }

    auto issue_chunk = [&](int c, int s) {
        const int kc = c * CHUNK_K;
        const uint32_t st = tile_u32 + s * STAGE_BYTES;
        #pragma unroll
        for (int i = 0; i < 4; i++) {
            int idx = tid + i*256;           // 0..1023
            int r   = idx >> 3;              // tile row 0..127
            int g   = idx & 7;               // 16B group in row
            uint32_t so = SMEM_SWIZZLE_128B((uint32_t)(r*128 + g*16));
            size_t aoff = (size_t)(m0 + r) * CC + kc + g*8;
            size_t boff = (size_t)(n0 + r) * CC + kc + g*8;
            cp16(st + OFF_A + so, A + aoff);
            cp16(st + OFF_B + so, B + boff);
        }
        CP_COMMIT();
    };

    float acc[2][8][4];
    #pragma unroll
    for (int mt = 0; mt < 2; mt++)
        #pragma unroll
        for (int nt = 0; nt < 8; nt++)
            #pragma unroll
            for (int e = 0; e < 4; e++) acc[mt][nt][e] = 0.f;

    issue_chunk(0, 0);
    issue_chunk(1, 1);
    issue_chunk(2, 2);

    for (int c = 0; c < NCHUNK; ++c) {
        const int s = c % 3;
        if (c + 2 < NCHUNK)      { CP_WAIT2(); }
        else if (c + 1 < NCHUNK) { CP_WAIT1(); }
        else                     { CP_WAIT0(); }
        __syncthreads();

        const uint32_t sA = tile_u32 + s*STAGE_BYTES + OFF_A;
        const uint32_t sB = tile_u32 + s*STAGE_BYTES + OFF_B;

        #pragma unroll
        for (int ks = 0; ks < 4; ++ks) {
            uint32_t af[2][4];
            #pragma unroll
            for (int mt = 0; mt < 2; ++mt) {
                int r = wm*32 + mt*16 + (lane & 15);
                int g = ks*2 + (lane >> 4);
                uint32_t off = SMEM_SWIZZLE_128B((uint32_t)(r*128 + g*16));
                ldsm_x4(af[mt], sA + off);
            }
            #pragma unroll
            for (int np = 0; np < 4; ++np) {
                int n = wn*64 + np*16 + ((lane >> 4) << 3) + (lane & 7);
                int g = ks*2 + ((lane >> 3) & 1);
                uint32_t off = SMEM_SWIZZLE_128B((uint32_t)(n*128 + g*16));
                uint32_t bf[4];
                ldsm_x4(bf, sB + off);
                #pragma unroll
                for (int mt = 0; mt < 2; ++mt) {
                    mma_fp16(acc[mt][2*np],   af[mt], bf);
                    mma_fp16(acc[mt][2*np+1], af[mt], bf + 2);
                }
            }
        }

        if (c + 3 < NCHUNK) {
            __syncthreads();           // all warps done reading stage s
            issue_chunk(c + 3, s);
        }
    }

    // --- epilogue ---
    const int gl = lane >> 2;          // 0..7
    const int tl = lane & 3;           // 0..3
    #pragma unroll
    for (int mt = 0; mt < 2; ++mt) {
        #pragma unroll
        for (int nt = 0; nt < 8; ++nt) {
            const int row0 = m0 + wm*32 + mt*16 + gl;
            const int colg = n0 + wn*64 + nt*8 + 2*tl;
            if (mode == 0) {
                const int head = colg >> 6;        // 0..47
                const int proj = head >> 4;        // 0=q 1=k 2=v
                const int h    = head & 15;
                const int d0c  = colg & 63;
                __half* dstp = (proj == 0) ? g_q : (proj == 1) ? g_k : g_v;
                const float2 bia = *(const float2*)&g_bqkv[colg];
                #pragma unroll
                for (int rr = 0; rr < 2; ++rr) {
                    const int m = row0 + rr*8;
                    const int b_ = m >> 11, t = m & 2047;
                    float v0 = acc[mt][nt][2*rr+0] + bia.x;
                    float v1 = acc[mt][nt][2*rr+1] + bia.y;
                    if (proj == 0) { v0 *= QSCALE; v1 *= QSCALE; }
                    size_t off = ((size_t)(b_*HH + h) * TT + t) * DD + d0c;
                    *(uint32_t*)(dstp + off) = pack_h2(v0, v1);
                }
            } else {
                const float2 bia = *(const float2*)&bias1[colg];
                #pragma unroll
                for (int rr = 0; rr < 2; ++rr) {
                    const int m = row0 + rr*8;
                    float2 o;
                    o.x = acc[mt][nt][2*rr+0] + bia.x;
                    o.y = acc[mt][nt][2*rr+1] + bia.y;
                    *(float2*)(outf + (size_t)m * CC + colg) = o;
                }
            }
        }
    }
}

// ---------------------------------------------------------------------------
// Tensor-core flash attention, fp16 single-term, f16x2 exp, ones-MMA row sums.
// R13: 3 KV stages (prefetch depth 2), smem 56 KB -> 3 CTAs/SM.
// ---------------------------------------------------------------------------
#define F_THREADS 128
#define F_STAGE 16384                 // K(8KB) + V(8KB) per stage
#define F_SMEM (8192 + 3*F_STAGE)     // Q 8KB + 3 stages = 57344 B

__global__ __launch_bounds__(F_THREADS, 3) void flash_tc()
{
    extern __shared__ char fsm[];
    const uint32_t sb = smem_to_u32(fsm);
    const uint32_t sQ = sb;

    const int tid = threadIdx.x, wid = tid >> 5, lane = tid & 31;
    const int gl = lane >> 2, tl = lane & 3;
    const int jq = (int)gridDim.x - 1 - (int)blockIdx.x;   // heavy tiles first
    const int q0 = jq << 6;                                 // 64-row q tiles
    const int bh = blockIdx.y;
    const size_t hb = (size_t)bh * TT * DD;
    const __half *qp = g_q + hb + (size_t)q0 * DD;
    const __half *kp = g_k + hb, *vp = g_v + hb;
    const int ntiles = jq + 1;

    // --- Q tile: 64 rows x 8 chunks = 512 chunks (4 iters x 128 thr) ---
    #pragma unroll
    for (int i = 0; i < 4; i++) {
        int idx = tid + i*F_THREADS;        // 0..511
        int r = idx >> 3, c = idx & 7;
        uint32_t so = SMEM_SWIZZLE_128B((uint32_t)(r*128 + c*16));
        cp16(sQ + so, qp + (size_t)r*DD + c*8);
    }
    CP_COMMIT();

    auto issue_kv = [&](int kt, int s) {
        const uint32_t st = sb + 8192 + s*F_STAGE;
        const int r0 = kt << 6;
        #pragma unroll
        for (int i = 0; i < 8; i++) {
            int idx = tid + i*F_THREADS;    // 0..1023
            int buf = idx >> 9;             // 0 K, 1 V
            int rc = idx & 511; int r = rc >> 3, c = rc & 7;
            uint32_t so = SMEM_SWIZZLE_128B((uint32_t)(r*128 + c*16));
            const __half* src = (buf ? vp : kp) + (size_t)(r0 + r) * DD + c*8;
            cp16(st + buf*8192 + so, src);
        }
        CP_COMMIT();
    };
    issue_kv(0, 0);
    issue_kv(1, 1);       // prefetch depth 2 (valid memory even if unused:
    issue_kv(2, 2);       //  rows < 3*64 << T always exist)

    // Q + stage0 ready (leave kv1, kv2 in flight)
    CP_WAIT2();
    __syncthreads();

    // --- Q fragments (persistent) ---
    const int qrow = wid << 4;               // 0..48
    uint32_t qf[4][4];
    #pragma unroll
    for (int dc = 0; dc < 4; dc++) {
        uint32_t so = SMEM_SWIZZLE_128B((uint32_t)(
            (qrow + (lane & 15))*128 + (dc*16 + ((lane >> 4) << 3))*2));
        ldsm_x4(qf[dc], sQ + so);
    }

    float m_run[2] = {-1e30f, -1e30f};
    float l_run[2] = {0.f, 0.f};
    float oacc[8][4];
    #pragma unroll
    for (int f = 0; f < 8; f++)
        #pragma unroll
        for (int e = 0; e < 4; e++) oacc[f][e] = 0.f;

    const uint32_t onesB[2] = {0x3C003C00u, 0x3C003C00u};   // fp16 1.0 x4

    for (int kt = 0; kt < ntiles; kt++) {
        const int s = kt % 3;
        if (kt == 0) { /* already waited above */ }
        else if (kt + 2 < ntiles) { CP_WAIT2(); }
        else if (kt + 1 < ntiles) { CP_WAIT1(); }
        else                      { CP_WAIT0(); }
        if (kt) __syncthreads();

        const uint32_t st = sb + 8192 + s*F_STAGE;

        // ---- S = Q @ K^T (fp16 single) ----
        float sacc[8][4] = {};
        #pragma unroll
        for (int dc = 0; dc < 4; dc++) {
            #pragma unroll
            for (int ng = 0; ng < 4; ng++) {
                uint32_t so = SMEM_SWIZZLE_128B((uint32_t)(
                    ((ng<<4) + (lane & 7) + ((lane >> 4) << 3))*128 +
                    ((dc<<4) + ((lane >> 3) & 1)*8)*2));
                uint32_t kf[4];
                ldsm_x4(kf, st + so);
                mma_fp16(sacc[2*ng],   qf[dc], kf);
                mma_fp16(sacc[2*ng+1], qf[dc], kf + 2);
            }
        }

        // ---- causal mask (diagonal = last tile) ----
        if (kt == jq) {
            const int r0g = q0 + qrow + gl;
            #pragma unroll
            for (int f = 0; f < 8; f++) {
                const int kc0 = (kt << 6) + (f << 3) + (tl << 1);
                if (kc0     > r0g)     sacc[f][0] = -1e30f;
                if (kc0 + 1 > r0g)     sacc[f][1] = -1e30f;
                if (kc0     > r0g + 8) sacc[f][2] = -1e30f;
                if (kc0 + 1 > r0g + 8) sacc[f][3] = -1e30f;
            }
        }

        // ---- online softmax (base 2; exp via f16x2, sums via ones-MMA) ----
        float mx0 = m_run[0], mx1 = m_run[1];
        #pragma unroll
        for (int f = 0; f < 8; f++) {
            mx0 = fmaxf(mx0, fmaxf(sacc[f][0], sacc[f][1]));
            mx1 = fmaxf(mx1, fmaxf(sacc[f][2], sacc[f][3]));
        }
        mx0 = fmaxf(mx0, __shfl_xor_sync(0xffffffffu, mx0, 1));
        mx0 = fmaxf(mx0, __shfl_xor_sync(0xffffffffu, mx0, 2));
        mx1 = fmaxf(mx1, __shfl_xor_sync(0xffffffffu, mx1, 1));
        mx1 = fmaxf(mx1, __shfl_xor_sync(0xffffffffu, mx1, 2));
        const float a0 = exp2a(m_run[0] - mx0);
        const float a1 = exp2a(m_run[1] - mx1);
        m_run[0] = mx0; m_run[1] = mx1;

        uint32_t pA[8], pB[8];
        #pragma unroll
        for (int f = 0; f < 8; f++) {
            pA[f] = exp2_h2(pack_h2(sacc[f][0] - mx0, sacc[f][1] - mx0));
            pB[f] = exp2_h2(pack_h2(sacc[f][2] - mx1, sacc[f][3] - mx1));
        }

        // row sums: lacc = P @ ones  (d[0]=row gl, d[2]=row gl+8)
        float lacc[4] = {0.f, 0.f, 0.f, 0.f};
        #pragma unroll
        for (int kc = 0; kc < 4; kc++) {
            uint32_t Af[4] = {pA[2*kc], pB[2*kc], pA[2*kc+1], pB[2*kc+1]};
            mma_fp16(lacc, Af, onesB);
        }
        l_run[0] = l_run[0]*a0 + lacc[0];
        l_run[1] = l_run[1]*a1 + lacc[2];
        #pragma unroll
        for (int f = 0; f < 8; f++) {
            oacc[f][0] *= a0; oacc[f][1] *= a0;
            oacc[f][2] *= a1; oacc[f][3] *= a1;
        }

        // ---- O += P @ V (fp16 single; V via ldmatrix.trans) ----
        #pragma unroll
        for (int kc = 0; kc < 4; kc++) {
            uint32_t Af[4] = {pA[2*kc], pB[2*kc], pA[2*kc+1], pB[2*kc+1]};
            #pragma unroll
            for (int dg = 0; dg < 4; dg++) {
                uint32_t so = SMEM_SWIZZLE_128B((uint32_t)(
                    ((kc<<4) + (lane & 7) + ((lane >> 3) & 1)*8)*128 +
                    ((dg<<4) + (lane >> 4)*8)*2));
                uint32_t vf[4];
                ldsm_x4_t(vf, st + 8192 + so);
                mma_fp16(oacc[2*dg],   Af, vf);
                mma_fp16(oacc[2*dg+1], Af, vf + 2);
            }
        }

        if (kt + 3 < ntiles) {
            __syncthreads();            // all warps done reading stage s
            issue_kv(kt + 3, s);
        }
    }

    // ---- epilogue: normalize, write y as fp16 [B,T,C] ----
    const float inv0 = 1.f / l_run[0];
    const float inv1 = 1.f / l_run[1];
    const int b_ = bh >> 4, h = bh & 15;
    const int t0 = q0 + qrow + gl, t1 = t0 + 8;
    #pragma unroll
    for (int f = 0; f < 8; f++) {
        const int col = h*DD + (f << 3) + (tl << 1);
        *(uint32_t*)(g_yh + (size_t)(b_*TT + t0) * CC + col) =
            pack_h2(oacc[f][0] * inv0, oacc[f][1] * inv0);
        *(uint32_t*)(g_yh + (size_t)(b_*TT + t1) * CC + col) =
            pack_h2(oacc[f][2] * inv1, oacc[f][3] * inv1);
    }
}

// ---------------------------------------------------------------------------

extern "C" void kernel_launch(void* const* d_in, const int* in_sizes, int n_in,
                              void* d_out, int out_size)
{
    const float* x  = (const float*)d_in[0];
    const float* Wq = (const float*)d_in[1];
    const float* bq = (const float*)d_in[2];
    const float* Wk = (const float*)d_in[3];
    const float* bk = (const float*)d_in[4];
    const float* Wv = (const float*)d_in[5];
    const float* bv = (const float*)d_in[6];
    const float* Wo = (const float*)d_in[7];
    const float* bo = (const float*)d_in[8];
    float* out = (float*)d_out;

    // 0) fp32 -> fp16 conversions (x4 vectorized) + bias concat
    prep_split<<<(8*1024*1024)/1024, 256>>>(Wq, Wk, Wv, Wo, x);
    prep_bias<<<12, 256>>>(bq, bk, bv);

    // 1) fused QKV projection (fp16 single, 3-stage) -> fp16 q/k/v
    cudaFuncSetAttribute(gemm_tc, cudaFuncAttributeMaxDynamicSharedMemorySize,
                         GEMM_SMEM);
    gemm_tc<<<dim3(3*CC/128, MM/128), 256, GEMM_SMEM>>>(0, nullptr, nullptr);

    // 2) tensor-core causal flash attention (fp16, 3-stage) -> y fp16
    cudaFuncSetAttribute(flash_tc, cudaFuncAttributeMaxDynamicSharedMemorySize,
                         F_SMEM);
    flash_tc<<<dim3(TT/64, BB*HH), F_THREADS, F_SMEM>>>();

    // 3) output projection (fp16 single, 3-stage) -> d_out
    gemm_tc<<<dim3(CC/128, MM/128), 256, GEMM_SMEM>>>(1, bo, out);
}

// round 15
// speedup vs baseline: 3.9265x; 1.0076x over previous
#include <cuda_runtime.h>
#include <cuda_bf16.h>
#include <cuda_fp16.h>
#include <cstdint>
#include <math.h>

#define BB 2
#define TT 2048
#define CC 1024
#define HH 16
#define DD 64
#define MM (BB*TT)   // 4096 rows

// ---------------------------------------------------------------------------
// Scratch (__device__ globals; allocation-free rule)
// ---------------------------------------------------------------------------
__device__ __half g_q[BB*HH*TT*DD];   // fp16 [B,H,T,D], Q pre-scaled
__device__ __half g_k[BB*HH*TT*DD];
__device__ __half g_v[BB*HH*TT*DD];

__device__ __half g_xh[MM*CC];        // x fp16
__device__ __half g_wh[3*CC*CC];      // Wq|Wk|Wv concat fp16
__device__ __half g_woh[CC*CC];       // Wo fp16
__device__ __half g_yh[MM*CC];        // attention output fp16 [B,T,C]
__device__ float g_bqkv[3*CC];        // bq|bk|bv concat

// Q pre-scale: 1/sqrt(64) * log2(e)  (softmax done in base-2)
#define QSCALE (0.125f * 1.4426950408889634f)

// ---------------------------------------------------------------------------
// Helpers: ldmatrix / mma.sync / cp.async (baseline sm_80+)
// ---------------------------------------------------------------------------
__device__ __forceinline__ uint32_t smem_to_u32(const void* p) {
    uint32_t a;
    asm("{ .reg .u64 t; cvta.to.shared.u64 t, %1; cvt.u32.u64 %0, t; }"
        : "=r"(a) : "l"(p));
    return a;
}
__device__ __forceinline__ void ldsm_x4(uint32_t* r, uint32_t addr) {
    asm volatile("ldmatrix.sync.aligned.m8n8.x4.shared.b16 {%0,%1,%2,%3}, [%4];"
        : "=r"(r[0]), "=r"(r[1]), "=r"(r[2]), "=r"(r[3]) : "r"(addr));
}
__device__ __forceinline__ void ldsm_x4_t(uint32_t* r, uint32_t addr) {
    asm volatile("ldmatrix.sync.aligned.m8n8.x4.trans.shared.b16 {%0,%1,%2,%3}, [%4];"
        : "=r"(r[0]), "=r"(r[1]), "=r"(r[2]), "=r"(r[3]) : "r"(addr));
}
__device__ __forceinline__ void mma_fp16(float* d, const uint32_t* a,
                                         const uint32_t* b) {
    asm volatile(
        "mma.sync.aligned.m16n8k16.row.col.f32.f16.f16.f32 "
        "{%0,%1,%2,%3}, {%4,%5,%6,%7}, {%8,%9}, {%0,%1,%2,%3};"
        : "+f"(d[0]), "+f"(d[1]), "+f"(d[2]), "+f"(d[3])
        : "r"(a[0]), "r"(a[1]), "r"(a[2]), "r"(a[3]), "r"(b[0]), "r"(b[1]));
}
__device__ __forceinline__ void cp16(uint32_t saddr, const void* g) {
    asm volatile("cp.async.cg.shared.global [%0], [%1], 16;"
        :: "r"(saddr), "l"(g) : "memory");
}
#define CP_COMMIT()  asm volatile("cp.async.commit_group;" ::: "memory")
#define CP_WAIT2()   asm volatile("cp.async.wait_group 2;" ::: "memory")
#define CP_WAIT1()   asm volatile("cp.async.wait_group 1;" ::: "memory")
#define CP_WAIT0()   asm volatile("cp.async.wait_group 0;" ::: "memory")

#define SMEM_SWIZZLE_128B(byte_offset) \
    ((byte_offset) ^ (((byte_offset) >> 3) & 0x70))

__device__ __forceinline__ float exp2a(float x) {
    float y; asm("ex2.approx.f32 %0, %1;" : "=f"(y) : "f"(x)); return y;
}
__device__ __forceinline__ uint32_t exp2_h2(uint32_t x) {
    uint32_t y;
    asm("ex2.approx.f16x2 %0, %1;" : "=r"(y) : "r"(x));
    return y;
}
__device__ __forceinline__ uint32_t pack_h2(float a, float b) {
    __half2 h = __floats2half2_rn(a, b);
    return *reinterpret_cast<uint32_t*>(&h);
}
__device__ __forceinline__ uint32_t hmax2u(uint32_t a, uint32_t b) {
    uint32_t r;
    asm("max.f16x2 %0, %1, %2;" : "=r"(r) : "r"(a), "r"(b));
    return r;
}
__device__ __forceinline__ float2 h2_to_f2(uint32_t u) {
    __half2 h = *reinterpret_cast<__half2*>(&u);
    return __half22float2(h);
}

// ---------------------------------------------------------------------------
// Prep: fp32 -> fp16 (vectorized x4) + bias concat (block 0).
// ---------------------------------------------------------------------------
__global__ __launch_bounds__(256) void prep_split(
    const float* __restrict__ Wq, const float* __restrict__ Wk,
    const float* __restrict__ Wv, const float* __restrict__ Wo,
    const float* __restrict__ x,
    const float* __restrict__ bq, const float* __restrict__ bk,
    const float* __restrict__ bv)
{
    const int i = (blockIdx.x * 256 + threadIdx.x) * 4;   // 0 .. 8M-1, step 4
    const int WQKV = 3*CC*CC, WO = CC*CC;
    const float* src;
    __half* dst;
    int j;
    if (i < WQKV) {
        src = (i < CC*CC) ? Wq : (i < 2*CC*CC) ? Wk : Wv;
        src += (i & (CC*CC - 1));
        dst = g_wh; j = i;
    } else if (i < WQKV + WO) {
        j = i - WQKV;
        src = Wo + j;
        dst = g_woh;
    } else {
        j = i - WQKV - WO;      // 0 .. 4M-1
        src = x + j;
        dst = g_xh;
    }
    float4 v = *(const float4*)src;
    uint2 o;
    o.x = pack_h2(v.x, v.y);
    o.y = pack_h2(v.z, v.w);
    *(uint2*)(dst + j) = o;

    if (blockIdx.x == 0) {
        for (int t = threadIdx.x; t < 3*CC; t += 256)
            g_bqkv[t] = (t < CC) ? bq[t] : (t < 2*CC) ? bk[t-CC] : bv[t-2*CC];
    }
}

// ---------------------------------------------------------------------------
// mma.sync GEMM (fp16 single-term): 128x128 tile, 3-stage cp.async pipeline.
// mode 0: A=x, B=WqWkWv -> fp16 q/k/v (+bias, Q scaled).
// mode 1: A=y(fp16), B=Wo -> d_out fp32 (+bo).
// ---------------------------------------------------------------------------
#define CHUNK_K   64
#define NCHUNK    (CC / CHUNK_K)      // 16
#define BUF_BYTES (128*64*2)          // 16 KB per operand buffer
#define STAGE_BYTES (2*BUF_BYTES)     // 32 KB
#define OFF_A 0
#define OFF_B BUF_BYTES
#define GEMM_SMEM (3*STAGE_BYTES + 1024)   // 99328 B (2 CTAs/SM)

__global__ __launch_bounds__(256, 2) void gemm_tc(
    int mode, const float* __restrict__ bias1, float* __restrict__ outf)
{
    extern __shared__ char smem[];
    const uint32_t smem_u32 = smem_to_u32(smem);
    const uint32_t tile_u32 = (smem_u32 + 1023) & ~1023u;

    const int tid  = threadIdx.x;
    const int wid  = tid >> 5;
    const int lane = tid & 31;
    const int wm   = wid >> 1;          // 0..3 (M)
    const int wn   = wid & 1;           // 0..1 (N)
    const int m0   = blockIdx.y << 7;
    const int n0   = blockIdx.x << 7;

    const __half *A, *B;
    if (mode == 0) { A = g_xh; B = g_wh;  }
    else           { A = g_yh; B = g_woh; }

    auto issue_chunk = [&](int c, int s) {
        const int kc = c * CHUNK_K;
        const uint32_t st = tile_u32 + s * STAGE_BYTES;
        #pragma unroll
        for (int i = 0; i < 4; i++) {
            int idx = tid + i*256;           // 0..1023
            int r   = idx >> 3;              // tile row 0..127
            int g   = idx & 7;               // 16B group in row
            uint32_t so = SMEM_SWIZZLE_128B((uint32_t)(r*128 + g*16));
            size_t aoff = (size_t)(m0 + r) * CC + kc + g*8;
            size_t boff = (size_t)(n0 + r) * CC + kc + g*8;
            cp16(st + OFF_A + so, A + aoff);
            cp16(st + OFF_B + so, B + boff);
        }
        CP_COMMIT();
    };

    float acc[2][8][4];
    #pragma unroll
    for (int mt = 0; mt < 2; mt++)
        #pragma unroll
        for (int nt = 0; nt < 8; nt++)
            #pragma unroll
            for (int e = 0; e < 4; e++) acc[mt][nt][e] = 0.f;

    issue_chunk(0, 0);
    issue_chunk(1, 1);
    issue_chunk(2, 2);

    for (int c = 0; c < NCHUNK; ++c) {
        const int s = c % 3;
        if (c + 2 < NCHUNK)      { CP_WAIT2(); }
        else if (c + 1 < NCHUNK) { CP_WAIT1(); }
        else                     { CP_WAIT0(); }
        __syncthreads();

        const uint32_t sA = tile_u32 + s*STAGE_BYTES + OFF_A;
        const uint32_t sB = tile_u32 + s*STAGE_BYTES + OFF_B;

        #pragma unroll
        for (int ks = 0; ks < 4; ++ks) {
            uint32_t af[2][4];
            #pragma unroll
            for (int mt = 0; mt < 2; ++mt) {
                int r = wm*32 + mt*16 + (lane & 15);
                int g = ks*2 + (lane >> 4);
                uint32_t off = SMEM_SWIZZLE_128B((uint32_t)(r*128 + g*16));
                ldsm_x4(af[mt], sA + off);
            }
            #pragma unroll
            for (int np = 0; np < 4; ++np) {
                int n = wn*64 + np*16 + ((lane >> 4) << 3) + (lane & 7);
                int g = ks*2 + ((lane >> 3) & 1);
                uint32_t off = SMEM_SWIZZLE_128B((uint32_t)(n*128 + g*16));
                uint32_t bf[4];
                ldsm_x4(bf, sB + off);
                #pragma unroll
                for (int mt = 0; mt < 2; ++mt) {
                    mma_fp16(acc[mt][2*np],   af[mt], bf);
                    mma_fp16(acc[mt][2*np+1], af[mt], bf + 2);
                }
            }
        }

        if (c + 3 < NCHUNK) {
            __syncthreads();           // all warps done reading stage s
            issue_chunk(c + 3, s);
        }
    }

    // --- epilogue ---
    const int gl = lane >> 2;          // 0..7
    const int tl = lane & 3;           // 0..3
    #pragma unroll
    for (int mt = 0; mt < 2; ++mt) {
        #pragma unroll
        for (int nt = 0; nt < 8; ++nt) {
            const int row0 = m0 + wm*32 + mt*16 + gl;
            const int colg = n0 + wn*64 + nt*8 + 2*tl;
            if (mode == 0) {
                const int head = colg >> 6;        // 0..47
                const int proj = head >> 4;        // 0=q 1=k 2=v
                const int h    = head & 15;
                const int d0c  = colg & 63;
                __half* dstp = (proj == 0) ? g_q : (proj == 1) ? g_k : g_v;
                const float2 bia = *(const float2*)&g_bqkv[colg];
                #pragma unroll
                for (int rr = 0; rr < 2; ++rr) {
                    const int m = row0 + rr*8;
                    const int b_ = m >> 11, t = m & 2047;
                    float v0 = acc[mt][nt][2*rr+0] + bia.x;
                    float v1 = acc[mt][nt][2*rr+1] + bia.y;
                    if (proj == 0) { v0 *= QSCALE; v1 *= QSCALE; }
                    size_t off = ((size_t)(b_*HH + h) * TT + t) * DD + d0c;
                    *(uint32_t*)(dstp + off) = pack_h2(v0, v1);
                }
            } else {
                const float2 bia = *(const float2*)&bias1[colg];
                #pragma unroll
                for (int rr = 0; rr < 2; ++rr) {
                    const int m = row0 + rr*8;
                    float2 o;
                    o.x = acc[mt][nt][2*rr+0] + bia.x;
                    o.y = acc[mt][nt][2*rr+1] + bia.y;
                    *(float2*)(outf + (size_t)m * CC + colg) = o;
                }
            }
        }
    }
}

// ---------------------------------------------------------------------------
// Tensor-core flash attention, fp16 single-term (R13 arithmetic restored).
// R15: packed-h2 max reduce (2 shuffles), skip-rescale when row max
// unchanged (warp-uniform branch). f16x2 exp, ones-MMA row sums, 3 stages.
// ---------------------------------------------------------------------------
#define F_THREADS 128
#define F_STAGE 16384                 // K(8KB) + V(8KB) per stage
#define F_SMEM (8192 + 3*F_STAGE)     // Q 8KB + 3 stages = 57344 B

__global__ __launch_bounds__(F_THREADS, 3) void flash_tc()
{
    extern __shared__ char fsm[];
    const uint32_t sb = smem_to_u32(fsm);
    const uint32_t sQ = sb;

    const int tid = threadIdx.x, wid = tid >> 5, lane = tid & 31;
    const int gl = lane >> 2, tl = lane & 3;
    const int jq = (int)gridDim.x - 1 - (int)blockIdx.x;   // heavy tiles first
    const int q0 = jq << 6;                                 // 64-row q tiles
    const int bh = blockIdx.y;
    const size_t hb = (size_t)bh * TT * DD;
    const __half *qp = g_q + hb + (size_t)q0 * DD;
    const __half *kp = g_k + hb, *vp = g_v + hb;
    const int ntiles = jq + 1;

    // --- Q tile: 64 rows x 8 chunks = 512 chunks (4 iters x 128 thr) ---
    #pragma unroll
    for (int i = 0; i < 4; i++) {
        int idx = tid + i*F_THREADS;        // 0..511
        int r = idx >> 3, c = idx & 7;
        uint32_t so = SMEM_SWIZZLE_128B((uint32_t)(r*128 + c*16));
        cp16(sQ + so, qp + (size_t)r*DD + c*8);
    }
    CP_COMMIT();

    auto issue_kv = [&](int kt, int s) {
        const uint32_t st = sb + 8192 + s*F_STAGE;
        const int r0 = kt << 6;
        #pragma unroll
        for (int i = 0; i < 8; i++) {
            int idx = tid + i*F_THREADS;    // 0..1023
            int buf = idx >> 9;             // 0 K, 1 V
            int rc = idx & 511; int r = rc >> 3, c = rc & 7;
            uint32_t so = SMEM_SWIZZLE_128B((uint32_t)(r*128 + c*16));
            const __half* src = (buf ? vp : kp) + (size_t)(r0 + r) * DD + c*8;
            cp16(st + buf*8192 + so, src);
        }
        CP_COMMIT();
    };
    issue_kv(0, 0);
    issue_kv(1, 1);       // prefetch depth 2 (valid memory even if unused)
    issue_kv(2, 2);

    CP_WAIT2();           // Q + stage0 ready
    __syncthreads();

    // --- Q fragments (persistent) ---
    const int qrow = wid << 4;               // 0..48
    uint32_t qf[4][4];
    #pragma unroll
    for (int dc = 0; dc < 4; dc++) {
        uint32_t so = SMEM_SWIZZLE_128B((uint32_t)(
            (qrow + (lane & 15))*128 + (dc*16 + ((lane >> 4) << 3))*2));
        ldsm_x4(qf[dc], sQ + so);
    }

    float m_run[2] = {-1e30f, -1e30f};
    float l_run[2] = {0.f, 0.f};
    float oacc[8][4];
    #pragma unroll
    for (int f = 0; f < 8; f++)
        #pragma unroll
        for (int e = 0; e < 4; e++) oacc[f][e] = 0.f;

    const uint32_t onesB[2] = {0x3C003C00u, 0x3C003C00u};   // fp16 1.0 x4

    for (int kt = 0; kt < ntiles; kt++) {
        const int s = kt % 3;
        if (kt == 0) { /* waited above */ }
        else if (kt + 2 < ntiles) { CP_WAIT2(); }
        else if (kt + 1 < ntiles) { CP_WAIT1(); }
        else                      { CP_WAIT0(); }
        if (kt) __syncthreads();

        const uint32_t st = sb + 8192 + s*F_STAGE;

        // ---- S = Q @ K^T (fp16 single) ----
        float sacc[8][4] = {};
        #pragma unroll
        for (int dc = 0; dc < 4; dc++) {
            #pragma unroll
            for (int ng = 0; ng < 4; ng++) {
                uint32_t so = SMEM_SWIZZLE_128B((uint32_t)(
                    ((ng<<4) + (lane & 7) + ((lane >> 4) << 3))*128 +
                    ((dc<<4) + ((lane >> 3) & 1)*8)*2));
                uint32_t kf[4];
                ldsm_x4(kf, st + so);
                mma_fp16(sacc[2*ng],   qf[dc], kf);
                mma_fp16(sacc[2*ng+1], qf[dc], kf + 2);
            }
        }

        // ---- causal mask (diagonal = last tile) ----
        if (kt == jq) {
            const int r0g = q0 + qrow + gl;
            #pragma unroll
            for (int f = 0; f < 8; f++) {
                const int kc0 = (kt << 6) + (f << 3) + (tl << 1);
                if (kc0     > r0g)     sacc[f][0] = -1e30f;
                if (kc0 + 1 > r0g)     sacc[f][1] = -1e30f;
                if (kc0     > r0g + 8) sacc[f][2] = -1e30f;
                if (kc0 + 1 > r0g + 8) sacc[f][3] = -1e30f;
            }
        }

        // ---- online softmax: packed-h2 quad max reduce ----
        float mx0 = m_run[0], mx1 = m_run[1];
        #pragma unroll
        for (int f = 0; f < 8; f++) {
            mx0 = fmaxf(mx0, fmaxf(sacc[f][0], sacc[f][1]));
            mx1 = fmaxf(mx1, fmaxf(sacc[f][2], sacc[f][3]));
        }
        uint32_t mxp = pack_h2(mx0, mx1);
        mxp = hmax2u(mxp, __shfl_xor_sync(0xffffffffu, mxp, 1));
        mxp = hmax2u(mxp, __shfl_xor_sync(0xffffffffu, mxp, 2));
        float2 mxf = h2_to_f2(mxp);
        mx0 = mxf.x; mx1 = mxf.y;

        // rescale only if some row's max actually increased (warp-uniform)
        bool chg = __any_sync(0xffffffffu,
                              (mx0 > m_run[0]) || (mx1 > m_run[1]));
        if (chg) {
            const float a0 = exp2a(m_run[0] - mx0);
            const float a1 = exp2a(m_run[1] - mx1);
            l_run[0] *= a0; l_run[1] *= a1;
            #pragma unroll
            for (int f = 0; f < 8; f++) {
                oacc[f][0] *= a0; oacc[f][1] *= a0;
                oacc[f][2] *= a1; oacc[f][3] *= a1;
            }
            m_run[0] = mx0; m_run[1] = mx1;
        }

        // ---- p = exp2(s - m)  (f16x2) ----
        uint32_t pA[8], pB[8];
        #pragma unroll
        for (int f = 0; f < 8; f++) {
            pA[f] = exp2_h2(pack_h2(sacc[f][0] - m_run[0],
                                    sacc[f][1] - m_run[0]));
            pB[f] = exp2_h2(pack_h2(sacc[f][2] - m_run[1],
                                    sacc[f][3] - m_run[1]));
        }

        // row sums: lacc = P @ ones  (d[0]=row gl, d[2]=row gl+8)
        float lacc[4] = {0.f, 0.f, 0.f, 0.f};
        #pragma unroll
        for (int kc = 0; kc < 4; kc++) {
            uint32_t Af[4] = {pA[2*kc], pB[2*kc], pA[2*kc+1], pB[2*kc+1]};
            mma_fp16(lacc, Af, onesB);
        }
        l_run[0] += lacc[0];
        l_run[1] += lacc[2];

        // ---- O += P @ V (fp16 single; V via ldmatrix.trans) ----
        #pragma unroll
        for (int kc = 0; kc < 4; kc++) {
            uint32_t Af[4] = {pA[2*kc], pB[2*kc], pA[2*kc+1], pB[2*kc+1]};
            #pragma unroll
            for (int dg = 0; dg < 4; dg++) {
                uint32_t so = SMEM_SWIZZLE_128B((uint32_t)(
                    ((kc<<4) + (lane & 7) + ((lane >> 3) & 1)*8)*128 +
                    ((dg<<4) + (lane >> 4)*8)*2));
                uint32_t vf[4];
                ldsm_x4_t(vf, st + 8192 + so);
                mma_fp16(oacc[2*dg],   Af, vf);
                mma_fp16(oacc[2*dg+1], Af, vf + 2);
            }
        }

        if (kt + 3 < ntiles) {
            __syncthreads();            // all warps done reading stage s
            issue_kv(kt + 3, s);
        }
    }

    // ---- epilogue: normalize, write y as fp16 [B,T,C] ----
    const float inv0 = 1.f / l_run[0];
    const float inv1 = 1.f / l_run[1];
    const int b_ = bh >> 4, h = bh & 15;
    const int t0 = q0 + qrow + gl, t1 = t0 + 8;
    #pragma unroll
    for (int f = 0; f < 8; f++) {
        const int col = h*DD + (f << 3) + (tl << 1);
        *(uint32_t*)(g_yh + (size_t)(b_*TT + t0) * CC + col) =
            pack_h2(oacc[f][0] * inv0, oacc[f][1] * inv0);
        *(uint32_t*)(g_yh + (size_t)(b_*TT + t1) * CC + col) =
            pack_h2(oacc[f][2] * inv1, oacc[f][3] * inv1);
    }
}

// ---------------------------------------------------------------------------

extern "C" void kernel_launch(void* const* d_in, const int* in_sizes, int n_in,
                              void* d_out, int out_size)
{
    const float* x  = (const float*)d_in[0];
    const float* Wq = (const float*)d_in[1];
    const float* bq = (const float*)d_in[2];
    const float* Wk = (const float*)d_in[3];
    const float* bk = (const float*)d_in[4];
    const float* Wv = (const float*)d_in[5];
    const float* bv = (const float*)d_in[6];
    const float* Wo = (const float*)d_in[7];
    const float* bo = (const float*)d_in[8];
    float* out = (float*)d_out;

    // 0) fp32 -> fp16 conversions (x4 vectorized) + bias concat (fused)
    prep_split<<<(8*1024*1024)/1024, 256>>>(Wq, Wk, Wv, Wo, x, bq, bk, bv);

    // 1) fused QKV projection (fp16 single, 3-stage) -> fp16 q/k/v
    cudaFuncSetAttribute(gemm_tc, cudaFuncAttributeMaxDynamicSharedMemorySize,
                         GEMM_SMEM);
    gemm_tc<<<dim3(3*CC/128, MM/128), 256, GEMM_SMEM>>>(0, nullptr, nullptr);

    // 2) tensor-core causal flash attention (online max, f16x2 exp) -> y fp16
    cudaFuncSetAttribute(flash_tc, cudaFuncAttributeMaxDynamicSharedMemorySize,
                         F_SMEM);
    flash_tc<<<dim3(TT/64, BB*HH), F_THREADS, F_SMEM>>>();

    // 3) output projection (fp16 single, 3-stage) -> d_out
    gemm_tc<<<dim3(CC/128, MM/128), 256, GEMM_SMEM>>>(1, bo, out);
}

// round 16
// speedup vs baseline: 4.0090x; 1.0210x over previous
#include <cuda_runtime.h>
#include <cuda_bf16.h>
#include <cuda_fp16.h>
#include <cstdint>
#include <math.h>

#define BB 2
#define TT 2048
#define CC 1024
#define HH 16
#define DD 64
#define MM (BB*TT)   // 4096 rows

// ---------------------------------------------------------------------------
// Scratch (__device__ globals; allocation-free rule)
// ---------------------------------------------------------------------------
__device__ __half g_q[BB*HH*TT*DD];   // fp16 [B,H,T,D], Q pre-scaled
__device__ __half g_k[BB*HH*TT*DD];
__device__ __half g_v[BB*HH*TT*DD];

__device__ __half g_xh[MM*CC];        // x fp16
__device__ __half g_wh[3*CC*CC];      // Wq|Wk|Wv concat fp16
__device__ __half g_woh[CC*CC];       // Wo fp16
__device__ __half g_yh[MM*CC];        // attention output fp16 [B,T,C]
__device__ float g_bqkv[3*CC];        // bq|bk|bv concat

// Q pre-scale: 1/sqrt(64) * log2(e)  (softmax done in base-2)
#define QSCALE (0.125f * 1.4426950408889634f)

// ---------------------------------------------------------------------------
// Helpers: ldmatrix / mma.sync / cp.async (baseline sm_80+)
// ---------------------------------------------------------------------------
__device__ __forceinline__ uint32_t smem_to_u32(const void* p) {
    uint32_t a;
    asm("{ .reg .u64 t; cvta.to.shared.u64 t, %1; cvt.u32.u64 %0, t; }"
        : "=r"(a) : "l"(p));
    return a;
}
__device__ __forceinline__ void ldsm_x4(uint32_t* r, uint32_t addr) {
    asm volatile("ldmatrix.sync.aligned.m8n8.x4.shared.b16 {%0,%1,%2,%3}, [%4];"
        : "=r"(r[0]), "=r"(r[1]), "=r"(r[2]), "=r"(r[3]) : "r"(addr));
}
__device__ __forceinline__ void ldsm_x4_t(uint32_t* r, uint32_t addr) {
    asm volatile("ldmatrix.sync.aligned.m8n8.x4.trans.shared.b16 {%0,%1,%2,%3}, [%4];"
        : "=r"(r[0]), "=r"(r[1]), "=r"(r[2]), "=r"(r[3]) : "r"(addr));
}
__device__ __forceinline__ void mma_fp16(float* d, const uint32_t* a,
                                         const uint32_t* b) {
    asm volatile(
        "mma.sync.aligned.m16n8k16.row.col.f32.f16.f16.f32 "
        "{%0,%1,%2,%3}, {%4,%5,%6,%7}, {%8,%9}, {%0,%1,%2,%3};"
        : "+f"(d[0]), "+f"(d[1]), "+f"(d[2]), "+f"(d[3])
        : "r"(a[0]), "r"(a[1]), "r"(a[2]), "r"(a[3]), "r"(b[0]), "r"(b[1]));
}
__device__ __forceinline__ void cp16(uint32_t saddr, const void* g) {
    asm volatile("cp.async.cg.shared.global [%0], [%1], 16;"
        :: "r"(saddr), "l"(g) : "memory");
}
#define CP_COMMIT()  asm volatile("cp.async.commit_group;" ::: "memory")
#define CP_WAIT2()   asm volatile("cp.async.wait_group 2;" ::: "memory")
#define CP_WAIT1()   asm volatile("cp.async.wait_group 1;" ::: "memory")
#define CP_WAIT0()   asm volatile("cp.async.wait_group 0;" ::: "memory")

#define SMEM_SWIZZLE_128B(byte_offset) \
    ((byte_offset) ^ (((byte_offset) >> 3) & 0x70))

__device__ __forceinline__ float exp2a(float x) {
    float y; asm("ex2.approx.f32 %0, %1;" : "=f"(y) : "f"(x)); return y;
}
__device__ __forceinline__ uint32_t exp2_h2(uint32_t x) {
    uint32_t y;
    asm("ex2.approx.f16x2 %0, %1;" : "=r"(y) : "r"(x));
    return y;
}
__device__ __forceinline__ uint32_t pack_h2(float a, float b) {
    __half2 h = __floats2half2_rn(a, b);
    return *reinterpret_cast<uint32_t*>(&h);
}
__device__ __forceinline__ uint32_t hmax2u(uint32_t a, uint32_t b) {
    uint32_t r;
    asm("max.f16x2 %0, %1, %2;" : "=r"(r) : "r"(a), "r"(b));
    return r;
}
__device__ __forceinline__ float2 h2_to_f2(uint32_t u) {
    __half2 h = *reinterpret_cast<__half2*>(&u);
    return __half22float2(h);
}

// ---------------------------------------------------------------------------
// Prep: fp32 -> fp16 (vectorized x4) + bias concat (block 0).
// ---------------------------------------------------------------------------
__global__ __launch_bounds__(256) void prep_split(
    const float* __restrict__ Wq, const float* __restrict__ Wk,
    const float* __restrict__ Wv, const float* __restrict__ Wo,
    const float* __restrict__ x,
    const float* __restrict__ bq, const float* __restrict__ bk,
    const float* __restrict__ bv)
{
    const int i = (blockIdx.x * 256 + threadIdx.x) * 4;   // 0 .. 8M-1, step 4
    const int WQKV = 3*CC*CC, WO = CC*CC;
    const float* src;
    __half* dst;
    int j;
    if (i < WQKV) {
        src = (i < CC*CC) ? Wq : (i < 2*CC*CC) ? Wk : Wv;
        src += (i & (CC*CC - 1));
        dst = g_wh; j = i;
    } else if (i < WQKV + WO) {
        j = i - WQKV;
        src = Wo + j;
        dst = g_woh;
    } else {
        j = i - WQKV - WO;      // 0 .. 4M-1
        src = x + j;
        dst = g_xh;
    }
    float4 v = *(const float4*)src;
    uint2 o;
    o.x = pack_h2(v.x, v.y);
    o.y = pack_h2(v.z, v.w);
    *(uint2*)(dst + j) = o;

    if (blockIdx.x == 0) {
        for (int t = threadIdx.x; t < 3*CC; t += 256)
            g_bqkv[t] = (t < CC) ? bq[t] : (t < 2*CC) ? bk[t-CC] : bv[t-2*CC];
    }
}

// ---------------------------------------------------------------------------
// mma.sync GEMM (fp16 single-term), R16: 64x128 tile, 128 threads / 4 warps,
// 2-stage cp.async, 49 KB smem -> 4 CTAs/SM (4 warps/SMSP latency hiding).
// Warp tile 32x64 (inner loop identical to R15).
// mode 0: A=x, B=WqWkWv -> fp16 q/k/v (+bias, Q scaled).
// mode 1: A=y(fp16), B=Wo -> d_out fp32 (+bo).
// ---------------------------------------------------------------------------
#define CHUNK_K   64
#define NCHUNK    (CC / CHUNK_K)      // 16
#define G_THREADS 128
#define ABUF_BYTES (64*64*2)          // 8 KB
#define BBUF_BYTES (128*64*2)         // 16 KB
#define STAGE_BYTES (ABUF_BYTES + BBUF_BYTES)  // 24 KB
#define OFF_A 0
#define OFF_B ABUF_BYTES
#define GEMM_SMEM (2*STAGE_BYTES + 1024)       // 50176 B (4 CTAs/SM)

__global__ __launch_bounds__(G_THREADS, 4) void gemm_tc(
    int mode, const float* __restrict__ bias1, float* __restrict__ outf)
{
    extern __shared__ char smem[];
    const uint32_t smem_u32 = smem_to_u32(smem);
    const uint32_t tile_u32 = (smem_u32 + 1023) & ~1023u;

    const int tid  = threadIdx.x;
    const int wid  = tid >> 5;
    const int lane = tid & 31;
    const int wm   = wid >> 1;          // 0..1 (M, 32 rows each)
    const int wn   = wid & 1;           // 0..1 (N, 64 cols each)
    const int m0   = blockIdx.y << 6;   // 64-row tiles
    const int n0   = blockIdx.x << 7;   // 128-col tiles

    const __half *A, *B;
    if (mode == 0) { A = g_xh; B = g_wh;  }
    else           { A = g_yh; B = g_woh; }

    auto issue_chunk = [&](int c, int s) {
        const int kc = c * CHUNK_K;
        const uint32_t st = tile_u32 + s * STAGE_BYTES;
        #pragma unroll
        for (int i = 0; i < 4; i++) {          // A: 512 chunks
            int idx = tid + i*G_THREADS;       // 0..511
            int r   = idx >> 3;                // 0..63
            int g   = idx & 7;
            uint32_t so = SMEM_SWIZZLE_128B((uint32_t)(r*128 + g*16));
            cp16(st + OFF_A + so, A + (size_t)(m0 + r) * CC + kc + g*8);
        }
        #pragma unroll
        for (int i = 0; i < 8; i++) {          // B: 1024 chunks
            int idx = tid + i*G_THREADS;       // 0..1023
            int r   = idx >> 3;                // 0..127
            int g   = idx & 7;
            uint32_t so = SMEM_SWIZZLE_128B((uint32_t)(r*128 + g*16));
            cp16(st + OFF_B + so, B + (size_t)(n0 + r) * CC + kc + g*8);
        }
        CP_COMMIT();
    };

    float acc[2][8][4];
    #pragma unroll
    for (int mt = 0; mt < 2; mt++)
        #pragma unroll
        for (int nt = 0; nt < 8; nt++)
            #pragma unroll
            for (int e = 0; e < 4; e++) acc[mt][nt][e] = 0.f;

    issue_chunk(0, 0);
    issue_chunk(1, 1);

    for (int c = 0; c < NCHUNK; ++c) {
        const int s = c & 1;
        if (c + 1 < NCHUNK) { CP_WAIT1(); } else { CP_WAIT0(); }
        __syncthreads();

        const uint32_t sA = tile_u32 + s*STAGE_BYTES + OFF_A;
        const uint32_t sB = tile_u32 + s*STAGE_BYTES + OFF_B;

        #pragma unroll
        for (int ks = 0; ks < 4; ++ks) {
            uint32_t af[2][4];
            #pragma unroll
            for (int mt = 0; mt < 2; ++mt) {
                int r = wm*32 + mt*16 + (lane & 15);
                int g = ks*2 + (lane >> 4);
                uint32_t off = SMEM_SWIZZLE_128B((uint32_t)(r*128 + g*16));
                ldsm_x4(af[mt], sA + off);
            }
            #pragma unroll
            for (int np = 0; np < 4; ++np) {
                int n = wn*64 + np*16 + ((lane >> 4) << 3) + (lane & 7);
                int g = ks*2 + ((lane >> 3) & 1);
                uint32_t off = SMEM_SWIZZLE_128B((uint32_t)(n*128 + g*16));
                uint32_t bf[4];
                ldsm_x4(bf, sB + off);
                #pragma unroll
                for (int mt = 0; mt < 2; ++mt) {
                    mma_fp16(acc[mt][2*np],   af[mt], bf);
                    mma_fp16(acc[mt][2*np+1], af[mt], bf + 2);
                }
            }
        }

        if (c + 2 < NCHUNK) {
            __syncthreads();           // all warps done reading stage s
            issue_chunk(c + 2, s);
        }
    }

    // --- epilogue ---
    const int gl = lane >> 2;          // 0..7
    const int tl = lane & 3;           // 0..3
    #pragma unroll
    for (int mt = 0; mt < 2; ++mt) {
        #pragma unroll
        for (int nt = 0; nt < 8; ++nt) {
            const int row0 = m0 + wm*32 + mt*16 + gl;
            const int colg = n0 + wn*64 + nt*8 + 2*tl;
            if (mode == 0) {
                const int head = colg >> 6;        // 0..47
                const int proj = head >> 4;        // 0=q 1=k 2=v
                const int h    = head & 15;
                const int d0c  = colg & 63;
                __half* dstp = (proj == 0) ? g_q : (proj == 1) ? g_k : g_v;
                const float2 bia = *(const float2*)&g_bqkv[colg];
                #pragma unroll
                for (int rr = 0; rr < 2; ++rr) {
                    const int m = row0 + rr*8;
                    const int b_ = m >> 11, t = m & 2047;
                    float v0 = acc[mt][nt][2*rr+0] + bia.x;
                    float v1 = acc[mt][nt][2*rr+1] + bia.y;
                    if (proj == 0) { v0 *= QSCALE; v1 *= QSCALE; }
                    size_t off = ((size_t)(b_*HH + h) * TT + t) * DD + d0c;
                    *(uint32_t*)(dstp + off) = pack_h2(v0, v1);
                }
            } else {
                const float2 bia = *(const float2*)&bias1[colg];
                #pragma unroll
                for (int rr = 0; rr < 2; ++rr) {
                    const int m = row0 + rr*8;
                    float2 o;
                    o.x = acc[mt][nt][2*rr+0] + bia.x;
                    o.y = acc[mt][nt][2*rr+1] + bia.y;
                    *(float2*)(outf + (size_t)m * CC + colg) = o;
                }
            }
        }
    }
}

// ---------------------------------------------------------------------------
// Tensor-core flash attention (unchanged from R15 — passing at 5.53e-4).
// ---------------------------------------------------------------------------
#define F_THREADS 128
#define F_STAGE 16384                 // K(8KB) + V(8KB) per stage
#define F_SMEM (8192 + 3*F_STAGE)     // Q 8KB + 3 stages = 57344 B

__global__ __launch_bounds__(F_THREADS, 3) void flash_tc()
{
    extern __shared__ char fsm[];
    const uint32_t sb = smem_to_u32(fsm);
    const uint32_t sQ = sb;

    const int tid = threadIdx.x, wid = tid >> 5, lane = tid & 31;
    const int gl = lane >> 2, tl = lane & 3;
    const int jq = (int)gridDim.x - 1 - (int)blockIdx.x;   // heavy tiles first
    const int q0 = jq << 6;                                 // 64-row q tiles
    const int bh = blockIdx.y;
    const size_t hb = (size_t)bh * TT * DD;
    const __half *qp = g_q + hb + (size_t)q0 * DD;
    const __half *kp = g_k + hb, *vp = g_v + hb;
    const int ntiles = jq + 1;

    // --- Q tile: 64 rows x 8 chunks = 512 chunks (4 iters x 128 thr) ---
    #pragma unroll
    for (int i = 0; i < 4; i++) {
        int idx = tid + i*F_THREADS;        // 0..511
        int r = idx >> 3, c = idx & 7;
        uint32_t so = SMEM_SWIZZLE_128B((uint32_t)(r*128 + c*16));
        cp16(sQ + so, qp + (size_t)r*DD + c*8);
    }
    CP_COMMIT();

    auto issue_kv = [&](int kt, int s) {
        const uint32_t st = sb + 8192 + s*F_STAGE;
        const int r0 = kt << 6;
        #pragma unroll
        for (int i = 0; i < 8; i++) {
            int idx = tid + i*F_THREADS;    // 0..1023
            int buf = idx >> 9;             // 0 K, 1 V
            int rc = idx & 511; int r = rc >> 3, c = rc & 7;
            uint32_t so = SMEM_SWIZZLE_128B((uint32_t)(r*128 + c*16));
            const __half* src = (buf ? vp : kp) + (size_t)(r0 + r) * DD + c*8;
            cp16(st + buf*8192 + so, src);
        }
        CP_COMMIT();
    };
    issue_kv(0, 0);
    issue_kv(1, 1);       // prefetch depth 2 (valid memory even if unused)
    issue_kv(2, 2);

    CP_WAIT2();           // Q + stage0 ready
    __syncthreads();

    // --- Q fragments (persistent) ---
    const int qrow = wid << 4;               // 0..48
    uint32_t qf[4][4];
    #pragma unroll
    for (int dc = 0; dc < 4; dc++) {
        uint32_t so = SMEM_SWIZZLE_128B((uint32_t)(
            (qrow + (lane & 15))*128 + (dc*16 + ((lane >> 4) << 3))*2));
        ldsm_x4(qf[dc], sQ + so);
    }

    float m_run[2] = {-1e30f, -1e30f};
    float l_run[2] = {0.f, 0.f};
    float oacc[8][4];
    #pragma unroll
    for (int f = 0; f < 8; f++)
        #pragma unroll
        for (int e = 0; e < 4; e++) oacc[f][e] = 0.f;

    const uint32_t onesB[2] = {0x3C003C00u, 0x3C003C00u};   // fp16 1.0 x4

    for (int kt = 0; kt < ntiles; kt++) {
        const int s = kt % 3;
        if (kt == 0) { /* waited above */ }
        else if (kt + 2 < ntiles) { CP_WAIT2(); }
        else if (kt + 1 < ntiles) { CP_WAIT1(); }
        else                      { CP_WAIT0(); }
        if (kt) __syncthreads();

        const uint32_t st = sb + 8192 + s*F_STAGE;

        // ---- S = Q @ K^T (fp16 single) ----
        float sacc[8][4] = {};
        #pragma unroll
        for (int dc = 0; dc < 4; dc++) {
            #pragma unroll
            for (int ng = 0; ng < 4; ng++) {
                uint32_t so = SMEM_SWIZZLE_128B((uint32_t)(
                    ((ng<<4) + (lane & 7) + ((lane >> 4) << 3))*128 +
                    ((dc<<4) + ((lane >> 3) & 1)*8)*2));
                uint32_t kf[4];
                ldsm_x4(kf, st + so);
                mma_fp16(sacc[2*ng],   qf[dc], kf);
                mma_fp16(sacc[2*ng+1], qf[dc], kf + 2);
            }
        }

        // ---- causal mask (diagonal = last tile) ----
        if (kt == jq) {
            const int r0g = q0 + qrow + gl;
            #pragma unroll
            for (int f = 0; f < 8; f++) {
                const int kc0 = (kt << 6) + (f << 3) + (tl << 1);
                if (kc0     > r0g)     sacc[f][0] = -1e30f;
                if (kc0 + 1 > r0g)     sacc[f][1] = -1e30f;
                if (kc0     > r0g + 8) sacc[f][2] = -1e30f;
                if (kc0 + 1 > r0g + 8) sacc[f][3] = -1e30f;
            }
        }

        // ---- online softmax: packed-h2 quad max reduce ----
        float mx0 = m_run[0], mx1 = m_run[1];
        #pragma unroll
        for (int f = 0; f < 8; f++) {
            mx0 = fmaxf(mx0, fmaxf(sacc[f][0], sacc[f][1]));
            mx1 = fmaxf(mx1, fmaxf(sacc[f][2], sacc[f][3]));
        }
        uint32_t mxp = pack_h2(mx0, mx1);
        mxp = hmax2u(mxp, __shfl_xor_sync(0xffffffffu, mxp, 1));
        mxp = hmax2u(mxp, __shfl_xor_sync(0xffffffffu, mxp, 2));
        float2 mxf = h2_to_f2(mxp);
        mx0 = mxf.x; mx1 = mxf.y;

        bool chg = __any_sync(0xffffffffu,
                              (mx0 > m_run[0]) || (mx1 > m_run[1]));
        if (chg) {
            const float a0 = exp2a(m_run[0] - mx0);
            const float a1 = exp2a(m_run[1] - mx1);
            l_run[0] *= a0; l_run[1] *= a1;
            #pragma unroll
            for (int f = 0; f < 8; f++) {
                oacc[f][0] *= a0; oacc[f][1] *= a0;
                oacc[f][2] *= a1; oacc[f][3] *= a1;
            }
            m_run[0] = mx0; m_run[1] = mx1;
        }

        // ---- p = exp2(s - m)  (f16x2) ----
        uint32_t pA[8], pB[8];
        #pragma unroll
        for (int f = 0; f < 8; f++) {
            pA[f] = exp2_h2(pack_h2(sacc[f][0] - m_run[0],
                                    sacc[f][1] - m_run[0]));
            pB[f] = exp2_h2(pack_h2(sacc[f][2] - m_run[1],
                                    sacc[f][3] - m_run[1]));
        }

        // row sums: lacc = P @ ones  (d[0]=row gl, d[2]=row gl+8)
        float lacc[4] = {0.f, 0.f, 0.f, 0.f};
        #pragma unroll
        for (int kc = 0; kc < 4; kc++) {
            uint32_t Af[4] = {pA[2*kc], pB[2*kc], pA[2*kc+1], pB[2*kc+1]};
            mma_fp16(lacc, Af, onesB);
        }
        l_run[0] += lacc[0];
        l_run[1] += lacc[2];

        // ---- O += P @ V (fp16 single; V via ldmatrix.trans) ----
        #pragma unroll
        for (int kc = 0; kc < 4; kc++) {
            uint32_t Af[4] = {pA[2*kc], pB[2*kc], pA[2*kc+1], pB[2*kc+1]};
            #pragma unroll
            for (int dg = 0; dg < 4; dg++) {
                uint32_t so = SMEM_SWIZZLE_128B((uint32_t)(
                    ((kc<<4) + (lane & 7) + ((lane >> 3) & 1)*8)*128 +
                    ((dg<<4) + (lane >> 4)*8)*2));
                uint32_t vf[4];
                ldsm_x4_t(vf, st + 8192 + so);
                mma_fp16(oacc[2*dg],   Af, vf);
                mma_fp16(oacc[2*dg+1], Af, vf + 2);
            }
        }

        if (kt + 3 < ntiles) {
            __syncthreads();            // all warps done reading stage s
            issue_kv(kt + 3, s);
        }
    }

    // ---- epilogue: normalize, write y as fp16 [B,T,C] ----
    const float inv0 = 1.f / l_run[0];
    const float inv1 = 1.f / l_run[1];
    const int b_ = bh >> 4, h = bh & 15;
    const int t0 = q0 + qrow + gl, t1 = t0 + 8;
    #pragma unroll
    for (int f = 0; f < 8; f++) {
        const int col = h*DD + (f << 3) + (tl << 1);
        *(uint32_t*)(g_yh + (size_t)(b_*TT + t0) * CC + col) =
            pack_h2(oacc[f][0] * inv0, oacc[f][1] * inv0);
        *(uint32_t*)(g_yh + (size_t)(b_*TT + t1) * CC + col) =
            pack_h2(oacc[f][2] * inv1, oacc[f][3] * inv1);
    }
}

// ---------------------------------------------------------------------------

extern "C" void kernel_launch(void* const* d_in, const int* in_sizes, int n_in,
                              void* d_out, int out_size)
{
    const float* x  = (const float*)d_in[0];
    const float* Wq = (const float*)d_in[1];
    const float* bq = (const float*)d_in[2];
    const float* Wk = (const float*)d_in[3];
    const float* bk = (const float*)d_in[4];
    const float* Wv = (const float*)d_in[5];
    const float* bv = (const float*)d_in[6];
    const float* Wo = (const float*)d_in[7];
    const float* bo = (const float*)d_in[8];
    float* out = (float*)d_out;

    // 0) fp32 -> fp16 conversions (x4 vectorized) + bias concat (fused)
    prep_split<<<(8*1024*1024)/1024, 256>>>(Wq, Wk, Wv, Wo, x, bq, bk, bv);

    // 1) fused QKV projection (64x128 tiles, 4 CTAs/SM) -> fp16 q/k/v
    cudaFuncSetAttribute(gemm_tc, cudaFuncAttributeMaxDynamicSharedMemorySize,
                         GEMM_SMEM);
    gemm_tc<<<dim3(3*CC/128, MM/64), G_THREADS, GEMM_SMEM>>>(0, nullptr, nullptr);

    // 2) tensor-core causal flash attention -> y fp16
    cudaFuncSetAttribute(flash_tc, cudaFuncAttributeMaxDynamicSharedMemorySize,
                         F_SMEM);
    flash_tc<<<dim3(TT/64, BB*HH), F_THREADS, F_SMEM>>>();

    // 3) output projection (64x128 tiles, 4 CTAs/SM) -> d_out
    gemm_tc<<<dim3(CC/128, MM/64), G_THREADS, GEMM_SMEM>>>(1, bo, out);
}